// round 5
// baseline (speedup 1.0000x reference)
#include <cuda_runtime.h>
#include <cuda_bf16.h>
#include <cstdint>

#define BQ 8
#define TT 2048
#define CC 512
#define HH 16
#define HSZ 32
#define BT (BQ*TT)            // 16384
#define UEL ((size_t)BT*CC)   // 8388608 elements per [B,T,C] buffer

// ---------------------------------------------------------------------------
// Scratch (bytes). One big device array; no allocations anywhere.
// ---------------------------------------------------------------------------
#define SZ_F32   (UEL*4)
#define SZ_BF16  (UEL*2)
#define SZ_MIX   ((size_t)BT*160*4)
#define SZ_W64   ((size_t)BT*64*4)
#define SZ_WBF   ((size_t)CC*CC*2)

#define O_MIX   ((size_t)0)
#define O_XW    (O_MIX + SZ_MIX)
#define O_W64   (O_XW + SZ_F32)
#define O_DB    (O_W64 + SZ_W64)
#define O_RB    (O_DB + SZ_F32)
#define O_KB    (O_RB + SZ_F32)
#define O_VB    (O_KB + SZ_F32)
#define O_GB    (O_VB + SZ_F32)
#define O_KH    (O_GB + SZ_F32)
#define O_KL    (O_KH + SZ_BF16)
#define O_VH    (O_KL + SZ_BF16)
#define O_VL    (O_VH + SZ_BF16)
#define O_RH    (O_VL + SZ_BF16)
#define O_RL    (O_RH + SZ_BF16)
#define O_GH    (O_RL + SZ_BF16)
#define O_GL    (O_GH + SZ_BF16)
#define O_ZH    (O_GL + SZ_BF16)
#define O_ZL    (O_ZH + SZ_BF16)
#define O_WRH   (O_ZL + SZ_BF16)
#define O_WRL   (O_WRH + SZ_WBF)
#define O_WKH   (O_WRL + SZ_WBF)
#define O_WKL   (O_WKH + SZ_WBF)
#define O_WVH   (O_WKL + SZ_WBF)
#define O_WVL   (O_WVH + SZ_WBF)
#define O_WGH   (O_WVL + SZ_WBF)
#define O_WGL   (O_WGH + SZ_WBF)
#define O_WOH   (O_WGL + SZ_WBF)
#define O_WOL   (O_WOH + SZ_WBF)
#define SCRATCH_BYTES (O_WOL + SZ_WBF)

__device__ __align__(256) unsigned char g_scratch[SCRATCH_BYTES];

// ---------------------------------------------------------------------------
// mma.sync / cp.async helpers (valid on plain compute_103 / sm_80+)
// ---------------------------------------------------------------------------
__device__ __forceinline__ uint32_t smem_u32(const void* p) {
    uint32_t a;
    asm("{ .reg .u64 t; cvta.to.shared.u64 t, %1; cvt.u32.u64 %0, t; }"
        : "=r"(a) : "l"(p));
    return a;
}

#define LDSM4(r, a) \
    asm volatile("ldmatrix.sync.aligned.m8n8.x4.shared.b16 {%0,%1,%2,%3}, [%4];" \
        : "=r"((r)[0]), "=r"((r)[1]), "=r"((r)[2]), "=r"((r)[3]) : "r"(a))

#define MMA16816(d, a, b0, b1) \
    asm volatile("mma.sync.aligned.m16n8k16.row.col.f32.bf16.bf16.f32 " \
        "{%0,%1,%2,%3}, {%4,%5,%6,%7}, {%8,%9}, {%0,%1,%2,%3};" \
        : "+f"((d)[0]), "+f"((d)[1]), "+f"((d)[2]), "+f"((d)[3]) \
        : "r"((a)[0]), "r"((a)[1]), "r"((a)[2]), "r"((a)[3]), "r"(b0), "r"(b1))

#define CP_ASYNC16(dst, src) \
    asm volatile("cp.async.cg.shared.global [%0], [%1], 16;" :: "r"(dst), "l"(src))
#define CP_COMMIT() asm volatile("cp.async.commit_group;" ::: "memory")
#define CP_WAIT(n)  asm volatile("cp.async.wait_group %0;" :: "n"(n) : "memory")

// ---------------------------------------------------------------------------
// Pipelined tensor-core GEMM: C[M,512] = epi(A @ W^T), split bf16 (hi/lo),
// 3 terms: Ah*Bh + Ah*Bl + Al*Bh. Tile 128x128, K-chunk 32, cp.async 2-stage.
// ---------------------------------------------------------------------------
#define TROWB 80
#define TTILE (128*TROWB)     // 10240
#define TSTAGE (4*TTILE)      // 40960
#define TG_SMEM (2*TSTAGE)    // 81920

__device__ __forceinline__ void tg_stage_loads(
    uint32_t smb, int stage,
    const __nv_bfloat16* __restrict__ Ah, const __nv_bfloat16* __restrict__ Al,
    const __nv_bfloat16* __restrict__ Bh, const __nv_bfloat16* __restrict__ Bl,
    int bm, int bn, int k0, int tid)
{
    uint32_t sbase = smb + stage * TSTAGE;
    #pragma unroll
    for (int m = 0; m < 4; ++m) {
        const __nv_bfloat16* G = (m == 0) ? Ah : (m == 1) ? Al : (m == 2) ? Bh : Bl;
        int rbase = (m < 2) ? bm : bn;
        #pragma unroll
        for (int it = 0; it < 2; ++it) {
            int idx = it * 256 + tid;          // 0..511
            int row = idx >> 2, g = idx & 3;
            uint32_t d = sbase + m * TTILE + row * TROWB + g * 16;
            const void* src = G + (size_t)(rbase + row) * 512 + k0 + g * 8;
            CP_ASYNC16(d, src);
        }
    }
}

template<int EPI>
__global__ void __launch_bounds__(256, 2)
tgemm_kernel(const __nv_bfloat16* __restrict__ Ah, const __nv_bfloat16* __restrict__ Al,
             const __nv_bfloat16* __restrict__ Bh, const __nv_bfloat16* __restrict__ Bl,
             float* __restrict__ C)
{
    extern __shared__ unsigned char sm[];
    uint32_t smb = smem_u32(sm);
    int tid = threadIdx.x;
    int wid = tid >> 5, lane = tid & 31;
    int bm = blockIdx.y * 128, bn = blockIdx.x * 128;
    int wm = (wid & 3) * 32, wn = (wid >> 2) * 64;

    float acc[2][8][4];
    #pragma unroll
    for (int i = 0; i < 2; ++i)
        #pragma unroll
        for (int j = 0; j < 8; ++j)
            #pragma unroll
            for (int q = 0; q < 4; ++q) acc[i][j][q] = 0.f;

    int mat = lane >> 3, r8 = lane & 7;
    int lrow = (mat & 1) * 8 + r8;
    int lkb  = (mat >> 1) * 16;

    tg_stage_loads(smb, 0, Ah, Al, Bh, Bl, bm, bn, 0, tid);
    CP_COMMIT();

    for (int ch = 0; ch < 16; ++ch) {
        if (ch + 1 < 16) {
            tg_stage_loads(smb, (ch + 1) & 1, Ah, Al, Bh, Bl, bm, bn, (ch + 1) * 32, tid);
            CP_COMMIT();
            CP_WAIT(1);
        } else {
            CP_WAIT(0);
        }
        __syncthreads();

        uint32_t sbase = smb + (ch & 1) * TSTAGE;
        #pragma unroll
        for (int ks = 0; ks < 2; ++ks) {
            uint32_t ah[2][4], al[2][4];
            #pragma unroll
            for (int mt = 0; mt < 2; ++mt) {
                uint32_t ra = sbase + (wm + mt * 16 + lrow) * TROWB + ks * 32 + lkb;
                LDSM4(ah[mt], ra);
                LDSM4(al[mt], ra + TTILE);
            }
            #pragma unroll
            for (int nt = 0; nt < 4; ++nt) {
                uint32_t rb = sbase + 2 * TTILE + (wn + nt * 16 + lrow) * TROWB + ks * 32 + lkb;
                uint32_t bh4[4], bl4[4];
                LDSM4(bh4, rb);
                LDSM4(bl4, rb + TTILE);
                #pragma unroll
                for (int mt = 0; mt < 2; ++mt) {
                    MMA16816(acc[mt][nt*2+0], ah[mt], bh4[0], bh4[2]);
                    MMA16816(acc[mt][nt*2+1], ah[mt], bh4[1], bh4[3]);
                    MMA16816(acc[mt][nt*2+0], ah[mt], bl4[0], bl4[2]);
                    MMA16816(acc[mt][nt*2+1], ah[mt], bl4[1], bl4[3]);
                    MMA16816(acc[mt][nt*2+0], al[mt], bh4[0], bh4[2]);
                    MMA16816(acc[mt][nt*2+1], al[mt], bh4[1], bh4[3]);
                }
            }
        }
        __syncthreads();
    }

    int r0 = lane >> 2, c0 = (lane & 3) * 2;
    #pragma unroll
    for (int mt = 0; mt < 2; ++mt) {
        #pragma unroll
        for (int nt = 0; nt < 4; ++nt) {
            #pragma unroll
            for (int s = 0; s < 2; ++s) {
                float* a4 = acc[mt][nt*2+s];
                int col = bn + wn + nt * 16 + s * 8 + c0;
                int row = bm + wm + mt * 16 + r0;
                float v0 = a4[0], v1 = a4[1], v2 = a4[2], v3 = a4[3];
                if (EPI == 2) {
                    v0 = v0 / (1.f + __expf(-v0));
                    v1 = v1 / (1.f + __expf(-v1));
                    v2 = v2 / (1.f + __expf(-v2));
                    v3 = v3 / (1.f + __expf(-v3));
                }
                *reinterpret_cast<float2*>(C + (size_t)row * 512 + col)       = make_float2(v0, v1);
                *reinterpret_cast<float2*>(C + (size_t)(row + 8) * 512 + col) = make_float2(v2, v3);
            }
        }
    }
}

// ---------------------------------------------------------------------------
// SIMT SGEMM. MIXA: A element = x + (xshift - x) * tmx  computed on the fly.
// EPI: 0 none, 1 tanh, 3 exp(-exp(bias+v)).
// ---------------------------------------------------------------------------
template<bool BT_MAJOR, int EPI, bool MIXA>
__global__ void __launch_bounds__(256) sgemm_kernel(
    const float* __restrict__ A, const float* __restrict__ Bm,
    float* __restrict__ Cout, const float* __restrict__ bias,
    const float* __restrict__ tmx,
    int M, int N, int K)
{
    __shared__ float As[16][65];
    __shared__ float Bs[16][65];
    int tid = threadIdx.x;
    int bm = blockIdx.y * 64;
    int bn = blockIdx.x * 64;
    int tx = tid & 15, ty = tid >> 4;
    float acc[4][4] = {};
    int arow = tid >> 2, aseg = tid & 3;

    for (int k0 = 0; k0 < K; k0 += 16) {
        int grow = bm + arow;
        const float* ap = A + (size_t)grow * K + k0 + aseg * 4;
        float4 a4 = *reinterpret_cast<const float4*>(ap);
        if (MIXA) {
            float4 xp = make_float4(0.f, 0.f, 0.f, 0.f);
            if (grow & (TT - 1)) xp = *reinterpret_cast<const float4*>(ap - K);
            float4 tm = *reinterpret_cast<const float4*>(tmx + k0 + aseg * 4);
            a4.x += (xp.x - a4.x) * tm.x;
            a4.y += (xp.y - a4.y) * tm.y;
            a4.z += (xp.z - a4.z) * tm.z;
            a4.w += (xp.w - a4.w) * tm.w;
        }
        As[aseg*4+0][arow] = a4.x; As[aseg*4+1][arow] = a4.y;
        As[aseg*4+2][arow] = a4.z; As[aseg*4+3][arow] = a4.w;

        if (BT_MAJOR) {
            int n = tid >> 2, seg = tid & 3;
            float4 b4 = make_float4(0.f, 0.f, 0.f, 0.f);
            if (bn + n < N)
                b4 = *reinterpret_cast<const float4*>(
                    Bm + (size_t)(bn + n) * K + k0 + seg * 4);
            Bs[seg*4+0][n] = b4.x; Bs[seg*4+1][n] = b4.y;
            Bs[seg*4+2][n] = b4.z; Bs[seg*4+3][n] = b4.w;
        } else {
            int kk = tid >> 4, nb = (tid & 15) * 4;
            float4 b4 = make_float4(0.f, 0.f, 0.f, 0.f);
            if (bn + nb < N)
                b4 = *reinterpret_cast<const float4*>(
                    Bm + (size_t)(k0 + kk) * N + bn + nb);
            Bs[kk][nb+0] = b4.x; Bs[kk][nb+1] = b4.y;
            Bs[kk][nb+2] = b4.z; Bs[kk][nb+3] = b4.w;
        }
        __syncthreads();

        #pragma unroll
        for (int kk = 0; kk < 16; ++kk) {
            float ar[4], br[4];
            #pragma unroll
            for (int q = 0; q < 4; ++q) ar[q] = As[kk][ty*4 + q];
            #pragma unroll
            for (int p = 0; p < 4; ++p) br[p] = Bs[kk][tx*4 + p];
            #pragma unroll
            for (int q = 0; q < 4; ++q)
                #pragma unroll
                for (int p = 0; p < 4; ++p)
                    acc[q][p] = fmaf(ar[q], br[p], acc[q][p]);
        }
        __syncthreads();
    }

    #pragma unroll
    for (int q = 0; q < 4; ++q) {
        int row = bm + ty*4 + q;
        #pragma unroll
        for (int p = 0; p < 4; ++p) {
            int col = bn + tx*4 + p;
            if (col < N) {
                float v = acc[q][p];
                if (EPI == 1) v = tanhf(v);
                else if (EPI == 3) v = __expf(-__expf(bias[col] + v));
                Cout[(size_t)row * N + col] = v;
            }
        }
    }
}

// ---------------------------------------------------------------------------
// split helper
// ---------------------------------------------------------------------------
__device__ __forceinline__ void wsplit(float v, __nv_bfloat16* hi, __nv_bfloat16* lo, size_t i) {
    __nv_bfloat16 h = __float2bfloat16(v);
    hi[i] = h;
    lo[i] = __float2bfloat16(v - __bfloat162float(h));
}

// ---------------------------------------------------------------------------
// mix back-projection + 5-way token mix. Block = 8 bt rows x 512 c.
// ---------------------------------------------------------------------------
__global__ void __launch_bounds__(512, 2) mix_combine_kernel(
    const float* __restrict__ x, const float* __restrict__ mix,
    const float* __restrict__ W2,
    const float* __restrict__ maaw, const float* __restrict__ maak,
    const float* __restrict__ maav, const float* __restrict__ maar,
    const float* __restrict__ maag,
    float* __restrict__ xw,
    __nv_bfloat16* __restrict__ kh, __nv_bfloat16* __restrict__ kl,
    __nv_bfloat16* __restrict__ vh, __nv_bfloat16* __restrict__ vl,
    __nv_bfloat16* __restrict__ rh, __nv_bfloat16* __restrict__ rl,
    __nv_bfloat16* __restrict__ gh, __nv_bfloat16* __restrict__ gl)
{
    __shared__ float s_mix[8][160];
    __shared__ float s_x[9][512];     // [0] = prev row of first
    int bt0 = blockIdx.x * 8;
    int c = threadIdx.x;

    for (int i = threadIdx.x; i < 8 * 160; i += 512)
        s_mix[i / 160][i % 160] = mix[(size_t)bt0 * 160 + i];
    #pragma unroll
    for (int row = 0; row < 8; ++row)
        s_x[row + 1][c] = x[(size_t)(bt0 + row) * 512 + c];
    s_x[0][c] = (bt0 & (TT - 1)) ? x[(size_t)(bt0 - 1) * 512 + c] : 0.f;
    __syncthreads();

    float maa[5];
    maa[0] = maaw[c]; maa[1] = maak[c]; maa[2] = maav[c];
    maa[3] = maar[c]; maa[4] = maag[c];

    #pragma unroll
    for (int f = 0; f < 5; ++f) {
        float acc[8];
        #pragma unroll
        for (int row = 0; row < 8; ++row) acc[row] = 0.f;
        #pragma unroll 8
        for (int dd = 0; dd < 32; ++dd) {
            float w = W2[(size_t)(f * 32 + dd) * 512 + c];
            #pragma unroll
            for (int row = 0; row < 8; ++row)
                acc[row] = fmaf(s_mix[row][f * 32 + dd], w, acc[row]);
        }
        #pragma unroll
        for (int row = 0; row < 8; ++row) {
            size_t gi = (size_t)(bt0 + row) * 512 + c;
            float xc = s_x[row + 1][c];
            float xp = s_x[row][c];
            float v = fmaf(xp - xc, maa[f] + acc[row], xc);
            if (f == 0) xw[gi] = v;
            else if (f == 1) wsplit(v, kh, kl, gi);
            else if (f == 2) wsplit(v, vh, vl, gi);
            else if (f == 3) wsplit(v, rh, rl, gi);
            else             wsplit(v, gh, gl, gi);
        }
    }
}

// ---------------------------------------------------------------------------
// All weight fp32 -> bf16 hi/lo splits in one launch (grid.y = which weight)
// ---------------------------------------------------------------------------
__global__ void convw_all_kernel(const float* __restrict__ W0, const float* __restrict__ W1,
                                 const float* __restrict__ W2, const float* __restrict__ W3,
                                 const float* __restrict__ W4,
                                 __nv_bfloat16* __restrict__ H0, __nv_bfloat16* __restrict__ L0,
                                 __nv_bfloat16* __restrict__ H1, __nv_bfloat16* __restrict__ L1,
                                 __nv_bfloat16* __restrict__ H2, __nv_bfloat16* __restrict__ L2,
                                 __nv_bfloat16* __restrict__ H3, __nv_bfloat16* __restrict__ L3,
                                 __nv_bfloat16* __restrict__ H4, __nv_bfloat16* __restrict__ L4)
{
    int w = blockIdx.y;
    const float* W = (w == 0) ? W0 : (w == 1) ? W1 : (w == 2) ? W2 : (w == 3) ? W3 : W4;
    __nv_bfloat16* H = (w == 0) ? H0 : (w == 1) ? H1 : (w == 2) ? H2 : (w == 3) ? H3 : H4;
    __nv_bfloat16* L = (w == 0) ? L0 : (w == 1) ? L1 : (w == 2) ? L2 : (w == 3) ? L3 : L4;
    int i = blockIdx.x * 256 + threadIdx.x;
    float v = W[i];
    __nv_bfloat16 h = __float2bfloat16(v);
    H[i] = h;
    L[i] = __float2bfloat16(v - __bfloat162float(h));
}

// ---------------------------------------------------------------------------
// WKV6 scan + fused per-head groupnorm * ln * gate -> bf16 hi/lo (zh, zl).
// One block per (b,h); warp = output dim i, lane = key dim j in the scan;
// in the write phase warp = time row, lane = head channel.
// ---------------------------------------------------------------------------
__global__ void __launch_bounds__(1024) wkv_kernel(
    const float* __restrict__ r, const float* __restrict__ k,
    const float* __restrict__ v, const float* __restrict__ d,
    const float* __restrict__ u, const float* __restrict__ gate,
    const float* __restrict__ lnw, const float* __restrict__ lnb,
    __nv_bfloat16* __restrict__ zh, __nv_bfloat16* __restrict__ zl)
{
    int bh = blockIdx.x;
    int b = bh / HH, h = bh % HH;
    int warp = threadIdx.x >> 5;
    int lane = threadIdx.x & 31;
    __shared__ float ys[32][32];

    float uj = u[h * HSZ + lane];
    float lw = lnw[h * HSZ + lane];
    float lb = lnb[h * HSZ + lane];
    float S = 0.f;
    size_t base = ((size_t)b * TT) * CC + h * HSZ;

    for (int t0 = 0; t0 < TT; t0 += 32) {
        #pragma unroll 4
        for (int tt = 0; tt < 32; ++tt) {
            size_t off = base + (size_t)(t0 + tt) * CC;
            float rj = r[off + lane];
            float kj = k[off + lane];
            float dj = d[off + lane];
            float vi = v[off + warp];
            float a  = kj * vi;
            float p  = rj * S + (rj * uj) * a;
            #pragma unroll
            for (int s = 16; s; s >>= 1)
                p += __shfl_xor_sync(0xffffffffu, p, s);
            S = fmaf(dj, S, a);
            if (lane == 0) ys[tt][warp] = p;
        }
        __syncthreads();
        {
            // groupnorm over the 32 head channels (lanes) of time row (warp)
            size_t off = base + (size_t)(t0 + warp) * CC;
            float yv = ys[warp][lane];
            float s = yv;
            #pragma unroll
            for (int o = 16; o; o >>= 1) s += __shfl_xor_sync(0xffffffffu, s, o);
            float mu = s * (1.f / 32.f);
            float dv = yv - mu;
            float q = dv * dv;
            #pragma unroll
            for (int o = 16; o; o >>= 1) q += __shfl_xor_sync(0xffffffffu, q, o);
            float yn = dv * rsqrtf(q * (1.f / 32.f) + 1e-5f);
            float z = (yn * lw + lb) * gate[off + lane];
            wsplit(z, zh, zl, off + lane);
        }
        __syncthreads();
    }
}

// ---------------------------------------------------------------------------
extern "C" void kernel_launch(void* const* d_in, const int* in_sizes, int n_in,
                              void* d_out, int out_size) {
    const float* x      = (const float*)d_in[0];
    const float* tmaa_x = (const float*)d_in[1];
    const float* tmaa_w = (const float*)d_in[2];
    const float* tmaa_k = (const float*)d_in[3];
    const float* tmaa_v = (const float*)d_in[4];
    const float* tmaa_r = (const float*)d_in[5];
    const float* tmaa_g = (const float*)d_in[6];
    const float* w1     = (const float*)d_in[7];   // (C,160)
    const float* w2     = (const float*)d_in[8];   // (5,32,C)
    const float* tdecay = (const float*)d_in[9];   // (C,)
    const float* tdw1   = (const float*)d_in[10];  // (C,64)
    const float* tdw2   = (const float*)d_in[11];  // (64,C)
    const float* faaaa  = (const float*)d_in[12];  // (H,HS)
    const float* Wr     = (const float*)d_in[13];
    const float* Wk     = (const float*)d_in[14];
    const float* Wv     = (const float*)d_in[15];
    const float* Wg     = (const float*)d_in[16];
    const float* Wo     = (const float*)d_in[17];
    const float* lnw    = (const float*)d_in[18];
    const float* lnb    = (const float*)d_in[19];
    float* out = (float*)d_out;

    unsigned char* S;
    cudaGetSymbolAddress((void**)&S, g_scratch);
    float* mixb = (float*)(S + O_MIX);
    float* xw   = (float*)(S + O_XW);
    float* w64  = (float*)(S + O_W64);
    float* db   = (float*)(S + O_DB);
    float* rb   = (float*)(S + O_RB);
    float* kb   = (float*)(S + O_KB);
    float* vb   = (float*)(S + O_VB);
    float* gb   = (float*)(S + O_GB);
    __nv_bfloat16* kh = (__nv_bfloat16*)(S + O_KH);
    __nv_bfloat16* kl = (__nv_bfloat16*)(S + O_KL);
    __nv_bfloat16* vh = (__nv_bfloat16*)(S + O_VH);
    __nv_bfloat16* vl = (__nv_bfloat16*)(S + O_VL);
    __nv_bfloat16* rh = (__nv_bfloat16*)(S + O_RH);
    __nv_bfloat16* rl = (__nv_bfloat16*)(S + O_RL);
    __nv_bfloat16* gh = (__nv_bfloat16*)(S + O_GH);
    __nv_bfloat16* gl = (__nv_bfloat16*)(S + O_GL);
    __nv_bfloat16* zh = (__nv_bfloat16*)(S + O_ZH);
    __nv_bfloat16* zl = (__nv_bfloat16*)(S + O_ZL);
    __nv_bfloat16* wrh = (__nv_bfloat16*)(S + O_WRH);
    __nv_bfloat16* wrl = (__nv_bfloat16*)(S + O_WRL);
    __nv_bfloat16* wkh = (__nv_bfloat16*)(S + O_WKH);
    __nv_bfloat16* wkl = (__nv_bfloat16*)(S + O_WKL);
    __nv_bfloat16* wvh = (__nv_bfloat16*)(S + O_WVH);
    __nv_bfloat16* wvl = (__nv_bfloat16*)(S + O_WVL);
    __nv_bfloat16* wgh = (__nv_bfloat16*)(S + O_WGH);
    __nv_bfloat16* wgl = (__nv_bfloat16*)(S + O_WGL);
    __nv_bfloat16* woh = (__nv_bfloat16*)(S + O_WOH);
    __nv_bfloat16* wol = (__nv_bfloat16*)(S + O_WOL);

    cudaFuncSetAttribute(tgemm_kernel<0>, cudaFuncAttributeMaxDynamicSharedMemorySize, TG_SMEM);
    cudaFuncSetAttribute(tgemm_kernel<2>, cudaFuncAttributeMaxDynamicSharedMemorySize, TG_SMEM);

    // 0) weight splits, one launch
    convw_all_kernel<<<dim3(1024, 5), 256>>>(Wr, Wk, Wv, Wg, Wo,
                                             wrh, wrl, wkh, wkl, wvh, wvl,
                                             wgh, wgl, woh, wol);

    // 1) mix = tanh((x + (shift(x)-x)*maa_x) @ w1)   [BT,160], prep fused
    sgemm_kernel<false, 1, true><<<dim3(3, BT / 64), 256>>>(
        x, w1, mixb, nullptr, tmaa_x, BT, 160, CC);

    // 2) 5-way mix back-projection + token mixing (8 bt rows per block)
    mix_combine_kernel<<<BT / 8, 512>>>(x, mixb, w2, tmaa_w, tmaa_k, tmaa_v,
                                        tmaa_r, tmaa_g, xw, kh, kl, vh, vl,
                                        rh, rl, gh, gl);

    // 3) projections on tensor cores (mma.sync, split-bf16, cp.async pipeline)
    tgemm_kernel<0><<<dim3(4, BT / 128), 256, TG_SMEM>>>(rh, rl, wrh, wrl, rb);
    tgemm_kernel<0><<<dim3(4, BT / 128), 256, TG_SMEM>>>(kh, kl, wkh, wkl, kb);
    tgemm_kernel<0><<<dim3(4, BT / 128), 256, TG_SMEM>>>(vh, vl, wvh, wvl, vb);
    tgemm_kernel<2><<<dim3(4, BT / 128), 256, TG_SMEM>>>(gh, gl, wgh, wgl, gb);

    // 4) decay MLP: w64 = tanh(xw @ tdw1); d = exp(-exp(tdecay + w64 @ tdw2))
    sgemm_kernel<false, 1, false><<<dim3(1, BT / 64), 256>>>(
        xw, tdw1, w64, nullptr, nullptr, BT, 64, CC);
    sgemm_kernel<false, 3, false><<<dim3(8, BT / 64), 256>>>(
        w64, tdw2, db, tdecay, nullptr, BT, CC, 64);

    // 5) WKV6 scan + fused groupnorm*ln*gate -> zh/zl
    wkv_kernel<<<BQ * HH, 1024>>>(rb, kb, vb, db, faaaa, gb, lnw, lnb, zh, zl);

    // 6) out = z @ Wo^T (tensor cores)
    tgemm_kernel<0><<<dim3(4, BT / 128), 256, TG_SMEM>>>(zh, zl, woh, wol, out);
}

// round 6
// speedup vs baseline: 1.1829x; 1.1829x over previous
#include <cuda_runtime.h>
#include <cuda_bf16.h>
#include <cstdint>

#define BQ 8
#define TT 2048
#define CC 512
#define HH 16
#define HSZ 32
#define BT (BQ*TT)            // 16384
#define UEL ((size_t)BT*CC)   // 8388608 elements per [B,T,C] buffer

// ---------------------------------------------------------------------------
// Scratch (bytes). One big device array; no allocations anywhere.
// ---------------------------------------------------------------------------
#define SZ_F32   (UEL*4)
#define SZ_BF16  (UEL*2)
#define SZ_MIX   ((size_t)BT*160*4)
#define SZ_W64   ((size_t)BT*64*4)
#define SZ_WBF   ((size_t)CC*CC*2)

#define O_MIX   ((size_t)0)
#define O_XW    (O_MIX + SZ_MIX)
#define O_W64   (O_XW + SZ_F32)
#define O_DB    (O_W64 + SZ_W64)
#define O_RB    (O_DB + SZ_F32)
#define O_KB    (O_RB + SZ_F32)
#define O_VB    (O_KB + SZ_F32)
#define O_GB    (O_VB + SZ_F32)
#define O_YB    (O_GB + SZ_F32)
#define O_KH    (O_YB + SZ_F32)
#define O_KL    (O_KH + SZ_BF16)
#define O_VH    (O_KL + SZ_BF16)
#define O_VL    (O_VH + SZ_BF16)
#define O_RH    (O_VL + SZ_BF16)
#define O_RL    (O_RH + SZ_BF16)
#define O_GH    (O_RL + SZ_BF16)
#define O_GL    (O_GH + SZ_BF16)
#define O_ZH    (O_GL + SZ_BF16)
#define O_ZL    (O_ZH + SZ_BF16)
#define O_WRH   (O_ZL + SZ_BF16)
#define O_WRL   (O_WRH + SZ_WBF)
#define O_WKH   (O_WRL + SZ_WBF)
#define O_WKL   (O_WKH + SZ_WBF)
#define O_WVH   (O_WKL + SZ_WBF)
#define O_WVL   (O_WVH + SZ_WBF)
#define O_WGH   (O_WVL + SZ_WBF)
#define O_WGL   (O_WGH + SZ_WBF)
#define O_WOH   (O_WGL + SZ_WBF)
#define O_WOL   (O_WOH + SZ_WBF)
#define SCRATCH_BYTES (O_WOL + SZ_WBF)

__device__ __align__(256) unsigned char g_scratch[SCRATCH_BYTES];

// ---------------------------------------------------------------------------
// mma.sync / cp.async helpers (valid on plain compute_103 / sm_80+)
// ---------------------------------------------------------------------------
__device__ __forceinline__ uint32_t smem_u32(const void* p) {
    uint32_t a;
    asm("{ .reg .u64 t; cvta.to.shared.u64 t, %1; cvt.u32.u64 %0, t; }"
        : "=r"(a) : "l"(p));
    return a;
}

#define LDSM4(r, a) \
    asm volatile("ldmatrix.sync.aligned.m8n8.x4.shared.b16 {%0,%1,%2,%3}, [%4];" \
        : "=r"((r)[0]), "=r"((r)[1]), "=r"((r)[2]), "=r"((r)[3]) : "r"(a))

#define MMA16816(d, a, b0, b1) \
    asm volatile("mma.sync.aligned.m16n8k16.row.col.f32.bf16.bf16.f32 " \
        "{%0,%1,%2,%3}, {%4,%5,%6,%7}, {%8,%9}, {%0,%1,%2,%3};" \
        : "+f"((d)[0]), "+f"((d)[1]), "+f"((d)[2]), "+f"((d)[3]) \
        : "r"((a)[0]), "r"((a)[1]), "r"((a)[2]), "r"((a)[3]), "r"(b0), "r"(b1))

#define CP_ASYNC16(dst, src) \
    asm volatile("cp.async.cg.shared.global [%0], [%1], 16;" :: "r"(dst), "l"(src))
#define CP_COMMIT() asm volatile("cp.async.commit_group;" ::: "memory")
#define CP_WAIT(n)  asm volatile("cp.async.wait_group %0;" :: "n"(n) : "memory")

// ---------------------------------------------------------------------------
// Pipelined tensor-core GEMM: C[M,512] = epi(A @ W^T), split bf16 (hi/lo),
// 3 terms: Ah*Bh + Ah*Bl + Al*Bh. Tile 128x128, K-chunk 32, cp.async 2-stage.
// Batched over blockIdx.z: 4 independent (A,B,C) problems in one launch.
// ---------------------------------------------------------------------------
#define TROWB 80
#define TTILE (128*TROWB)     // 10240
#define TSTAGE (4*TTILE)      // 40960
#define TG_SMEM (2*TSTAGE)    // 81920

struct TGBatch {
    const __nv_bfloat16 *ah[4], *al[4], *bh[4], *bl[4];
    float* c[4];
};

__device__ __forceinline__ void tg_stage_loads(
    uint32_t smb, int stage,
    const __nv_bfloat16* __restrict__ Ah, const __nv_bfloat16* __restrict__ Al,
    const __nv_bfloat16* __restrict__ Bh, const __nv_bfloat16* __restrict__ Bl,
    int bm, int bn, int k0, int tid)
{
    uint32_t sbase = smb + stage * TSTAGE;
    #pragma unroll
    for (int m = 0; m < 4; ++m) {
        const __nv_bfloat16* G = (m == 0) ? Ah : (m == 1) ? Al : (m == 2) ? Bh : Bl;
        int rbase = (m < 2) ? bm : bn;
        #pragma unroll
        for (int it = 0; it < 2; ++it) {
            int idx = it * 256 + tid;          // 0..511
            int row = idx >> 2, g = idx & 3;
            uint32_t d = sbase + m * TTILE + row * TROWB + g * 16;
            const void* src = G + (size_t)(rbase + row) * 512 + k0 + g * 8;
            CP_ASYNC16(d, src);
        }
    }
}

template<bool BATCH, int EPI>
__global__ void __launch_bounds__(256, 2)
tgemm_kernel(TGBatch bt_,
             const __nv_bfloat16* __restrict__ Ah_, const __nv_bfloat16* __restrict__ Al_,
             const __nv_bfloat16* __restrict__ Bh_, const __nv_bfloat16* __restrict__ Bl_,
             float* __restrict__ C_)
{
    extern __shared__ unsigned char sm[];
    uint32_t smb = smem_u32(sm);
    int tid = threadIdx.x;
    int wid = tid >> 5, lane = tid & 31;
    int bm = blockIdx.y * 128, bn = blockIdx.x * 128;
    int wm = (wid & 3) * 32, wn = (wid >> 2) * 64;

    int z = BATCH ? blockIdx.z : 0;
    const __nv_bfloat16* Ah = BATCH ? bt_.ah[z] : Ah_;
    const __nv_bfloat16* Al = BATCH ? bt_.al[z] : Al_;
    const __nv_bfloat16* Bh = BATCH ? bt_.bh[z] : Bh_;
    const __nv_bfloat16* Bl = BATCH ? bt_.bl[z] : Bl_;
    float* C = BATCH ? bt_.c[z] : C_;
    bool do_silu = BATCH ? (z == 3) : (EPI == 2);

    float acc[2][8][4];
    #pragma unroll
    for (int i = 0; i < 2; ++i)
        #pragma unroll
        for (int j = 0; j < 8; ++j)
            #pragma unroll
            for (int q = 0; q < 4; ++q) acc[i][j][q] = 0.f;

    int mat = lane >> 3, r8 = lane & 7;
    int lrow = (mat & 1) * 8 + r8;
    int lkb  = (mat >> 1) * 16;

    tg_stage_loads(smb, 0, Ah, Al, Bh, Bl, bm, bn, 0, tid);
    CP_COMMIT();

    for (int ch = 0; ch < 16; ++ch) {
        if (ch + 1 < 16) {
            tg_stage_loads(smb, (ch + 1) & 1, Ah, Al, Bh, Bl, bm, bn, (ch + 1) * 32, tid);
            CP_COMMIT();
            CP_WAIT(1);
        } else {
            CP_WAIT(0);
        }
        __syncthreads();

        uint32_t sbase = smb + (ch & 1) * TSTAGE;
        #pragma unroll
        for (int ks = 0; ks < 2; ++ks) {
            uint32_t ah[2][4], al[2][4];
            #pragma unroll
            for (int mt = 0; mt < 2; ++mt) {
                uint32_t ra = sbase + (wm + mt * 16 + lrow) * TROWB + ks * 32 + lkb;
                LDSM4(ah[mt], ra);
                LDSM4(al[mt], ra + TTILE);
            }
            #pragma unroll
            for (int nt = 0; nt < 4; ++nt) {
                uint32_t rb = sbase + 2 * TTILE + (wn + nt * 16 + lrow) * TROWB + ks * 32 + lkb;
                uint32_t bh4[4], bl4[4];
                LDSM4(bh4, rb);
                LDSM4(bl4, rb + TTILE);
                #pragma unroll
                for (int mt = 0; mt < 2; ++mt) {
                    MMA16816(acc[mt][nt*2+0], ah[mt], bh4[0], bh4[2]);
                    MMA16816(acc[mt][nt*2+1], ah[mt], bh4[1], bh4[3]);
                    MMA16816(acc[mt][nt*2+0], ah[mt], bl4[0], bl4[2]);
                    MMA16816(acc[mt][nt*2+1], ah[mt], bl4[1], bl4[3]);
                    MMA16816(acc[mt][nt*2+0], al[mt], bh4[0], bh4[2]);
                    MMA16816(acc[mt][nt*2+1], al[mt], bh4[1], bh4[3]);
                }
            }
        }
        __syncthreads();
    }

    int r0 = lane >> 2, c0 = (lane & 3) * 2;
    #pragma unroll
    for (int mt = 0; mt < 2; ++mt) {
        #pragma unroll
        for (int nt = 0; nt < 4; ++nt) {
            #pragma unroll
            for (int s = 0; s < 2; ++s) {
                float* a4 = acc[mt][nt*2+s];
                int col = bn + wn + nt * 16 + s * 8 + c0;
                int row = bm + wm + mt * 16 + r0;
                float v0 = a4[0], v1 = a4[1], v2 = a4[2], v3 = a4[3];
                if (do_silu) {
                    v0 = v0 / (1.f + __expf(-v0));
                    v1 = v1 / (1.f + __expf(-v1));
                    v2 = v2 / (1.f + __expf(-v2));
                    v3 = v3 / (1.f + __expf(-v3));
                }
                *reinterpret_cast<float2*>(C + (size_t)row * 512 + col)       = make_float2(v0, v1);
                *reinterpret_cast<float2*>(C + (size_t)(row + 8) * 512 + col) = make_float2(v2, v3);
            }
        }
    }
}

// ---------------------------------------------------------------------------
// SIMT SGEMM. MIXA: A element = x + (xshift - x) * tmx computed on the fly.
// EPI: 0 none, 1 tanh, 3 exp(-exp(bias+v)).
// ---------------------------------------------------------------------------
template<bool BT_MAJOR, int EPI, bool MIXA>
__global__ void __launch_bounds__(256) sgemm_kernel(
    const float* __restrict__ A, const float* __restrict__ Bm,
    float* __restrict__ Cout, const float* __restrict__ bias,
    const float* __restrict__ tmx,
    int M, int N, int K)
{
    __shared__ float As[16][65];
    __shared__ float Bs[16][65];
    int tid = threadIdx.x;
    int bm = blockIdx.y * 64;
    int bn = blockIdx.x * 64;
    int tx = tid & 15, ty = tid >> 4;
    float acc[4][4] = {};
    int arow = tid >> 2, aseg = tid & 3;

    for (int k0 = 0; k0 < K; k0 += 16) {
        int grow = bm + arow;
        const float* ap = A + (size_t)grow * K + k0 + aseg * 4;
        float4 a4 = *reinterpret_cast<const float4*>(ap);
        if (MIXA) {
            float4 xp = make_float4(0.f, 0.f, 0.f, 0.f);
            if (grow & (TT - 1)) xp = *reinterpret_cast<const float4*>(ap - K);
            float4 tm = *reinterpret_cast<const float4*>(tmx + k0 + aseg * 4);
            a4.x += (xp.x - a4.x) * tm.x;
            a4.y += (xp.y - a4.y) * tm.y;
            a4.z += (xp.z - a4.z) * tm.z;
            a4.w += (xp.w - a4.w) * tm.w;
        }
        As[aseg*4+0][arow] = a4.x; As[aseg*4+1][arow] = a4.y;
        As[aseg*4+2][arow] = a4.z; As[aseg*4+3][arow] = a4.w;

        if (BT_MAJOR) {
            int n = tid >> 2, seg = tid & 3;
            float4 b4 = make_float4(0.f, 0.f, 0.f, 0.f);
            if (bn + n < N)
                b4 = *reinterpret_cast<const float4*>(
                    Bm + (size_t)(bn + n) * K + k0 + seg * 4);
            Bs[seg*4+0][n] = b4.x; Bs[seg*4+1][n] = b4.y;
            Bs[seg*4+2][n] = b4.z; Bs[seg*4+3][n] = b4.w;
        } else {
            int kk = tid >> 4, nb = (tid & 15) * 4;
            float4 b4 = make_float4(0.f, 0.f, 0.f, 0.f);
            if (bn + nb < N)
                b4 = *reinterpret_cast<const float4*>(
                    Bm + (size_t)(k0 + kk) * N + bn + nb);
            Bs[kk][nb+0] = b4.x; Bs[kk][nb+1] = b4.y;
            Bs[kk][nb+2] = b4.z; Bs[kk][nb+3] = b4.w;
        }
        __syncthreads();

        #pragma unroll
        for (int kk = 0; kk < 16; ++kk) {
            float ar[4], br[4];
            #pragma unroll
            for (int q = 0; q < 4; ++q) ar[q] = As[kk][ty*4 + q];
            #pragma unroll
            for (int p = 0; p < 4; ++p) br[p] = Bs[kk][tx*4 + p];
            #pragma unroll
            for (int q = 0; q < 4; ++q)
                #pragma unroll
                for (int p = 0; p < 4; ++p)
                    acc[q][p] = fmaf(ar[q], br[p], acc[q][p]);
        }
        __syncthreads();
    }

    #pragma unroll
    for (int q = 0; q < 4; ++q) {
        int row = bm + ty*4 + q;
        #pragma unroll
        for (int p = 0; p < 4; ++p) {
            int col = bn + tx*4 + p;
            if (col < N) {
                float v = acc[q][p];
                if (EPI == 1) v = tanhf(v);
                else if (EPI == 3) v = __expf(-__expf(bias[col] + v));
                Cout[(size_t)row * N + col] = v;
            }
        }
    }
}

// ---------------------------------------------------------------------------
// split helper
// ---------------------------------------------------------------------------
__device__ __forceinline__ void wsplit(float v, __nv_bfloat16* hi, __nv_bfloat16* lo, size_t i) {
    __nv_bfloat16 h = __float2bfloat16(v);
    hi[i] = h;
    lo[i] = __float2bfloat16(v - __bfloat162float(h));
}

// ---------------------------------------------------------------------------
// mix back-projection + 5-way token mix. Block = 16 bt rows x 512 c.
// (R4 configuration: known 140us)
// ---------------------------------------------------------------------------
__global__ void __launch_bounds__(512) mix_combine_kernel(
    const float* __restrict__ x, const float* __restrict__ mix,
    const float* __restrict__ W2,
    const float* __restrict__ maaw, const float* __restrict__ maak,
    const float* __restrict__ maav, const float* __restrict__ maar,
    const float* __restrict__ maag,
    float* __restrict__ xw,
    __nv_bfloat16* __restrict__ kh, __nv_bfloat16* __restrict__ kl,
    __nv_bfloat16* __restrict__ vh, __nv_bfloat16* __restrict__ vl,
    __nv_bfloat16* __restrict__ rh, __nv_bfloat16* __restrict__ rl,
    __nv_bfloat16* __restrict__ gh, __nv_bfloat16* __restrict__ gl)
{
    __shared__ float s_mix[16][160];
    __shared__ float s_x[16][512];
    __shared__ float s_xp0[512];
    int bt0 = blockIdx.x * 16;
    int c = threadIdx.x;

    for (int i = threadIdx.x; i < 16 * 160; i += 512)
        s_mix[i / 160][i % 160] = mix[(size_t)bt0 * 160 + i];
    #pragma unroll
    for (int row = 0; row < 16; ++row)
        s_x[row][c] = x[(size_t)(bt0 + row) * 512 + c];
    s_xp0[c] = (bt0 & (TT - 1)) ? x[(size_t)(bt0 - 1) * 512 + c] : 0.f;
    __syncthreads();

    float maa[5];
    maa[0] = maaw[c]; maa[1] = maak[c]; maa[2] = maav[c];
    maa[3] = maar[c]; maa[4] = maag[c];

    #pragma unroll
    for (int f = 0; f < 5; ++f) {
        float acc[16];
        #pragma unroll
        for (int row = 0; row < 16; ++row) acc[row] = 0.f;
        #pragma unroll 8
        for (int dd = 0; dd < 32; ++dd) {
            float w = W2[(size_t)(f * 32 + dd) * 512 + c];
            #pragma unroll
            for (int row = 0; row < 16; ++row)
                acc[row] = fmaf(s_mix[row][f * 32 + dd], w, acc[row]);
        }
        #pragma unroll
        for (int row = 0; row < 16; ++row) {
            size_t gi = (size_t)(bt0 + row) * 512 + c;
            float xc = s_x[row][c];
            float xp = (row > 0) ? s_x[row - 1][c] : s_xp0[c];
            float v = fmaf(xp - xc, maa[f] + acc[row], xc);
            if (f == 0) xw[gi] = v;
            else if (f == 1) wsplit(v, kh, kl, gi);
            else if (f == 2) wsplit(v, vh, vl, gi);
            else if (f == 3) wsplit(v, rh, rl, gi);
            else             wsplit(v, gh, gl, gi);
        }
    }
}

// ---------------------------------------------------------------------------
// All weight fp32 -> bf16 hi/lo splits in one launch (grid.y = which weight)
// ---------------------------------------------------------------------------
__global__ void convw_all_kernel(const float* __restrict__ W0, const float* __restrict__ W1,
                                 const float* __restrict__ W2, const float* __restrict__ W3,
                                 const float* __restrict__ W4,
                                 __nv_bfloat16* __restrict__ H0, __nv_bfloat16* __restrict__ L0,
                                 __nv_bfloat16* __restrict__ H1, __nv_bfloat16* __restrict__ L1,
                                 __nv_bfloat16* __restrict__ H2, __nv_bfloat16* __restrict__ L2,
                                 __nv_bfloat16* __restrict__ H3, __nv_bfloat16* __restrict__ L3,
                                 __nv_bfloat16* __restrict__ H4, __nv_bfloat16* __restrict__ L4)
{
    int w = blockIdx.y;
    const float* W = (w == 0) ? W0 : (w == 1) ? W1 : (w == 2) ? W2 : (w == 3) ? W3 : W4;
    __nv_bfloat16* H = (w == 0) ? H0 : (w == 1) ? H1 : (w == 2) ? H2 : (w == 3) ? H3 : H4;
    __nv_bfloat16* L = (w == 0) ? L0 : (w == 1) ? L1 : (w == 2) ? L2 : (w == 3) ? L3 : L4;
    int i = blockIdx.x * 256 + threadIdx.x;
    float v = W[i];
    __nv_bfloat16 h = __float2bfloat16(v);
    H[i] = h;
    L[i] = __float2bfloat16(v - __bfloat162float(h));
}

// ---------------------------------------------------------------------------
// WKV6 scan (plain R4 version: no fusion, keeps registers lean).
// One block per (b,h); warp = output dim i, lane = key dim j.
// ---------------------------------------------------------------------------
__global__ void __launch_bounds__(1024) wkv_kernel(
    const float* __restrict__ r, const float* __restrict__ k,
    const float* __restrict__ v, const float* __restrict__ d,
    const float* __restrict__ u, float* __restrict__ y)
{
    int bh = blockIdx.x;
    int b = bh / HH, h = bh % HH;
    int warp = threadIdx.x >> 5;
    int lane = threadIdx.x & 31;
    __shared__ float ys[32][32];

    float uj = u[h * HSZ + lane];
    float S = 0.f;
    size_t base = ((size_t)b * TT) * CC + h * HSZ;

    for (int t0 = 0; t0 < TT; t0 += 32) {
        #pragma unroll 4
        for (int tt = 0; tt < 32; ++tt) {
            size_t off = base + (size_t)(t0 + tt) * CC;
            float rj = r[off + lane];
            float kj = k[off + lane];
            float dj = d[off + lane];
            float vi = v[off + warp];
            float a  = kj * vi;
            float p  = rj * S + (rj * uj) * a;
            #pragma unroll
            for (int s = 16; s; s >>= 1)
                p += __shfl_xor_sync(0xffffffffu, p, s);
            S = fmaf(dj, S, a);
            if (lane == 0) ys[tt][warp] = p;
        }
        __syncthreads();
        {
            size_t off = base + (size_t)(t0 + warp) * CC;
            y[off + lane] = ys[warp][lane];
        }
        __syncthreads();
    }
}

// ---------------------------------------------------------------------------
// Per-head groupnorm * ln * gate -> bf16 hi/lo split for the Wo GEMM
// ---------------------------------------------------------------------------
__global__ void __launch_bounds__(256) gn_kernel(
    const float* __restrict__ y, const float* __restrict__ gate,
    const float* __restrict__ lnw, const float* __restrict__ lnb,
    __nv_bfloat16* __restrict__ zh, __nv_bfloat16* __restrict__ zl)
{
    int g = blockIdx.x * 8 + (threadIdx.x >> 5);
    int lane = threadIdx.x & 31;
    size_t idx = (size_t)g * 32 + lane;
    float v = y[idx];
    float s = v;
    #pragma unroll
    for (int o = 16; o; o >>= 1) s += __shfl_xor_sync(0xffffffffu, s, o);
    float mu = s * (1.f / 32.f);
    float dv = v - mu;
    float q = dv * dv;
    #pragma unroll
    for (int o = 16; o; o >>= 1) q += __shfl_xor_sync(0xffffffffu, q, o);
    float var = q * (1.f / 32.f);
    float yn = dv * rsqrtf(var + 1e-5f);
    int c = (int)(idx & (CC - 1));
    float z = (yn * lnw[c] + lnb[c]) * gate[idx];
    wsplit(z, zh, zl, idx);
}

// ---------------------------------------------------------------------------
extern "C" void kernel_launch(void* const* d_in, const int* in_sizes, int n_in,
                              void* d_out, int out_size) {
    const float* x      = (const float*)d_in[0];
    const float* tmaa_x = (const float*)d_in[1];
    const float* tmaa_w = (const float*)d_in[2];
    const float* tmaa_k = (const float*)d_in[3];
    const float* tmaa_v = (const float*)d_in[4];
    const float* tmaa_r = (const float*)d_in[5];
    const float* tmaa_g = (const float*)d_in[6];
    const float* w1     = (const float*)d_in[7];   // (C,160)
    const float* w2     = (const float*)d_in[8];   // (5,32,C)
    const float* tdecay = (const float*)d_in[9];   // (C,)
    const float* tdw1   = (const float*)d_in[10];  // (C,64)
    const float* tdw2   = (const float*)d_in[11];  // (64,C)
    const float* faaaa  = (const float*)d_in[12];  // (H,HS)
    const float* Wr     = (const float*)d_in[13];
    const float* Wk     = (const float*)d_in[14];
    const float* Wv     = (const float*)d_in[15];
    const float* Wg     = (const float*)d_in[16];
    const float* Wo     = (const float*)d_in[17];
    const float* lnw    = (const float*)d_in[18];
    const float* lnb    = (const float*)d_in[19];
    float* out = (float*)d_out;

    unsigned char* S;
    cudaGetSymbolAddress((void**)&S, g_scratch);
    float* mixb = (float*)(S + O_MIX);
    float* xw   = (float*)(S + O_XW);
    float* w64  = (float*)(S + O_W64);
    float* db   = (float*)(S + O_DB);
    float* rb   = (float*)(S + O_RB);
    float* kb   = (float*)(S + O_KB);
    float* vb   = (float*)(S + O_VB);
    float* gb   = (float*)(S + O_GB);
    float* yb   = (float*)(S + O_YB);
    __nv_bfloat16* kh = (__nv_bfloat16*)(S + O_KH);
    __nv_bfloat16* kl = (__nv_bfloat16*)(S + O_KL);
    __nv_bfloat16* vh = (__nv_bfloat16*)(S + O_VH);
    __nv_bfloat16* vl = (__nv_bfloat16*)(S + O_VL);
    __nv_bfloat16* rh = (__nv_bfloat16*)(S + O_RH);
    __nv_bfloat16* rl = (__nv_bfloat16*)(S + O_RL);
    __nv_bfloat16* gh = (__nv_bfloat16*)(S + O_GH);
    __nv_bfloat16* gl = (__nv_bfloat16*)(S + O_GL);
    __nv_bfloat16* zh = (__nv_bfloat16*)(S + O_ZH);
    __nv_bfloat16* zl = (__nv_bfloat16*)(S + O_ZL);
    __nv_bfloat16* wrh = (__nv_bfloat16*)(S + O_WRH);
    __nv_bfloat16* wrl = (__nv_bfloat16*)(S + O_WRL);
    __nv_bfloat16* wkh = (__nv_bfloat16*)(S + O_WKH);
    __nv_bfloat16* wkl = (__nv_bfloat16*)(S + O_WKL);
    __nv_bfloat16* wvh = (__nv_bfloat16*)(S + O_WVH);
    __nv_bfloat16* wvl = (__nv_bfloat16*)(S + O_WVL);
    __nv_bfloat16* wgh = (__nv_bfloat16*)(S + O_WGH);
    __nv_bfloat16* wgl = (__nv_bfloat16*)(S + O_WGL);
    __nv_bfloat16* woh = (__nv_bfloat16*)(S + O_WOH);
    __nv_bfloat16* wol = (__nv_bfloat16*)(S + O_WOL);

    cudaFuncSetAttribute(tgemm_kernel<true, 0>, cudaFuncAttributeMaxDynamicSharedMemorySize, TG_SMEM);
    cudaFuncSetAttribute(tgemm_kernel<false, 0>, cudaFuncAttributeMaxDynamicSharedMemorySize, TG_SMEM);

    // 0) weight splits, one launch
    convw_all_kernel<<<dim3(1024, 5), 256>>>(Wr, Wk, Wv, Wg, Wo,
                                             wrh, wrl, wkh, wkl, wvh, wvl,
                                             wgh, wgl, woh, wol);

    // 1) mix = tanh((x + (shift(x)-x)*maa_x) @ w1)   [BT,160], prep fused
    sgemm_kernel<false, 1, true><<<dim3(3, BT / 64), 256>>>(
        x, w1, mixb, nullptr, tmaa_x, BT, 160, CC);

    // 2) 5-way mix back-projection + token mixing (16 bt rows per block)
    mix_combine_kernel<<<BT / 16, 512>>>(x, mixb, w2, tmaa_w, tmaa_k, tmaa_v,
                                         tmaa_r, tmaa_g, xw, kh, kl, vh, vl,
                                         rh, rl, gh, gl);

    // 3) 4 projections in ONE batched tensor-core launch (z selects problem;
    //    z==3 (g) applies silu)
    {
        TGBatch bt_{};
        bt_.ah[0] = rh; bt_.al[0] = rl; bt_.bh[0] = wrh; bt_.bl[0] = wrl; bt_.c[0] = rb;
        bt_.ah[1] = kh; bt_.al[1] = kl; bt_.bh[1] = wkh; bt_.bl[1] = wkl; bt_.c[1] = kb;
        bt_.ah[2] = vh; bt_.al[2] = vl; bt_.bh[2] = wvh; bt_.bl[2] = wvl; bt_.c[2] = vb;
        bt_.ah[3] = gh; bt_.al[3] = gl; bt_.bh[3] = wgh; bt_.bl[3] = wgl; bt_.c[3] = gb;
        tgemm_kernel<true, 0><<<dim3(4, BT / 128, 4), 256, TG_SMEM>>>(
            bt_, nullptr, nullptr, nullptr, nullptr, nullptr);
    }

    // 4) decay MLP: w64 = tanh(xw @ tdw1); d = exp(-exp(tdecay + w64 @ tdw2))
    sgemm_kernel<false, 1, false><<<dim3(1, BT / 64), 256>>>(
        xw, tdw1, w64, nullptr, nullptr, BT, 64, CC);
    sgemm_kernel<false, 3, false><<<dim3(8, BT / 64), 256>>>(
        w64, tdw2, db, tdecay, nullptr, BT, CC, 64);

    // 5) WKV6 scan
    wkv_kernel<<<BQ * HH, 1024>>>(rb, kb, vb, db, faaaa, yb);

    // 6) groupnorm * ln * gate -> z (bf16 split)
    gn_kernel<<<(BT * HH) / 8, 256>>>(yb, gb, lnw, lnb, zh, zl);

    // 7) out = z @ Wo^T (tensor cores)
    {
        TGBatch dummy{};
        tgemm_kernel<false, 0><<<dim3(4, BT / 128), 256, TG_SMEM>>>(
            dummy, zh, zl, woh, wol, out);
    }
}

// round 7
// speedup vs baseline: 1.7711x; 1.4973x over previous
#include <cuda_runtime.h>
#include <cuda_bf16.h>
#include <cstdint>

#define BQ 8
#define TT 2048
#define CC 512
#define HH 16
#define HSZ 32
#define BT (BQ*TT)            // 16384
#define UEL ((size_t)BT*CC)   // 8388608 elements per [B,T,C] buffer

// ---------------------------------------------------------------------------
// Scratch (bytes). One big device array; no allocations anywhere.
// ---------------------------------------------------------------------------
#define SZ_F32   (UEL*4)
#define SZ_BF16  (UEL*2)
#define SZ_MIX   ((size_t)BT*160*4)
#define SZ_W64   ((size_t)BT*64*4)
#define SZ_WBF   ((size_t)CC*CC*2)

#define O_MIX   ((size_t)0)
#define O_XW    (O_MIX + SZ_MIX)
#define O_W64   (O_XW + SZ_F32)
#define O_DB    (O_W64 + SZ_W64)
#define O_RB    (O_DB + SZ_F32)
#define O_KB    (O_RB + SZ_F32)
#define O_VB    (O_KB + SZ_F32)
#define O_GB    (O_VB + SZ_F32)
#define O_YB    (O_GB + SZ_F32)
#define O_KH    (O_YB + SZ_F32)
#define O_KL    (O_KH + SZ_BF16)
#define O_VH    (O_KL + SZ_BF16)
#define O_VL    (O_VH + SZ_BF16)
#define O_RH    (O_VL + SZ_BF16)
#define O_RL    (O_RH + SZ_BF16)
#define O_GH    (O_RL + SZ_BF16)
#define O_GL    (O_GH + SZ_BF16)
#define O_ZH    (O_GL + SZ_BF16)
#define O_ZL    (O_ZH + SZ_BF16)
#define O_WRH   (O_ZL + SZ_BF16)
#define O_WRL   (O_WRH + SZ_WBF)
#define O_WKH   (O_WRL + SZ_WBF)
#define O_WKL   (O_WKH + SZ_WBF)
#define O_WVH   (O_WKL + SZ_WBF)
#define O_WVL   (O_WVH + SZ_WBF)
#define O_WGH   (O_WVL + SZ_WBF)
#define O_WGL   (O_WGH + SZ_WBF)
#define O_WOH   (O_WGL + SZ_WBF)
#define O_WOL   (O_WOH + SZ_WBF)
#define SCRATCH_BYTES (O_WOL + SZ_WBF)

__device__ __align__(256) unsigned char g_scratch[SCRATCH_BYTES];

// ---------------------------------------------------------------------------
// mma.sync / cp.async helpers (valid on plain compute_103 / sm_80+)
// ---------------------------------------------------------------------------
__device__ __forceinline__ uint32_t smem_u32(const void* p) {
    uint32_t a;
    asm("{ .reg .u64 t; cvta.to.shared.u64 t, %1; cvt.u32.u64 %0, t; }"
        : "=r"(a) : "l"(p));
    return a;
}

#define LDSM4(r, a) \
    asm volatile("ldmatrix.sync.aligned.m8n8.x4.shared.b16 {%0,%1,%2,%3}, [%4];" \
        : "=r"((r)[0]), "=r"((r)[1]), "=r"((r)[2]), "=r"((r)[3]) : "r"(a))

#define MMA16816(d, a, b0, b1) \
    asm volatile("mma.sync.aligned.m16n8k16.row.col.f32.bf16.bf16.f32 " \
        "{%0,%1,%2,%3}, {%4,%5,%6,%7}, {%8,%9}, {%0,%1,%2,%3};" \
        : "+f"((d)[0]), "+f"((d)[1]), "+f"((d)[2]), "+f"((d)[3]) \
        : "r"((a)[0]), "r"((a)[1]), "r"((a)[2]), "r"((a)[3]), "r"(b0), "r"(b1))

#define CP_ASYNC16(dst, src) \
    asm volatile("cp.async.cg.shared.global [%0], [%1], 16;" :: "r"(dst), "l"(src))
#define CP_COMMIT() asm volatile("cp.async.commit_group;" ::: "memory")
#define CP_WAIT(n)  asm volatile("cp.async.wait_group %0;" :: "n"(n) : "memory")

// ---------------------------------------------------------------------------
// Pipelined tensor-core GEMM: C[M,512] = epi(A @ W^T), split bf16 (hi/lo),
// 3 terms: Ah*Bh + Ah*Bl + Al*Bh. Tile 128x128, K-chunk 32, cp.async 2-stage.
// Batched over blockIdx.z: 4 independent (A,B,C) problems in one launch.
// ---------------------------------------------------------------------------
#define TROWB 80
#define TTILE (128*TROWB)     // 10240
#define TSTAGE (4*TTILE)      // 40960
#define TG_SMEM (2*TSTAGE)    // 81920

struct TGBatch {
    const __nv_bfloat16 *ah[4], *al[4], *bh[4], *bl[4];
    float* c[4];
};

__device__ __forceinline__ void tg_stage_loads(
    uint32_t smb, int stage,
    const __nv_bfloat16* __restrict__ Ah, const __nv_bfloat16* __restrict__ Al,
    const __nv_bfloat16* __restrict__ Bh, const __nv_bfloat16* __restrict__ Bl,
    int bm, int bn, int k0, int tid)
{
    uint32_t sbase = smb + stage * TSTAGE;
    #pragma unroll
    for (int m = 0; m < 4; ++m) {
        const __nv_bfloat16* G = (m == 0) ? Ah : (m == 1) ? Al : (m == 2) ? Bh : Bl;
        int rbase = (m < 2) ? bm : bn;
        #pragma unroll
        for (int it = 0; it < 2; ++it) {
            int idx = it * 256 + tid;          // 0..511
            int row = idx >> 2, g = idx & 3;
            uint32_t d = sbase + m * TTILE + row * TROWB + g * 16;
            const void* src = G + (size_t)(rbase + row) * 512 + k0 + g * 8;
            CP_ASYNC16(d, src);
        }
    }
}

template<bool BATCH, int EPI>
__global__ void __launch_bounds__(256, 2)
tgemm_kernel(TGBatch bt_,
             const __nv_bfloat16* __restrict__ Ah_, const __nv_bfloat16* __restrict__ Al_,
             const __nv_bfloat16* __restrict__ Bh_, const __nv_bfloat16* __restrict__ Bl_,
             float* __restrict__ C_)
{
    extern __shared__ unsigned char sm[];
    uint32_t smb = smem_u32(sm);
    int tid = threadIdx.x;
    int wid = tid >> 5, lane = tid & 31;
    int bm = blockIdx.y * 128, bn = blockIdx.x * 128;
    int wm = (wid & 3) * 32, wn = (wid >> 2) * 64;

    int z = BATCH ? blockIdx.z : 0;
    const __nv_bfloat16* Ah = BATCH ? bt_.ah[z] : Ah_;
    const __nv_bfloat16* Al = BATCH ? bt_.al[z] : Al_;
    const __nv_bfloat16* Bh = BATCH ? bt_.bh[z] : Bh_;
    const __nv_bfloat16* Bl = BATCH ? bt_.bl[z] : Bl_;
    float* C = BATCH ? bt_.c[z] : C_;
    bool do_silu = BATCH ? (z == 3) : (EPI == 2);

    float acc[2][8][4];
    #pragma unroll
    for (int i = 0; i < 2; ++i)
        #pragma unroll
        for (int j = 0; j < 8; ++j)
            #pragma unroll
            for (int q = 0; q < 4; ++q) acc[i][j][q] = 0.f;

    int mat = lane >> 3, r8 = lane & 7;
    int lrow = (mat & 1) * 8 + r8;
    int lkb  = (mat >> 1) * 16;

    tg_stage_loads(smb, 0, Ah, Al, Bh, Bl, bm, bn, 0, tid);
    CP_COMMIT();

    for (int ch = 0; ch < 16; ++ch) {
        if (ch + 1 < 16) {
            tg_stage_loads(smb, (ch + 1) & 1, Ah, Al, Bh, Bl, bm, bn, (ch + 1) * 32, tid);
            CP_COMMIT();
            CP_WAIT(1);
        } else {
            CP_WAIT(0);
        }
        __syncthreads();

        uint32_t sbase = smb + (ch & 1) * TSTAGE;
        #pragma unroll
        for (int ks = 0; ks < 2; ++ks) {
            uint32_t ah[2][4], al[2][4];
            #pragma unroll
            for (int mt = 0; mt < 2; ++mt) {
                uint32_t ra = sbase + (wm + mt * 16 + lrow) * TROWB + ks * 32 + lkb;
                LDSM4(ah[mt], ra);
                LDSM4(al[mt], ra + TTILE);
            }
            #pragma unroll
            for (int nt = 0; nt < 4; ++nt) {
                uint32_t rb = sbase + 2 * TTILE + (wn + nt * 16 + lrow) * TROWB + ks * 32 + lkb;
                uint32_t bh4[4], bl4[4];
                LDSM4(bh4, rb);
                LDSM4(bl4, rb + TTILE);
                #pragma unroll
                for (int mt = 0; mt < 2; ++mt) {
                    MMA16816(acc[mt][nt*2+0], ah[mt], bh4[0], bh4[2]);
                    MMA16816(acc[mt][nt*2+1], ah[mt], bh4[1], bh4[3]);
                    MMA16816(acc[mt][nt*2+0], ah[mt], bl4[0], bl4[2]);
                    MMA16816(acc[mt][nt*2+1], ah[mt], bl4[1], bl4[3]);
                    MMA16816(acc[mt][nt*2+0], al[mt], bh4[0], bh4[2]);
                    MMA16816(acc[mt][nt*2+1], al[mt], bh4[1], bh4[3]);
                }
            }
        }
        __syncthreads();
    }

    int r0 = lane >> 2, c0 = (lane & 3) * 2;
    #pragma unroll
    for (int mt = 0; mt < 2; ++mt) {
        #pragma unroll
        for (int nt = 0; nt < 4; ++nt) {
            #pragma unroll
            for (int s = 0; s < 2; ++s) {
                float* a4 = acc[mt][nt*2+s];
                int col = bn + wn + nt * 16 + s * 8 + c0;
                int row = bm + wm + mt * 16 + r0;
                float v0 = a4[0], v1 = a4[1], v2 = a4[2], v3 = a4[3];
                if (do_silu) {
                    v0 = v0 / (1.f + __expf(-v0));
                    v1 = v1 / (1.f + __expf(-v1));
                    v2 = v2 / (1.f + __expf(-v2));
                    v3 = v3 / (1.f + __expf(-v3));
                }
                *reinterpret_cast<float2*>(C + (size_t)row * 512 + col)       = make_float2(v0, v1);
                *reinterpret_cast<float2*>(C + (size_t)(row + 8) * 512 + col) = make_float2(v2, v3);
            }
        }
    }
}

// ---------------------------------------------------------------------------
// SIMT SGEMM. MIXA: A element = x + (xshift - x) * tmx computed on the fly.
// EPI: 0 none, 1 tanh, 3 exp(-exp(bias+v)).
// ---------------------------------------------------------------------------
template<bool BT_MAJOR, int EPI, bool MIXA>
__global__ void __launch_bounds__(256) sgemm_kernel(
    const float* __restrict__ A, const float* __restrict__ Bm,
    float* __restrict__ Cout, const float* __restrict__ bias,
    const float* __restrict__ tmx,
    int M, int N, int K)
{
    __shared__ float As[16][65];
    __shared__ float Bs[16][65];
    int tid = threadIdx.x;
    int bm = blockIdx.y * 64;
    int bn = blockIdx.x * 64;
    int tx = tid & 15, ty = tid >> 4;
    float acc[4][4] = {};
    int arow = tid >> 2, aseg = tid & 3;

    for (int k0 = 0; k0 < K; k0 += 16) {
        int grow = bm + arow;
        const float* ap = A + (size_t)grow * K + k0 + aseg * 4;
        float4 a4 = *reinterpret_cast<const float4*>(ap);
        if (MIXA) {
            float4 xp = make_float4(0.f, 0.f, 0.f, 0.f);
            if (grow & (TT - 1)) xp = *reinterpret_cast<const float4*>(ap - K);
            float4 tm = *reinterpret_cast<const float4*>(tmx + k0 + aseg * 4);
            a4.x += (xp.x - a4.x) * tm.x;
            a4.y += (xp.y - a4.y) * tm.y;
            a4.z += (xp.z - a4.z) * tm.z;
            a4.w += (xp.w - a4.w) * tm.w;
        }
        As[aseg*4+0][arow] = a4.x; As[aseg*4+1][arow] = a4.y;
        As[aseg*4+2][arow] = a4.z; As[aseg*4+3][arow] = a4.w;

        if (BT_MAJOR) {
            int n = tid >> 2, seg = tid & 3;
            float4 b4 = make_float4(0.f, 0.f, 0.f, 0.f);
            if (bn + n < N)
                b4 = *reinterpret_cast<const float4*>(
                    Bm + (size_t)(bn + n) * K + k0 + seg * 4);
            Bs[seg*4+0][n] = b4.x; Bs[seg*4+1][n] = b4.y;
            Bs[seg*4+2][n] = b4.z; Bs[seg*4+3][n] = b4.w;
        } else {
            int kk = tid >> 4, nb = (tid & 15) * 4;
            float4 b4 = make_float4(0.f, 0.f, 0.f, 0.f);
            if (bn + nb < N)
                b4 = *reinterpret_cast<const float4*>(
                    Bm + (size_t)(k0 + kk) * N + bn + nb);
            Bs[kk][nb+0] = b4.x; Bs[kk][nb+1] = b4.y;
            Bs[kk][nb+2] = b4.z; Bs[kk][nb+3] = b4.w;
        }
        __syncthreads();

        #pragma unroll
        for (int kk = 0; kk < 16; ++kk) {
            float ar[4], br[4];
            #pragma unroll
            for (int q = 0; q < 4; ++q) ar[q] = As[kk][ty*4 + q];
            #pragma unroll
            for (int p = 0; p < 4; ++p) br[p] = Bs[kk][tx*4 + p];
            #pragma unroll
            for (int q = 0; q < 4; ++q)
                #pragma unroll
                for (int p = 0; p < 4; ++p)
                    acc[q][p] = fmaf(ar[q], br[p], acc[q][p]);
        }
        __syncthreads();
    }

    #pragma unroll
    for (int q = 0; q < 4; ++q) {
        int row = bm + ty*4 + q;
        #pragma unroll
        for (int p = 0; p < 4; ++p) {
            int col = bn + tx*4 + p;
            if (col < N) {
                float v = acc[q][p];
                if (EPI == 1) v = tanhf(v);
                else if (EPI == 3) v = __expf(-__expf(bias[col] + v));
                Cout[(size_t)row * N + col] = v;
            }
        }
    }
}

// ---------------------------------------------------------------------------
// split helper
// ---------------------------------------------------------------------------
__device__ __forceinline__ void wsplit(float v, __nv_bfloat16* hi, __nv_bfloat16* lo, size_t i) {
    __nv_bfloat16 h = __float2bfloat16(v);
    hi[i] = h;
    lo[i] = __float2bfloat16(v - __bfloat162float(h));
}

// ---------------------------------------------------------------------------
// mix back-projection + 5-way token mix. Block = 16 bt rows x 512 c.
// ---------------------------------------------------------------------------
__global__ void __launch_bounds__(512) mix_combine_kernel(
    const float* __restrict__ x, const float* __restrict__ mix,
    const float* __restrict__ W2,
    const float* __restrict__ maaw, const float* __restrict__ maak,
    const float* __restrict__ maav, const float* __restrict__ maar,
    const float* __restrict__ maag,
    float* __restrict__ xw,
    __nv_bfloat16* __restrict__ kh, __nv_bfloat16* __restrict__ kl,
    __nv_bfloat16* __restrict__ vh, __nv_bfloat16* __restrict__ vl,
    __nv_bfloat16* __restrict__ rh, __nv_bfloat16* __restrict__ rl,
    __nv_bfloat16* __restrict__ gh, __nv_bfloat16* __restrict__ gl)
{
    __shared__ float s_mix[16][160];
    __shared__ float s_x[16][512];
    __shared__ float s_xp0[512];
    int bt0 = blockIdx.x * 16;
    int c = threadIdx.x;

    for (int i = threadIdx.x; i < 16 * 160; i += 512)
        s_mix[i / 160][i % 160] = mix[(size_t)bt0 * 160 + i];
    #pragma unroll
    for (int row = 0; row < 16; ++row)
        s_x[row][c] = x[(size_t)(bt0 + row) * 512 + c];
    s_xp0[c] = (bt0 & (TT - 1)) ? x[(size_t)(bt0 - 1) * 512 + c] : 0.f;
    __syncthreads();

    float maa[5];
    maa[0] = maaw[c]; maa[1] = maak[c]; maa[2] = maav[c];
    maa[3] = maar[c]; maa[4] = maag[c];

    #pragma unroll
    for (int f = 0; f < 5; ++f) {
        float acc[16];
        #pragma unroll
        for (int row = 0; row < 16; ++row) acc[row] = 0.f;
        #pragma unroll 8
        for (int dd = 0; dd < 32; ++dd) {
            float w = W2[(size_t)(f * 32 + dd) * 512 + c];
            #pragma unroll
            for (int row = 0; row < 16; ++row)
                acc[row] = fmaf(s_mix[row][f * 32 + dd], w, acc[row]);
        }
        #pragma unroll
        for (int row = 0; row < 16; ++row) {
            size_t gi = (size_t)(bt0 + row) * 512 + c;
            float xc = s_x[row][c];
            float xp = (row > 0) ? s_x[row - 1][c] : s_xp0[c];
            float v = fmaf(xp - xc, maa[f] + acc[row], xc);
            if (f == 0) xw[gi] = v;
            else if (f == 1) wsplit(v, kh, kl, gi);
            else if (f == 2) wsplit(v, vh, vl, gi);
            else if (f == 3) wsplit(v, rh, rl, gi);
            else             wsplit(v, gh, gl, gi);
        }
    }
}

// ---------------------------------------------------------------------------
// All weight fp32 -> bf16 hi/lo splits in one launch (grid.y = which weight)
// ---------------------------------------------------------------------------
__global__ void convw_all_kernel(const float* __restrict__ W0, const float* __restrict__ W1,
                                 const float* __restrict__ W2, const float* __restrict__ W3,
                                 const float* __restrict__ W4,
                                 __nv_bfloat16* __restrict__ H0, __nv_bfloat16* __restrict__ L0,
                                 __nv_bfloat16* __restrict__ H1, __nv_bfloat16* __restrict__ L1,
                                 __nv_bfloat16* __restrict__ H2, __nv_bfloat16* __restrict__ L2,
                                 __nv_bfloat16* __restrict__ H3, __nv_bfloat16* __restrict__ L3,
                                 __nv_bfloat16* __restrict__ H4, __nv_bfloat16* __restrict__ L4)
{
    int w = blockIdx.y;
    const float* W = (w == 0) ? W0 : (w == 1) ? W1 : (w == 2) ? W2 : (w == 3) ? W3 : W4;
    __nv_bfloat16* H = (w == 0) ? H0 : (w == 1) ? H1 : (w == 2) ? H2 : (w == 3) ? H3 : H4;
    __nv_bfloat16* L = (w == 0) ? L0 : (w == 1) ? L1 : (w == 2) ? L2 : (w == 3) ? L3 : L4;
    int i = blockIdx.x * 256 + threadIdx.x;
    float v = W[i];
    __nv_bfloat16 h = __float2bfloat16(v);
    H[i] = h;
    L[i] = __float2bfloat16(v - __bfloat162float(h));
}

// ---------------------------------------------------------------------------
// WKV6 scan with smem-staged inputs. One block per (b,h).
// Cooperative load: thread (warp=t_row, lane=chan) loads one element of each
// of r/k/d/v per 32-step tile (4 coalesced LDG, 32x fewer than before).
// Scan phase: warp = output dim i, lane = key dim j; inputs via LDS.
// ---------------------------------------------------------------------------
__global__ void __launch_bounds__(1024) wkv_kernel(
    const float* __restrict__ r, const float* __restrict__ k,
    const float* __restrict__ v, const float* __restrict__ d,
    const float* __restrict__ u, float* __restrict__ y)
{
    int bh = blockIdx.x;
    int b = bh / HH, h = bh % HH;
    int warp = threadIdx.x >> 5;
    int lane = threadIdx.x & 31;
    __shared__ float sr[32][32];
    __shared__ float sk[32][32];
    __shared__ float sd[32][32];
    __shared__ float sv[32][32];
    __shared__ float ys[32][33];

    float uj = u[h * HSZ + lane];
    float S = 0.f;
    size_t base = ((size_t)b * TT) * CC + h * HSZ;

    for (int t0 = 0; t0 < TT; t0 += 32) {
        // cooperative tile load: row = time step (warp), col = channel (lane)
        {
            size_t off = base + (size_t)(t0 + warp) * CC + lane;
            sr[warp][lane] = r[off];
            sk[warp][lane] = k[off];
            sd[warp][lane] = d[off];
            sv[warp][lane] = v[off];
        }
        __syncthreads();

        #pragma unroll 8
        for (int tt = 0; tt < 32; ++tt) {
            float rj = sr[tt][lane];
            float kj = sk[tt][lane];
            float dj = sd[tt][lane];
            float vi = sv[tt][warp];            // broadcast within warp
            float a  = kj * vi;
            float p  = rj * S + (rj * uj) * a;
            #pragma unroll
            for (int s = 16; s; s >>= 1)
                p += __shfl_xor_sync(0xffffffffu, p, s);
            S = fmaf(dj, S, a);
            if (lane == 0) ys[tt][warp] = p;
        }
        __syncthreads();
        {
            size_t off = base + (size_t)(t0 + warp) * CC;
            y[off + lane] = ys[warp][lane];
        }
        __syncthreads();
    }
}

// ---------------------------------------------------------------------------
// Per-head groupnorm * ln * gate -> bf16 hi/lo split for the Wo GEMM
// ---------------------------------------------------------------------------
__global__ void __launch_bounds__(256) gn_kernel(
    const float* __restrict__ y, const float* __restrict__ gate,
    const float* __restrict__ lnw, const float* __restrict__ lnb,
    __nv_bfloat16* __restrict__ zh, __nv_bfloat16* __restrict__ zl)
{
    int g = blockIdx.x * 8 + (threadIdx.x >> 5);
    int lane = threadIdx.x & 31;
    size_t idx = (size_t)g * 32 + lane;
    float v = y[idx];
    float s = v;
    #pragma unroll
    for (int o = 16; o; o >>= 1) s += __shfl_xor_sync(0xffffffffu, s, o);
    float mu = s * (1.f / 32.f);
    float dv = v - mu;
    float q = dv * dv;
    #pragma unroll
    for (int o = 16; o; o >>= 1) q += __shfl_xor_sync(0xffffffffu, q, o);
    float var = q * (1.f / 32.f);
    float yn = dv * rsqrtf(var + 1e-5f);
    int c = (int)(idx & (CC - 1));
    float z = (yn * lnw[c] + lnb[c]) * gate[idx];
    wsplit(z, zh, zl, idx);
}

// ---------------------------------------------------------------------------
extern "C" void kernel_launch(void* const* d_in, const int* in_sizes, int n_in,
                              void* d_out, int out_size) {
    const float* x      = (const float*)d_in[0];
    const float* tmaa_x = (const float*)d_in[1];
    const float* tmaa_w = (const float*)d_in[2];
    const float* tmaa_k = (const float*)d_in[3];
    const float* tmaa_v = (const float*)d_in[4];
    const float* tmaa_r = (const float*)d_in[5];
    const float* tmaa_g = (const float*)d_in[6];
    const float* w1     = (const float*)d_in[7];   // (C,160)
    const float* w2     = (const float*)d_in[8];   // (5,32,C)
    const float* tdecay = (const float*)d_in[9];   // (C,)
    const float* tdw1   = (const float*)d_in[10];  // (C,64)
    const float* tdw2   = (const float*)d_in[11];  // (64,C)
    const float* faaaa  = (const float*)d_in[12];  // (H,HS)
    const float* Wr     = (const float*)d_in[13];
    const float* Wk     = (const float*)d_in[14];
    const float* Wv     = (const float*)d_in[15];
    const float* Wg     = (const float*)d_in[16];
    const float* Wo     = (const float*)d_in[17];
    const float* lnw    = (const float*)d_in[18];
    const float* lnb    = (const float*)d_in[19];
    float* out = (float*)d_out;

    unsigned char* S;
    cudaGetSymbolAddress((void**)&S, g_scratch);
    float* mixb = (float*)(S + O_MIX);
    float* xw   = (float*)(S + O_XW);
    float* w64  = (float*)(S + O_W64);
    float* db   = (float*)(S + O_DB);
    float* rb   = (float*)(S + O_RB);
    float* kb   = (float*)(S + O_KB);
    float* vb   = (float*)(S + O_VB);
    float* gb   = (float*)(S + O_GB);
    float* yb   = (float*)(S + O_YB);
    __nv_bfloat16* kh = (__nv_bfloat16*)(S + O_KH);
    __nv_bfloat16* kl = (__nv_bfloat16*)(S + O_KL);
    __nv_bfloat16* vh = (__nv_bfloat16*)(S + O_VH);
    __nv_bfloat16* vl = (__nv_bfloat16*)(S + O_VL);
    __nv_bfloat16* rh = (__nv_bfloat16*)(S + O_RH);
    __nv_bfloat16* rl = (__nv_bfloat16*)(S + O_RL);
    __nv_bfloat16* gh = (__nv_bfloat16*)(S + O_GH);
    __nv_bfloat16* gl = (__nv_bfloat16*)(S + O_GL);
    __nv_bfloat16* zh = (__nv_bfloat16*)(S + O_ZH);
    __nv_bfloat16* zl = (__nv_bfloat16*)(S + O_ZL);
    __nv_bfloat16* wrh = (__nv_bfloat16*)(S + O_WRH);
    __nv_bfloat16* wrl = (__nv_bfloat16*)(S + O_WRL);
    __nv_bfloat16* wkh = (__nv_bfloat16*)(S + O_WKH);
    __nv_bfloat16* wkl = (__nv_bfloat16*)(S + O_WKL);
    __nv_bfloat16* wvh = (__nv_bfloat16*)(S + O_WVH);
    __nv_bfloat16* wvl = (__nv_bfloat16*)(S + O_WVL);
    __nv_bfloat16* wgh = (__nv_bfloat16*)(S + O_WGH);
    __nv_bfloat16* wgl = (__nv_bfloat16*)(S + O_WGL);
    __nv_bfloat16* woh = (__nv_bfloat16*)(S + O_WOH);
    __nv_bfloat16* wol = (__nv_bfloat16*)(S + O_WOL);

    cudaFuncSetAttribute(tgemm_kernel<true, 0>, cudaFuncAttributeMaxDynamicSharedMemorySize, TG_SMEM);
    cudaFuncSetAttribute(tgemm_kernel<false, 0>, cudaFuncAttributeMaxDynamicSharedMemorySize, TG_SMEM);

    // 0) weight splits, one launch
    convw_all_kernel<<<dim3(1024, 5), 256>>>(Wr, Wk, Wv, Wg, Wo,
                                             wrh, wrl, wkh, wkl, wvh, wvl,
                                             wgh, wgl, woh, wol);

    // 1) mix = tanh((x + (shift(x)-x)*maa_x) @ w1)   [BT,160], prep fused
    sgemm_kernel<false, 1, true><<<dim3(3, BT / 64), 256>>>(
        x, w1, mixb, nullptr, tmaa_x, BT, 160, CC);

    // 2) 5-way mix back-projection + token mixing (16 bt rows per block)
    mix_combine_kernel<<<BT / 16, 512>>>(x, mixb, w2, tmaa_w, tmaa_k, tmaa_v,
                                         tmaa_r, tmaa_g, xw, kh, kl, vh, vl,
                                         rh, rl, gh, gl);

    // 3) 4 projections in ONE batched tensor-core launch (z selects problem;
    //    z==3 (g) applies silu)
    {
        TGBatch bt_{};
        bt_.ah[0] = rh; bt_.al[0] = rl; bt_.bh[0] = wrh; bt_.bl[0] = wrl; bt_.c[0] = rb;
        bt_.ah[1] = kh; bt_.al[1] = kl; bt_.bh[1] = wkh; bt_.bl[1] = wkl; bt_.c[1] = kb;
        bt_.ah[2] = vh; bt_.al[2] = vl; bt_.bh[2] = wvh; bt_.bl[2] = wvl; bt_.c[2] = vb;
        bt_.ah[3] = gh; bt_.al[3] = gl; bt_.bh[3] = wgh; bt_.bl[3] = wgl; bt_.c[3] = gb;
        tgemm_kernel<true, 0><<<dim3(4, BT / 128, 4), 256, TG_SMEM>>>(
            bt_, nullptr, nullptr, nullptr, nullptr, nullptr);
    }

    // 4) decay MLP: w64 = tanh(xw @ tdw1); d = exp(-exp(tdecay + w64 @ tdw2))
    sgemm_kernel<false, 1, false><<<dim3(1, BT / 64), 256>>>(
        xw, tdw1, w64, nullptr, nullptr, BT, 64, CC);
    sgemm_kernel<false, 3, false><<<dim3(8, BT / 64), 256>>>(
        w64, tdw2, db, tdecay, nullptr, BT, CC, 64);

    // 5) WKV6 scan (smem-staged)
    wkv_kernel<<<BQ * HH, 1024>>>(rb, kb, vb, db, faaaa, yb);

    // 6) groupnorm * ln * gate -> z (bf16 split)
    gn_kernel<<<(BT * HH) / 8, 256>>>(yb, gb, lnw, lnb, zh, zl);

    // 7) out = z @ Wo^T (tensor cores)
    {
        TGBatch dummy{};
        tgemm_kernel<false, 0><<<dim3(4, BT / 128), 256, TG_SMEM>>>(
            dummy, zh, zl, woh, wol, out);
    }
}

// round 8
// speedup vs baseline: 2.1912x; 1.2372x over previous
#include <cuda_runtime.h>
#include <cuda_bf16.h>
#include <cstdint>

#define BQ 8
#define TT 2048
#define CC 512
#define HH 16
#define HSZ 32
#define BT (BQ*TT)            // 16384
#define UEL ((size_t)BT*CC)   // 8388608 elements per [B,T,C] buffer
#define NCH 16                // chunks per sequence
#define CHL 128               // chunk length (TT/NCH)
#define NCID (BQ*HH*NCH)      // 2048 total chunks

// ---------------------------------------------------------------------------
// Scratch (bytes). One big device array; no allocations anywhere.
// ---------------------------------------------------------------------------
#define SZ_F32   (UEL*4)
#define SZ_BF16  (UEL*2)
#define SZ_MIX   ((size_t)BT*160*4)
#define SZ_W64   ((size_t)BT*64*4)
#define SZ_WBF   ((size_t)CC*CC*2)
#define SZ_L     ((size_t)NCID*1024*4)
#define SZ_P     ((size_t)NCID*32*4)

#define O_MIX   ((size_t)0)
#define O_XW    (O_MIX + SZ_MIX)
#define O_W64   (O_XW + SZ_F32)
#define O_DB    (O_W64 + SZ_W64)
#define O_RB    (O_DB + SZ_F32)
#define O_KB    (O_RB + SZ_F32)
#define O_VB    (O_KB + SZ_F32)
#define O_GB    (O_VB + SZ_F32)
#define O_YB    (O_GB + SZ_F32)
#define O_AB    (O_YB + SZ_F32)
#define O_LB    (O_AB + SZ_F32)
#define O_PB    (O_LB + SZ_L)
#define O_S0    (O_PB + SZ_P)
#define O_KH    (O_S0 + SZ_L)
#define O_KL    (O_KH + SZ_BF16)
#define O_VH    (O_KL + SZ_BF16)
#define O_VL    (O_VH + SZ_BF16)
#define O_RH    (O_VL + SZ_BF16)
#define O_RL    (O_RH + SZ_BF16)
#define O_GH    (O_RL + SZ_BF16)
#define O_GL    (O_GH + SZ_BF16)
#define O_ZH    (O_GL + SZ_BF16)
#define O_ZL    (O_ZH + SZ_BF16)
#define O_WRH   (O_ZL + SZ_BF16)
#define O_WRL   (O_WRH + SZ_WBF)
#define O_WKH   (O_WRL + SZ_WBF)
#define O_WKL   (O_WKH + SZ_WBF)
#define O_WVH   (O_WKL + SZ_WBF)
#define O_WVL   (O_WVH + SZ_WBF)
#define O_WGH   (O_WVL + SZ_WBF)
#define O_WGL   (O_WGH + SZ_WBF)
#define O_WOH   (O_WGL + SZ_WBF)
#define O_WOL   (O_WOH + SZ_WBF)
#define SCRATCH_BYTES (O_WOL + SZ_WBF)

__device__ __align__(256) unsigned char g_scratch[SCRATCH_BYTES];

// ---------------------------------------------------------------------------
// mma.sync / cp.async helpers (valid on plain compute_103 / sm_80+)
// ---------------------------------------------------------------------------
__device__ __forceinline__ uint32_t smem_u32(const void* p) {
    uint32_t a;
    asm("{ .reg .u64 t; cvta.to.shared.u64 t, %1; cvt.u32.u64 %0, t; }"
        : "=r"(a) : "l"(p));
    return a;
}

#define LDSM4(r, a) \
    asm volatile("ldmatrix.sync.aligned.m8n8.x4.shared.b16 {%0,%1,%2,%3}, [%4];" \
        : "=r"((r)[0]), "=r"((r)[1]), "=r"((r)[2]), "=r"((r)[3]) : "r"(a))

#define MMA16816(d, a, b0, b1) \
    asm volatile("mma.sync.aligned.m16n8k16.row.col.f32.bf16.bf16.f32 " \
        "{%0,%1,%2,%3}, {%4,%5,%6,%7}, {%8,%9}, {%0,%1,%2,%3};" \
        : "+f"((d)[0]), "+f"((d)[1]), "+f"((d)[2]), "+f"((d)[3]) \
        : "r"((a)[0]), "r"((a)[1]), "r"((a)[2]), "r"((a)[3]), "r"(b0), "r"(b1))

#define CP_ASYNC16(dst, src) \
    asm volatile("cp.async.cg.shared.global [%0], [%1], 16;" :: "r"(dst), "l"(src))
#define CP_COMMIT() asm volatile("cp.async.commit_group;" ::: "memory")
#define CP_WAIT(n)  asm volatile("cp.async.wait_group %0;" :: "n"(n) : "memory")

// ---------------------------------------------------------------------------
// Pipelined tensor-core GEMM: C[M,512] = epi(A @ W^T), split bf16 (hi/lo),
// 3 terms: Ah*Bh + Ah*Bl + Al*Bh. Tile 128x128, K-chunk 32, cp.async 2-stage.
// Batched over blockIdx.z: 4 independent (A,B,C) problems in one launch.
// ---------------------------------------------------------------------------
#define TROWB 80
#define TTILE (128*TROWB)     // 10240
#define TSTAGE (4*TTILE)      // 40960
#define TG_SMEM (2*TSTAGE)    // 81920

struct TGBatch {
    const __nv_bfloat16 *ah[4], *al[4], *bh[4], *bl[4];
    float* c[4];
};

__device__ __forceinline__ void tg_stage_loads(
    uint32_t smb, int stage,
    const __nv_bfloat16* __restrict__ Ah, const __nv_bfloat16* __restrict__ Al,
    const __nv_bfloat16* __restrict__ Bh, const __nv_bfloat16* __restrict__ Bl,
    int bm, int bn, int k0, int tid)
{
    uint32_t sbase = smb + stage * TSTAGE;
    #pragma unroll
    for (int m = 0; m < 4; ++m) {
        const __nv_bfloat16* G = (m == 0) ? Ah : (m == 1) ? Al : (m == 2) ? Bh : Bl;
        int rbase = (m < 2) ? bm : bn;
        #pragma unroll
        for (int it = 0; it < 2; ++it) {
            int idx = it * 256 + tid;          // 0..511
            int row = idx >> 2, g = idx & 3;
            uint32_t d = sbase + m * TTILE + row * TROWB + g * 16;
            const void* src = G + (size_t)(rbase + row) * 512 + k0 + g * 8;
            CP_ASYNC16(d, src);
        }
    }
}

template<bool BATCH, int EPI>
__global__ void __launch_bounds__(256, 2)
tgemm_kernel(TGBatch bt_,
             const __nv_bfloat16* __restrict__ Ah_, const __nv_bfloat16* __restrict__ Al_,
             const __nv_bfloat16* __restrict__ Bh_, const __nv_bfloat16* __restrict__ Bl_,
             float* __restrict__ C_)
{
    extern __shared__ unsigned char sm[];
    uint32_t smb = smem_u32(sm);
    int tid = threadIdx.x;
    int wid = tid >> 5, lane = tid & 31;
    int bm = blockIdx.y * 128, bn = blockIdx.x * 128;
    int wm = (wid & 3) * 32, wn = (wid >> 2) * 64;

    int z = BATCH ? blockIdx.z : 0;
    const __nv_bfloat16* Ah = BATCH ? bt_.ah[z] : Ah_;
    const __nv_bfloat16* Al = BATCH ? bt_.al[z] : Al_;
    const __nv_bfloat16* Bh = BATCH ? bt_.bh[z] : Bh_;
    const __nv_bfloat16* Bl = BATCH ? bt_.bl[z] : Bl_;
    float* C = BATCH ? bt_.c[z] : C_;
    bool do_silu = BATCH ? (z == 3) : (EPI == 2);

    float acc[2][8][4];
    #pragma unroll
    for (int i = 0; i < 2; ++i)
        #pragma unroll
        for (int j = 0; j < 8; ++j)
            #pragma unroll
            for (int q = 0; q < 4; ++q) acc[i][j][q] = 0.f;

    int mat = lane >> 3, r8 = lane & 7;
    int lrow = (mat & 1) * 8 + r8;
    int lkb  = (mat >> 1) * 16;

    tg_stage_loads(smb, 0, Ah, Al, Bh, Bl, bm, bn, 0, tid);
    CP_COMMIT();

    for (int ch = 0; ch < 16; ++ch) {
        if (ch + 1 < 16) {
            tg_stage_loads(smb, (ch + 1) & 1, Ah, Al, Bh, Bl, bm, bn, (ch + 1) * 32, tid);
            CP_COMMIT();
            CP_WAIT(1);
        } else {
            CP_WAIT(0);
        }
        __syncthreads();

        uint32_t sbase = smb + (ch & 1) * TSTAGE;
        #pragma unroll
        for (int ks = 0; ks < 2; ++ks) {
            uint32_t ah[2][4], al[2][4];
            #pragma unroll
            for (int mt = 0; mt < 2; ++mt) {
                uint32_t ra = sbase + (wm + mt * 16 + lrow) * TROWB + ks * 32 + lkb;
                LDSM4(ah[mt], ra);
                LDSM4(al[mt], ra + TTILE);
            }
            #pragma unroll
            for (int nt = 0; nt < 4; ++nt) {
                uint32_t rb = sbase + 2 * TTILE + (wn + nt * 16 + lrow) * TROWB + ks * 32 + lkb;
                uint32_t bh4[4], bl4[4];
                LDSM4(bh4, rb);
                LDSM4(bl4, rb + TTILE);
                #pragma unroll
                for (int mt = 0; mt < 2; ++mt) {
                    MMA16816(acc[mt][nt*2+0], ah[mt], bh4[0], bh4[2]);
                    MMA16816(acc[mt][nt*2+1], ah[mt], bh4[1], bh4[3]);
                    MMA16816(acc[mt][nt*2+0], ah[mt], bl4[0], bl4[2]);
                    MMA16816(acc[mt][nt*2+1], ah[mt], bl4[1], bl4[3]);
                    MMA16816(acc[mt][nt*2+0], al[mt], bh4[0], bh4[2]);
                    MMA16816(acc[mt][nt*2+1], al[mt], bh4[1], bh4[3]);
                }
            }
        }
        __syncthreads();
    }

    int r0 = lane >> 2, c0 = (lane & 3) * 2;
    #pragma unroll
    for (int mt = 0; mt < 2; ++mt) {
        #pragma unroll
        for (int nt = 0; nt < 4; ++nt) {
            #pragma unroll
            for (int s = 0; s < 2; ++s) {
                float* a4 = acc[mt][nt*2+s];
                int col = bn + wn + nt * 16 + s * 8 + c0;
                int row = bm + wm + mt * 16 + r0;
                float v0 = a4[0], v1 = a4[1], v2 = a4[2], v3 = a4[3];
                if (do_silu) {
                    v0 = v0 / (1.f + __expf(-v0));
                    v1 = v1 / (1.f + __expf(-v1));
                    v2 = v2 / (1.f + __expf(-v2));
                    v3 = v3 / (1.f + __expf(-v3));
                }
                *reinterpret_cast<float2*>(C + (size_t)row * 512 + col)       = make_float2(v0, v1);
                *reinterpret_cast<float2*>(C + (size_t)(row + 8) * 512 + col) = make_float2(v2, v3);
            }
        }
    }
}

// ---------------------------------------------------------------------------
// SIMT SGEMM. MIXA: A element = x + (xshift - x) * tmx computed on the fly.
// EPI: 0 none, 1 tanh, 3 exp(-exp(bias+v)).
// ---------------------------------------------------------------------------
template<bool BT_MAJOR, int EPI, bool MIXA>
__global__ void __launch_bounds__(256) sgemm_kernel(
    const float* __restrict__ A, const float* __restrict__ Bm,
    float* __restrict__ Cout, const float* __restrict__ bias,
    const float* __restrict__ tmx,
    int M, int N, int K)
{
    __shared__ float As[16][65];
    __shared__ float Bs[16][65];
    int tid = threadIdx.x;
    int bm = blockIdx.y * 64;
    int bn = blockIdx.x * 64;
    int tx = tid & 15, ty = tid >> 4;
    float acc[4][4] = {};
    int arow = tid >> 2, aseg = tid & 3;

    for (int k0 = 0; k0 < K; k0 += 16) {
        int grow = bm + arow;
        const float* ap = A + (size_t)grow * K + k0 + aseg * 4;
        float4 a4 = *reinterpret_cast<const float4*>(ap);
        if (MIXA) {
            float4 xp = make_float4(0.f, 0.f, 0.f, 0.f);
            if (grow & (TT - 1)) xp = *reinterpret_cast<const float4*>(ap - K);
            float4 tm = *reinterpret_cast<const float4*>(tmx + k0 + aseg * 4);
            a4.x += (xp.x - a4.x) * tm.x;
            a4.y += (xp.y - a4.y) * tm.y;
            a4.z += (xp.z - a4.z) * tm.z;
            a4.w += (xp.w - a4.w) * tm.w;
        }
        As[aseg*4+0][arow] = a4.x; As[aseg*4+1][arow] = a4.y;
        As[aseg*4+2][arow] = a4.z; As[aseg*4+3][arow] = a4.w;

        if (BT_MAJOR) {
            int n = tid >> 2, seg = tid & 3;
            float4 b4 = make_float4(0.f, 0.f, 0.f, 0.f);
            if (bn + n < N)
                b4 = *reinterpret_cast<const float4*>(
                    Bm + (size_t)(bn + n) * K + k0 + seg * 4);
            Bs[seg*4+0][n] = b4.x; Bs[seg*4+1][n] = b4.y;
            Bs[seg*4+2][n] = b4.z; Bs[seg*4+3][n] = b4.w;
        } else {
            int kk = tid >> 4, nb = (tid & 15) * 4;
            float4 b4 = make_float4(0.f, 0.f, 0.f, 0.f);
            if (bn + nb < N)
                b4 = *reinterpret_cast<const float4*>(
                    Bm + (size_t)(k0 + kk) * N + bn + nb);
            Bs[kk][nb+0] = b4.x; Bs[kk][nb+1] = b4.y;
            Bs[kk][nb+2] = b4.z; Bs[kk][nb+3] = b4.w;
        }
        __syncthreads();

        #pragma unroll
        for (int kk = 0; kk < 16; ++kk) {
            float ar[4], br[4];
            #pragma unroll
            for (int q = 0; q < 4; ++q) ar[q] = As[kk][ty*4 + q];
            #pragma unroll
            for (int p = 0; p < 4; ++p) br[p] = Bs[kk][tx*4 + p];
            #pragma unroll
            for (int q = 0; q < 4; ++q)
                #pragma unroll
                for (int p = 0; p < 4; ++p)
                    acc[q][p] = fmaf(ar[q], br[p], acc[q][p]);
        }
        __syncthreads();
    }

    #pragma unroll
    for (int q = 0; q < 4; ++q) {
        int row = bm + ty*4 + q;
        #pragma unroll
        for (int p = 0; p < 4; ++p) {
            int col = bn + tx*4 + p;
            if (col < N) {
                float v = acc[q][p];
                if (EPI == 1) v = tanhf(v);
                else if (EPI == 3) v = __expf(-__expf(bias[col] + v));
                Cout[(size_t)row * N + col] = v;
            }
        }
    }
}

// ---------------------------------------------------------------------------
// split helper
// ---------------------------------------------------------------------------
__device__ __forceinline__ void wsplit(float v, __nv_bfloat16* hi, __nv_bfloat16* lo, size_t i) {
    __nv_bfloat16 h = __float2bfloat16(v);
    hi[i] = h;
    lo[i] = __float2bfloat16(v - __bfloat162float(h));
}

// ---------------------------------------------------------------------------
// mix back-projection + 5-way token mix. Block = 16 bt rows x 512 c.
// ---------------------------------------------------------------------------
__global__ void __launch_bounds__(512) mix_combine_kernel(
    const float* __restrict__ x, const float* __restrict__ mix,
    const float* __restrict__ W2,
    const float* __restrict__ maaw, const float* __restrict__ maak,
    const float* __restrict__ maav, const float* __restrict__ maar,
    const float* __restrict__ maag,
    float* __restrict__ xw,
    __nv_bfloat16* __restrict__ kh, __nv_bfloat16* __restrict__ kl,
    __nv_bfloat16* __restrict__ vh, __nv_bfloat16* __restrict__ vl,
    __nv_bfloat16* __restrict__ rh, __nv_bfloat16* __restrict__ rl,
    __nv_bfloat16* __restrict__ gh, __nv_bfloat16* __restrict__ gl)
{
    __shared__ float s_mix[16][160];
    __shared__ float s_x[16][512];
    __shared__ float s_xp0[512];
    int bt0 = blockIdx.x * 16;
    int c = threadIdx.x;

    for (int i = threadIdx.x; i < 16 * 160; i += 512)
        s_mix[i / 160][i % 160] = mix[(size_t)bt0 * 160 + i];
    #pragma unroll
    for (int row = 0; row < 16; ++row)
        s_x[row][c] = x[(size_t)(bt0 + row) * 512 + c];
    s_xp0[c] = (bt0 & (TT - 1)) ? x[(size_t)(bt0 - 1) * 512 + c] : 0.f;
    __syncthreads();

    float maa[5];
    maa[0] = maaw[c]; maa[1] = maak[c]; maa[2] = maav[c];
    maa[3] = maar[c]; maa[4] = maag[c];

    #pragma unroll
    for (int f = 0; f < 5; ++f) {
        float acc[16];
        #pragma unroll
        for (int row = 0; row < 16; ++row) acc[row] = 0.f;
        #pragma unroll 8
        for (int dd = 0; dd < 32; ++dd) {
            float w = W2[(size_t)(f * 32 + dd) * 512 + c];
            #pragma unroll
            for (int row = 0; row < 16; ++row)
                acc[row] = fmaf(s_mix[row][f * 32 + dd], w, acc[row]);
        }
        #pragma unroll
        for (int row = 0; row < 16; ++row) {
            size_t gi = (size_t)(bt0 + row) * 512 + c;
            float xc = s_x[row][c];
            float xp = (row > 0) ? s_x[row - 1][c] : s_xp0[c];
            float v = fmaf(xp - xc, maa[f] + acc[row], xc);
            if (f == 0) xw[gi] = v;
            else if (f == 1) wsplit(v, kh, kl, gi);
            else if (f == 2) wsplit(v, vh, vl, gi);
            else if (f == 3) wsplit(v, rh, rl, gi);
            else             wsplit(v, gh, gl, gi);
        }
    }
}

// ---------------------------------------------------------------------------
// All weight fp32 -> bf16 hi/lo splits in one launch (grid.y = which weight)
// ---------------------------------------------------------------------------
__global__ void convw_all_kernel(const float* __restrict__ W0, const float* __restrict__ W1,
                                 const float* __restrict__ W2, const float* __restrict__ W3,
                                 const float* __restrict__ W4,
                                 __nv_bfloat16* __restrict__ H0, __nv_bfloat16* __restrict__ L0,
                                 __nv_bfloat16* __restrict__ H1, __nv_bfloat16* __restrict__ L1,
                                 __nv_bfloat16* __restrict__ H2, __nv_bfloat16* __restrict__ L2,
                                 __nv_bfloat16* __restrict__ H3, __nv_bfloat16* __restrict__ L3,
                                 __nv_bfloat16* __restrict__ H4, __nv_bfloat16* __restrict__ L4)
{
    int w = blockIdx.y;
    const float* W = (w == 0) ? W0 : (w == 1) ? W1 : (w == 2) ? W2 : (w == 3) ? W3 : W4;
    __nv_bfloat16* H = (w == 0) ? H0 : (w == 1) ? H1 : (w == 2) ? H2 : (w == 3) ? H3 : H4;
    __nv_bfloat16* L = (w == 0) ? L0 : (w == 1) ? L1 : (w == 2) ? L2 : (w == 3) ? L3 : L4;
    int i = blockIdx.x * 256 + threadIdx.x;
    float v = W[i];
    __nv_bfloat16 h = __float2bfloat16(v);
    H[i] = h;
    L[i] = __float2bfloat16(v - __bfloat162float(h));
}

// ---------------------------------------------------------------------------
// Chunked WKV, kernel 1: per-chunk local scan.
// One warp per (bh, chunk). Lane = output channel i; S[j] (j=0..31) held in
// registers per lane. r/k/d broadcast through a per-warp smem row.
// Emits: y_local, A[t][j] = r_j * prod_{s<t} d_j, chunk-final L and P.
// ---------------------------------------------------------------------------
__global__ void __launch_bounds__(256) wkv_chunk_kernel(
    const float* __restrict__ r, const float* __restrict__ k,
    const float* __restrict__ v, const float* __restrict__ d,
    const float* __restrict__ u,
    float* __restrict__ ylocal, float* __restrict__ Aout,
    float* __restrict__ Lout, float* __restrict__ Pout)
{
    int wid = threadIdx.x >> 5, lane = threadIdx.x & 31;
    int cid = blockIdx.x * 8 + wid;        // 0..2047
    int bh = cid >> 4, ch = cid & (NCH - 1);
    int b = bh >> 4, h = bh & (HH - 1);
    size_t base = ((size_t)b * TT + (size_t)ch * CHL) * CC + h * HSZ + lane;

    __shared__ float srkd[8][3][32];

    float S[32];
    #pragma unroll
    for (int j = 0; j < 32; ++j) S[j] = 0.f;
    float P = 1.f;
    float ul = u[h * HSZ + lane];

    size_t off = base;
    float rl = r[off], kl = k[off], dl = d[off], vl = v[off];

    for (int t = 0; t < CHL; ++t) {
        // prefetch next step (clamped; last-iter values unused)
        int tn = (t + 1 < CHL) ? (t + 1) : t;
        size_t offn = base + (size_t)tn * CC;
        float rn = r[offn], kn = k[offn], dn = d[offn], vn = v[offn];

        Aout[off] = rl * P;     // uses P = prod of d over steps < t
        P *= dl;

        srkd[wid][0][lane] = rl;
        srkd[wid][1][lane] = kl;
        srkd[wid][2][lane] = dl;
        __syncwarp();

        // c = sum_j r_j u_j k_j (same for all i)
        float cp = rl * ul * kl;
        #pragma unroll
        for (int o = 16; o; o >>= 1) cp += __shfl_xor_sync(0xffffffffu, cp, o);

        float y0 = 0.f, y1 = 0.f, y2 = 0.f, y3 = 0.f;
        #pragma unroll
        for (int j4 = 0; j4 < 8; ++j4) {
            float4 r4 = *reinterpret_cast<const float4*>(&srkd[wid][0][j4 * 4]);
            float4 k4 = *reinterpret_cast<const float4*>(&srkd[wid][1][j4 * 4]);
            float4 d4 = *reinterpret_cast<const float4*>(&srkd[wid][2][j4 * 4]);
            y0 = fmaf(r4.x, S[j4*4+0], y0); S[j4*4+0] = fmaf(d4.x, S[j4*4+0], k4.x * vl);
            y1 = fmaf(r4.y, S[j4*4+1], y1); S[j4*4+1] = fmaf(d4.y, S[j4*4+1], k4.y * vl);
            y2 = fmaf(r4.z, S[j4*4+2], y2); S[j4*4+2] = fmaf(d4.z, S[j4*4+2], k4.z * vl);
            y3 = fmaf(r4.w, S[j4*4+3], y3); S[j4*4+3] = fmaf(d4.w, S[j4*4+3], k4.w * vl);
        }
        ylocal[off] = (y0 + y1) + (y2 + y3) + cp * vl;
        __syncwarp();

        rl = rn; kl = kn; dl = dn; vl = vn;
        off += CC;
    }

    #pragma unroll
    for (int j = 0; j < 32; ++j)
        Lout[(size_t)cid * 1024 + j * 32 + lane] = S[j];
    Pout[(size_t)cid * 32 + lane] = P;
}

// ---------------------------------------------------------------------------
// Chunked WKV, kernel 2: scan chunk states across the sequence.
// S0[c] = carried-in state at start of chunk c. S0[0] = 0.
// ---------------------------------------------------------------------------
__global__ void __launch_bounds__(1024) wkv_state_scan_kernel(
    const float* __restrict__ L, const float* __restrict__ P,
    float* __restrict__ S0out)
{
    int bh = blockIdx.x;
    int e = threadIdx.x;         // j*32 + i
    int j = e >> 5;
    float s = 0.f;
    #pragma unroll
    for (int c = 0; c < NCH; ++c) {
        size_t cid = (size_t)bh * NCH + c;
        S0out[cid * 1024 + e] = s;
        s = P[cid * 32 + j] * s + L[cid * 1024 + e];
    }
}

// ---------------------------------------------------------------------------
// Chunked WKV, kernel 3: y += A . S0 (per-chunk correction).
// Block = one (bh, chunk); S0 cached in smem; 8 warps x 16 timesteps.
// ---------------------------------------------------------------------------
__global__ void __launch_bounds__(256) wkv_apply_kernel(
    const float* __restrict__ A, const float* __restrict__ S0,
    float* __restrict__ y)
{
    int cid = blockIdx.x;
    int ch = cid & (NCH - 1);
    if (ch == 0) return;                   // S0 is zero for first chunk
    int bh = cid >> 4;
    int b = bh >> 4, h = bh & (HH - 1);
    int wid = threadIdx.x >> 5, lane = threadIdx.x & 31;

    __shared__ float s0[1024];
    __shared__ float sa[8][32];
    for (int i = threadIdx.x; i < 1024; i += 256)
        s0[i] = S0[(size_t)cid * 1024 + i];
    __syncthreads();

    size_t base = ((size_t)b * TT + (size_t)ch * CHL) * CC + h * HSZ + lane;
    for (int tt = 0; tt < 16; ++tt) {
        int t = wid * 16 + tt;
        size_t off = base + (size_t)t * CC;
        sa[wid][lane] = A[off];
        __syncwarp();
        float acc = 0.f;
        #pragma unroll
        for (int j4 = 0; j4 < 8; ++j4) {
            float4 a4 = *reinterpret_cast<const float4*>(&sa[wid][j4 * 4]);
            acc = fmaf(a4.x, s0[(j4*4+0)*32 + lane], acc);
            acc = fmaf(a4.y, s0[(j4*4+1)*32 + lane], acc);
            acc = fmaf(a4.z, s0[(j4*4+2)*32 + lane], acc);
            acc = fmaf(a4.w, s0[(j4*4+3)*32 + lane], acc);
        }
        y[off] += acc;
        __syncwarp();
    }
}

// ---------------------------------------------------------------------------
// Per-head groupnorm * ln * gate -> bf16 hi/lo split for the Wo GEMM
// ---------------------------------------------------------------------------
__global__ void __launch_bounds__(256) gn_kernel(
    const float* __restrict__ y, const float* __restrict__ gate,
    const float* __restrict__ lnw, const float* __restrict__ lnb,
    __nv_bfloat16* __restrict__ zh, __nv_bfloat16* __restrict__ zl)
{
    int g = blockIdx.x * 8 + (threadIdx.x >> 5);
    int lane = threadIdx.x & 31;
    size_t idx = (size_t)g * 32 + lane;
    float v = y[idx];
    float s = v;
    #pragma unroll
    for (int o = 16; o; o >>= 1) s += __shfl_xor_sync(0xffffffffu, s, o);
    float mu = s * (1.f / 32.f);
    float dv = v - mu;
    float q = dv * dv;
    #pragma unroll
    for (int o = 16; o; o >>= 1) q += __shfl_xor_sync(0xffffffffu, q, o);
    float var = q * (1.f / 32.f);
    float yn = dv * rsqrtf(var + 1e-5f);
    int c = (int)(idx & (CC - 1));
    float z = (yn * lnw[c] + lnb[c]) * gate[idx];
    wsplit(z, zh, zl, idx);
}

// ---------------------------------------------------------------------------
extern "C" void kernel_launch(void* const* d_in, const int* in_sizes, int n_in,
                              void* d_out, int out_size) {
    const float* x      = (const float*)d_in[0];
    const float* tmaa_x = (const float*)d_in[1];
    const float* tmaa_w = (const float*)d_in[2];
    const float* tmaa_k = (const float*)d_in[3];
    const float* tmaa_v = (const float*)d_in[4];
    const float* tmaa_r = (const float*)d_in[5];
    const float* tmaa_g = (const float*)d_in[6];
    const float* w1     = (const float*)d_in[7];   // (C,160)
    const float* w2     = (const float*)d_in[8];   // (5,32,C)
    const float* tdecay = (const float*)d_in[9];   // (C,)
    const float* tdw1   = (const float*)d_in[10];  // (C,64)
    const float* tdw2   = (const float*)d_in[11];  // (64,C)
    const float* faaaa  = (const float*)d_in[12];  // (H,HS)
    const float* Wr     = (const float*)d_in[13];
    const float* Wk     = (const float*)d_in[14];
    const float* Wv     = (const float*)d_in[15];
    const float* Wg     = (const float*)d_in[16];
    const float* Wo     = (const float*)d_in[17];
    const float* lnw    = (const float*)d_in[18];
    const float* lnb    = (const float*)d_in[19];
    float* out = (float*)d_out;

    unsigned char* S;
    cudaGetSymbolAddress((void**)&S, g_scratch);
    float* mixb = (float*)(S + O_MIX);
    float* xw   = (float*)(S + O_XW);
    float* w64  = (float*)(S + O_W64);
    float* db   = (float*)(S + O_DB);
    float* rb   = (float*)(S + O_RB);
    float* kb   = (float*)(S + O_KB);
    float* vb   = (float*)(S + O_VB);
    float* gb   = (float*)(S + O_GB);
    float* yb   = (float*)(S + O_YB);
    float* ab   = (float*)(S + O_AB);
    float* lb   = (float*)(S + O_LB);
    float* pb   = (float*)(S + O_PB);
    float* s0b  = (float*)(S + O_S0);
    __nv_bfloat16* kh = (__nv_bfloat16*)(S + O_KH);
    __nv_bfloat16* kl = (__nv_bfloat16*)(S + O_KL);
    __nv_bfloat16* vh = (__nv_bfloat16*)(S + O_VH);
    __nv_bfloat16* vl = (__nv_bfloat16*)(S + O_VL);
    __nv_bfloat16* rh = (__nv_bfloat16*)(S + O_RH);
    __nv_bfloat16* rl = (__nv_bfloat16*)(S + O_RL);
    __nv_bfloat16* gh = (__nv_bfloat16*)(S + O_GH);
    __nv_bfloat16* gl = (__nv_bfloat16*)(S + O_GL);
    __nv_bfloat16* zh = (__nv_bfloat16*)(S + O_ZH);
    __nv_bfloat16* zl = (__nv_bfloat16*)(S + O_ZL);
    __nv_bfloat16* wrh = (__nv_bfloat16*)(S + O_WRH);
    __nv_bfloat16* wrl = (__nv_bfloat16*)(S + O_WRL);
    __nv_bfloat16* wkh = (__nv_bfloat16*)(S + O_WKH);
    __nv_bfloat16* wkl = (__nv_bfloat16*)(S + O_WKL);
    __nv_bfloat16* wvh = (__nv_bfloat16*)(S + O_WVH);
    __nv_bfloat16* wvl = (__nv_bfloat16*)(S + O_WVL);
    __nv_bfloat16* wgh = (__nv_bfloat16*)(S + O_WGH);
    __nv_bfloat16* wgl = (__nv_bfloat16*)(S + O_WGL);
    __nv_bfloat16* woh = (__nv_bfloat16*)(S + O_WOH);
    __nv_bfloat16* wol = (__nv_bfloat16*)(S + O_WOL);

    cudaFuncSetAttribute(tgemm_kernel<true, 0>, cudaFuncAttributeMaxDynamicSharedMemorySize, TG_SMEM);
    cudaFuncSetAttribute(tgemm_kernel<false, 0>, cudaFuncAttributeMaxDynamicSharedMemorySize, TG_SMEM);

    // 0) weight splits, one launch
    convw_all_kernel<<<dim3(1024, 5), 256>>>(Wr, Wk, Wv, Wg, Wo,
                                             wrh, wrl, wkh, wkl, wvh, wvl,
                                             wgh, wgl, woh, wol);

    // 1) mix = tanh((x + (shift(x)-x)*maa_x) @ w1)   [BT,160], prep fused
    sgemm_kernel<false, 1, true><<<dim3(3, BT / 64), 256>>>(
        x, w1, mixb, nullptr, tmaa_x, BT, 160, CC);

    // 2) 5-way mix back-projection + token mixing (16 bt rows per block)
    mix_combine_kernel<<<BT / 16, 512>>>(x, mixb, w2, tmaa_w, tmaa_k, tmaa_v,
                                         tmaa_r, tmaa_g, xw, kh, kl, vh, vl,
                                         rh, rl, gh, gl);

    // 3) 4 projections in ONE batched tensor-core launch (z==3 (g) = silu)
    {
        TGBatch bt_{};
        bt_.ah[0] = rh; bt_.al[0] = rl; bt_.bh[0] = wrh; bt_.bl[0] = wrl; bt_.c[0] = rb;
        bt_.ah[1] = kh; bt_.al[1] = kl; bt_.bh[1] = wkh; bt_.bl[1] = wkl; bt_.c[1] = kb;
        bt_.ah[2] = vh; bt_.al[2] = vl; bt_.bh[2] = wvh; bt_.bl[2] = wvl; bt_.c[2] = vb;
        bt_.ah[3] = gh; bt_.al[3] = gl; bt_.bh[3] = wgh; bt_.bl[3] = wgl; bt_.c[3] = gb;
        tgemm_kernel<true, 0><<<dim3(4, BT / 128, 4), 256, TG_SMEM>>>(
            bt_, nullptr, nullptr, nullptr, nullptr, nullptr);
    }

    // 4) decay MLP: w64 = tanh(xw @ tdw1); d = exp(-exp(tdecay + w64 @ tdw2))
    sgemm_kernel<false, 1, false><<<dim3(1, BT / 64), 256>>>(
        xw, tdw1, w64, nullptr, nullptr, BT, 64, CC);
    sgemm_kernel<false, 3, false><<<dim3(8, BT / 64), 256>>>(
        w64, tdw2, db, tdecay, nullptr, BT, CC, 64);

    // 5) WKV6 chunked scan: local scans -> state scan -> correction
    wkv_chunk_kernel<<<NCID / 8, 256>>>(rb, kb, vb, db, faaaa, yb, ab, lb, pb);
    wkv_state_scan_kernel<<<BQ * HH, 1024>>>(lb, pb, s0b);
    wkv_apply_kernel<<<NCID, 256>>>(ab, s0b, yb);

    // 6) groupnorm * ln * gate -> z (bf16 split)
    gn_kernel<<<(BT * HH) / 8, 256>>>(yb, gb, lnw, lnb, zh, zl);

    // 7) out = z @ Wo^T (tensor cores)
    {
        TGBatch dummy{};
        tgemm_kernel<false, 0><<<dim3(4, BT / 128), 256, TG_SMEM>>>(
            dummy, zh, zl, woh, wol, out);
    }
}

// round 9
// speedup vs baseline: 2.2143x; 1.0105x over previous
#include <cuda_runtime.h>
#include <cuda_bf16.h>
#include <cstdint>

#define BQ 8
#define TT 2048
#define CC 512
#define HH 16
#define HSZ 32
#define BT (BQ*TT)            // 16384
#define UEL ((size_t)BT*CC)   // 8388608 elements per [B,T,C] buffer
#define NCH 16                // chunks per sequence
#define CHL 128               // chunk length (TT/NCH)
#define NCID (BQ*HH*NCH)      // 2048 total chunks

// ---------------------------------------------------------------------------
// Scratch (bytes). One big device array; no allocations anywhere.
// ---------------------------------------------------------------------------
#define SZ_F32   (UEL*4)
#define SZ_BF16  (UEL*2)
#define SZ_MIX   ((size_t)BT*160*4)
#define SZ_W64   ((size_t)BT*64*4)
#define SZ_WBF   ((size_t)CC*CC*2)
#define SZ_L     ((size_t)NCID*1024*4)
#define SZ_P     ((size_t)NCID*32*4)

#define O_MIX   ((size_t)0)
#define O_XW    (O_MIX + SZ_MIX)
#define O_W64   (O_XW + SZ_F32)
#define O_DB    (O_W64 + SZ_W64)
#define O_RB    (O_DB + SZ_F32)
#define O_KB    (O_RB + SZ_F32)
#define O_VB    (O_KB + SZ_F32)
#define O_GB    (O_VB + SZ_F32)
#define O_YB    (O_GB + SZ_F32)
#define O_AB    (O_YB + SZ_F32)
#define O_LB    (O_AB + SZ_F32)
#define O_PB    (O_LB + SZ_L)
#define O_S0    (O_PB + SZ_P)
#define O_KH    (O_S0 + SZ_L)
#define O_KL    (O_KH + SZ_BF16)
#define O_VH    (O_KL + SZ_BF16)
#define O_VL    (O_VH + SZ_BF16)
#define O_RH    (O_VL + SZ_BF16)
#define O_RL    (O_RH + SZ_BF16)
#define O_GH    (O_RL + SZ_BF16)
#define O_GL    (O_GH + SZ_BF16)
#define O_ZH    (O_GL + SZ_BF16)
#define O_ZL    (O_ZH + SZ_BF16)
#define O_WRH   (O_ZL + SZ_BF16)
#define O_WRL   (O_WRH + SZ_WBF)
#define O_WKH   (O_WRL + SZ_WBF)
#define O_WKL   (O_WKH + SZ_WBF)
#define O_WVH   (O_WKL + SZ_WBF)
#define O_WVL   (O_WVH + SZ_WBF)
#define O_WGH   (O_WVL + SZ_WBF)
#define O_WGL   (O_WGH + SZ_WBF)
#define O_WOH   (O_WGL + SZ_WBF)
#define O_WOL   (O_WOH + SZ_WBF)
#define SCRATCH_BYTES (O_WOL + SZ_WBF)

__device__ __align__(256) unsigned char g_scratch[SCRATCH_BYTES];

// ---------------------------------------------------------------------------
// mma.sync / cp.async helpers (valid on plain compute_103 / sm_80+)
// ---------------------------------------------------------------------------
__device__ __forceinline__ uint32_t smem_u32(const void* p) {
    uint32_t a;
    asm("{ .reg .u64 t; cvta.to.shared.u64 t, %1; cvt.u32.u64 %0, t; }"
        : "=r"(a) : "l"(p));
    return a;
}

#define LDSM4(r, a) \
    asm volatile("ldmatrix.sync.aligned.m8n8.x4.shared.b16 {%0,%1,%2,%3}, [%4];" \
        : "=r"((r)[0]), "=r"((r)[1]), "=r"((r)[2]), "=r"((r)[3]) : "r"(a))

#define MMA16816(d, a, b0, b1) \
    asm volatile("mma.sync.aligned.m16n8k16.row.col.f32.bf16.bf16.f32 " \
        "{%0,%1,%2,%3}, {%4,%5,%6,%7}, {%8,%9}, {%0,%1,%2,%3};" \
        : "+f"((d)[0]), "+f"((d)[1]), "+f"((d)[2]), "+f"((d)[3]) \
        : "r"((a)[0]), "r"((a)[1]), "r"((a)[2]), "r"((a)[3]), "r"(b0), "r"(b1))

#define CP_ASYNC16(dst, src) \
    asm volatile("cp.async.cg.shared.global [%0], [%1], 16;" :: "r"(dst), "l"(src))
#define CP_COMMIT() asm volatile("cp.async.commit_group;" ::: "memory")
#define CP_WAIT(n)  asm volatile("cp.async.wait_group %0;" :: "n"(n) : "memory")

// ---------------------------------------------------------------------------
// Pipelined tensor-core GEMM: C[M,512] = epi(A @ W^T), split bf16 (hi/lo),
// 3 terms: Ah*Bh + Ah*Bl + Al*Bh. Tile 128x128, K-chunk 32, cp.async 2-stage.
// Strength-reduced addressing: per-thread global pointers advance by constant
// per chunk; smem dsts computed once; ldmatrix bases hoisted.
// Batched over blockIdx.z: 4 independent (A,B,C) problems in one launch.
// ---------------------------------------------------------------------------
#define TROWB 80
#define TTILE (128*TROWB)     // 10240
#define TSTAGE (4*TTILE)      // 40960
#define TG_SMEM (2*TSTAGE)    // 81920
#define ROWSKIP (64*1024)     // 64 rows * 512 cols * 2B, global second-block skip
#define DSTSKIP (64*TROWB)    // smem second-block skip

struct TGBatch {
    const __nv_bfloat16 *ah[4], *al[4], *bh[4], *bl[4];
    float* c[4];
};

template<bool BATCH, int EPI>
__global__ void __launch_bounds__(256, 2)
tgemm_kernel(TGBatch bt_,
             const __nv_bfloat16* __restrict__ Ah_, const __nv_bfloat16* __restrict__ Al_,
             const __nv_bfloat16* __restrict__ Bh_, const __nv_bfloat16* __restrict__ Bl_,
             float* __restrict__ C_)
{
    extern __shared__ unsigned char sm[];
    uint32_t smb = smem_u32(sm);
    int tid = threadIdx.x;
    int wid = tid >> 5, lane = tid & 31;
    int bm = blockIdx.y * 128, bn = blockIdx.x * 128;
    int wm = (wid & 3) * 32, wn = (wid >> 2) * 64;

    int z = BATCH ? blockIdx.z : 0;
    const __nv_bfloat16* Ah = BATCH ? bt_.ah[z] : Ah_;
    const __nv_bfloat16* Al = BATCH ? bt_.al[z] : Al_;
    const __nv_bfloat16* Bh = BATCH ? bt_.bh[z] : Bh_;
    const __nv_bfloat16* Bl = BATCH ? bt_.bl[z] : Bl_;
    float* C = BATCH ? bt_.c[z] : C_;
    bool do_silu = BATCH ? (z == 3) : (EPI == 2);

    // -- load-path setup (once) --
    int rowq = tid >> 2;
    int gcol = (tid & 3) * 8;              // bf16 elements
    const char* pAh = (const char*)(Ah + (size_t)(bm + rowq) * 512 + gcol);
    const char* pAl = (const char*)(Al + (size_t)(bm + rowq) * 512 + gcol);
    const char* pBh = (const char*)(Bh + (size_t)(bn + rowq) * 512 + gcol);
    const char* pBl = (const char*)(Bl + (size_t)(bn + rowq) * 512 + gcol);
    uint32_t dA = smb + rowq * TROWB + (tid & 3) * 16;           // A-hi stage0
    uint32_t dB = dA + 2 * TTILE;                                // B-hi stage0

    float acc[2][8][4];
    #pragma unroll
    for (int i = 0; i < 2; ++i)
        #pragma unroll
        for (int j = 0; j < 8; ++j)
            #pragma unroll
            for (int q = 0; q < 4; ++q) acc[i][j][q] = 0.f;

    int mat = lane >> 3, r8 = lane & 7;
    int lrow = (mat & 1) * 8 + r8;
    int lkb  = (mat >> 1) * 16;

    // ldmatrix bases (stage 0)
    uint32_t raBase = smb + (wm + lrow) * TROWB + lkb;
    uint32_t rbBase = smb + 2 * TTILE + (wn + lrow) * TROWB + lkb;

    // prologue: stage chunk 0 into buffer 0
    {
        CP_ASYNC16(dA,                    pAh);
        CP_ASYNC16(dA + DSTSKIP,          pAh + ROWSKIP);
        CP_ASYNC16(dA + TTILE,            pAl);
        CP_ASYNC16(dA + TTILE + DSTSKIP,  pAl + ROWSKIP);
        CP_ASYNC16(dB,                    pBh);
        CP_ASYNC16(dB + DSTSKIP,          pBh + ROWSKIP);
        CP_ASYNC16(dB + TTILE,            pBl);
        CP_ASYNC16(dB + TTILE + DSTSKIP,  pBl + ROWSKIP);
        pAh += 64; pAl += 64; pBh += 64; pBl += 64;
        CP_COMMIT();
    }

    for (int ch = 0; ch < 16; ++ch) {
        if (ch + 1 < 16) {
            uint32_t so = ((ch + 1) & 1) * TSTAGE;
            CP_ASYNC16(dA + so,                    pAh);
            CP_ASYNC16(dA + so + DSTSKIP,          pAh + ROWSKIP);
            CP_ASYNC16(dA + so + TTILE,            pAl);
            CP_ASYNC16(dA + so + TTILE + DSTSKIP,  pAl + ROWSKIP);
            CP_ASYNC16(dB + so,                    pBh);
            CP_ASYNC16(dB + so + DSTSKIP,          pBh + ROWSKIP);
            CP_ASYNC16(dB + so + TTILE,            pBl);
            CP_ASYNC16(dB + so + TTILE + DSTSKIP,  pBl + ROWSKIP);
            pAh += 64; pAl += 64; pBh += 64; pBl += 64;
            CP_COMMIT();
            CP_WAIT(1);
        } else {
            CP_WAIT(0);
        }
        __syncthreads();

        uint32_t so = (ch & 1) * TSTAGE;
        uint32_t ra0 = raBase + so;
        uint32_t rb0 = rbBase + so;
        #pragma unroll
        for (int ks = 0; ks < 2; ++ks) {
            uint32_t ah[2][4], al[2][4];
            #pragma unroll
            for (int mt = 0; mt < 2; ++mt) {
                uint32_t ra = ra0 + mt * (16 * TROWB) + ks * 32;
                LDSM4(ah[mt], ra);
                LDSM4(al[mt], ra + TTILE);
            }
            #pragma unroll
            for (int nt = 0; nt < 4; ++nt) {
                uint32_t rb = rb0 + nt * (16 * TROWB) + ks * 32;
                uint32_t bh4[4], bl4[4];
                LDSM4(bh4, rb);
                LDSM4(bl4, rb + TTILE);
                #pragma unroll
                for (int mt = 0; mt < 2; ++mt) {
                    MMA16816(acc[mt][nt*2+0], ah[mt], bh4[0], bh4[2]);
                    MMA16816(acc[mt][nt*2+1], ah[mt], bh4[1], bh4[3]);
                    MMA16816(acc[mt][nt*2+0], ah[mt], bl4[0], bl4[2]);
                    MMA16816(acc[mt][nt*2+1], ah[mt], bl4[1], bl4[3]);
                    MMA16816(acc[mt][nt*2+0], al[mt], bh4[0], bh4[2]);
                    MMA16816(acc[mt][nt*2+1], al[mt], bh4[1], bh4[3]);
                }
            }
        }
        __syncthreads();
    }

    int r0 = lane >> 2, c0 = (lane & 3) * 2;
    #pragma unroll
    for (int mt = 0; mt < 2; ++mt) {
        #pragma unroll
        for (int nt = 0; nt < 4; ++nt) {
            #pragma unroll
            for (int s = 0; s < 2; ++s) {
                float* a4 = acc[mt][nt*2+s];
                int col = bn + wn + nt * 16 + s * 8 + c0;
                int row = bm + wm + mt * 16 + r0;
                float v0 = a4[0], v1 = a4[1], v2 = a4[2], v3 = a4[3];
                if (do_silu) {
                    v0 = v0 / (1.f + __expf(-v0));
                    v1 = v1 / (1.f + __expf(-v1));
                    v2 = v2 / (1.f + __expf(-v2));
                    v3 = v3 / (1.f + __expf(-v3));
                }
                *reinterpret_cast<float2*>(C + (size_t)row * 512 + col)       = make_float2(v0, v1);
                *reinterpret_cast<float2*>(C + (size_t)(row + 8) * 512 + col) = make_float2(v2, v3);
            }
        }
    }
}

// ---------------------------------------------------------------------------
// SIMT SGEMM. MIXA: A element = x + (xshift - x) * tmx computed on the fly.
// EPI: 0 none, 1 tanh, 3 exp(-exp(bias+v)).
// ---------------------------------------------------------------------------
template<bool BT_MAJOR, int EPI, bool MIXA>
__global__ void __launch_bounds__(256) sgemm_kernel(
    const float* __restrict__ A, const float* __restrict__ Bm,
    float* __restrict__ Cout, const float* __restrict__ bias,
    const float* __restrict__ tmx,
    int M, int N, int K)
{
    __shared__ float As[16][65];
    __shared__ float Bs[16][65];
    int tid = threadIdx.x;
    int bm = blockIdx.y * 64;
    int bn = blockIdx.x * 64;
    int tx = tid & 15, ty = tid >> 4;
    float acc[4][4] = {};
    int arow = tid >> 2, aseg = tid & 3;

    for (int k0 = 0; k0 < K; k0 += 16) {
        int grow = bm + arow;
        const float* ap = A + (size_t)grow * K + k0 + aseg * 4;
        float4 a4 = *reinterpret_cast<const float4*>(ap);
        if (MIXA) {
            float4 xp = make_float4(0.f, 0.f, 0.f, 0.f);
            if (grow & (TT - 1)) xp = *reinterpret_cast<const float4*>(ap - K);
            float4 tm = *reinterpret_cast<const float4*>(tmx + k0 + aseg * 4);
            a4.x += (xp.x - a4.x) * tm.x;
            a4.y += (xp.y - a4.y) * tm.y;
            a4.z += (xp.z - a4.z) * tm.z;
            a4.w += (xp.w - a4.w) * tm.w;
        }
        As[aseg*4+0][arow] = a4.x; As[aseg*4+1][arow] = a4.y;
        As[aseg*4+2][arow] = a4.z; As[aseg*4+3][arow] = a4.w;

        if (BT_MAJOR) {
            int n = tid >> 2, seg = tid & 3;
            float4 b4 = make_float4(0.f, 0.f, 0.f, 0.f);
            if (bn + n < N)
                b4 = *reinterpret_cast<const float4*>(
                    Bm + (size_t)(bn + n) * K + k0 + seg * 4);
            Bs[seg*4+0][n] = b4.x; Bs[seg*4+1][n] = b4.y;
            Bs[seg*4+2][n] = b4.z; Bs[seg*4+3][n] = b4.w;
        } else {
            int kk = tid >> 4, nb = (tid & 15) * 4;
            float4 b4 = make_float4(0.f, 0.f, 0.f, 0.f);
            if (bn + nb < N)
                b4 = *reinterpret_cast<const float4*>(
                    Bm + (size_t)(k0 + kk) * N + bn + nb);
            Bs[kk][nb+0] = b4.x; Bs[kk][nb+1] = b4.y;
            Bs[kk][nb+2] = b4.z; Bs[kk][nb+3] = b4.w;
        }
        __syncthreads();

        #pragma unroll
        for (int kk = 0; kk < 16; ++kk) {
            float ar[4], br[4];
            #pragma unroll
            for (int q = 0; q < 4; ++q) ar[q] = As[kk][ty*4 + q];
            #pragma unroll
            for (int p = 0; p < 4; ++p) br[p] = Bs[kk][tx*4 + p];
            #pragma unroll
            for (int q = 0; q < 4; ++q)
                #pragma unroll
                for (int p = 0; p < 4; ++p)
                    acc[q][p] = fmaf(ar[q], br[p], acc[q][p]);
        }
        __syncthreads();
    }

    #pragma unroll
    for (int q = 0; q < 4; ++q) {
        int row = bm + ty*4 + q;
        #pragma unroll
        for (int p = 0; p < 4; ++p) {
            int col = bn + tx*4 + p;
            if (col < N) {
                float v = acc[q][p];
                if (EPI == 1) v = tanhf(v);
                else if (EPI == 3) v = __expf(-__expf(bias[col] + v));
                Cout[(size_t)row * N + col] = v;
            }
        }
    }
}

// ---------------------------------------------------------------------------
// split helper
// ---------------------------------------------------------------------------
__device__ __forceinline__ void wsplit(float v, __nv_bfloat16* hi, __nv_bfloat16* lo, size_t i) {
    __nv_bfloat16 h = __float2bfloat16(v);
    hi[i] = h;
    lo[i] = __float2bfloat16(v - __bfloat162float(h));
}

// ---------------------------------------------------------------------------
// mix back-projection + 5-way token mix. Block = 16 bt rows x 512 c.
// ---------------------------------------------------------------------------
__global__ void __launch_bounds__(512) mix_combine_kernel(
    const float* __restrict__ x, const float* __restrict__ mix,
    const float* __restrict__ W2,
    const float* __restrict__ maaw, const float* __restrict__ maak,
    const float* __restrict__ maav, const float* __restrict__ maar,
    const float* __restrict__ maag,
    float* __restrict__ xw,
    __nv_bfloat16* __restrict__ kh, __nv_bfloat16* __restrict__ kl,
    __nv_bfloat16* __restrict__ vh, __nv_bfloat16* __restrict__ vl,
    __nv_bfloat16* __restrict__ rh, __nv_bfloat16* __restrict__ rl,
    __nv_bfloat16* __restrict__ gh, __nv_bfloat16* __restrict__ gl)
{
    __shared__ float s_mix[16][160];
    __shared__ float s_x[16][512];
    __shared__ float s_xp0[512];
    int bt0 = blockIdx.x * 16;
    int c = threadIdx.x;

    for (int i = threadIdx.x; i < 16 * 160; i += 512)
        s_mix[i / 160][i % 160] = mix[(size_t)bt0 * 160 + i];
    #pragma unroll
    for (int row = 0; row < 16; ++row)
        s_x[row][c] = x[(size_t)(bt0 + row) * 512 + c];
    s_xp0[c] = (bt0 & (TT - 1)) ? x[(size_t)(bt0 - 1) * 512 + c] : 0.f;
    __syncthreads();

    float maa[5];
    maa[0] = maaw[c]; maa[1] = maak[c]; maa[2] = maav[c];
    maa[3] = maar[c]; maa[4] = maag[c];

    #pragma unroll
    for (int f = 0; f < 5; ++f) {
        float acc[16];
        #pragma unroll
        for (int row = 0; row < 16; ++row) acc[row] = 0.f;
        #pragma unroll 8
        for (int dd = 0; dd < 32; ++dd) {
            float w = W2[(size_t)(f * 32 + dd) * 512 + c];
            #pragma unroll
            for (int row = 0; row < 16; ++row)
                acc[row] = fmaf(s_mix[row][f * 32 + dd], w, acc[row]);
        }
        #pragma unroll
        for (int row = 0; row < 16; ++row) {
            size_t gi = (size_t)(bt0 + row) * 512 + c;
            float xc = s_x[row][c];
            float xp = (row > 0) ? s_x[row - 1][c] : s_xp0[c];
            float v = fmaf(xp - xc, maa[f] + acc[row], xc);
            if (f == 0) xw[gi] = v;
            else if (f == 1) wsplit(v, kh, kl, gi);
            else if (f == 2) wsplit(v, vh, vl, gi);
            else if (f == 3) wsplit(v, rh, rl, gi);
            else             wsplit(v, gh, gl, gi);
        }
    }
}

// ---------------------------------------------------------------------------
// All weight fp32 -> bf16 hi/lo splits in one launch (grid.y = which weight)
// ---------------------------------------------------------------------------
__global__ void convw_all_kernel(const float* __restrict__ W0, const float* __restrict__ W1,
                                 const float* __restrict__ W2, const float* __restrict__ W3,
                                 const float* __restrict__ W4,
                                 __nv_bfloat16* __restrict__ H0, __nv_bfloat16* __restrict__ L0,
                                 __nv_bfloat16* __restrict__ H1, __nv_bfloat16* __restrict__ L1,
                                 __nv_bfloat16* __restrict__ H2, __nv_bfloat16* __restrict__ L2,
                                 __nv_bfloat16* __restrict__ H3, __nv_bfloat16* __restrict__ L3,
                                 __nv_bfloat16* __restrict__ H4, __nv_bfloat16* __restrict__ L4)
{
    int w = blockIdx.y;
    const float* W = (w == 0) ? W0 : (w == 1) ? W1 : (w == 2) ? W2 : (w == 3) ? W3 : W4;
    __nv_bfloat16* H = (w == 0) ? H0 : (w == 1) ? H1 : (w == 2) ? H2 : (w == 3) ? H3 : H4;
    __nv_bfloat16* L = (w == 0) ? L0 : (w == 1) ? L1 : (w == 2) ? L2 : (w == 3) ? L3 : L4;
    int i = blockIdx.x * 256 + threadIdx.x;
    float v = W[i];
    __nv_bfloat16 h = __float2bfloat16(v);
    H[i] = h;
    L[i] = __float2bfloat16(v - __bfloat162float(h));
}

// ---------------------------------------------------------------------------
// Chunked WKV, kernel 1: per-chunk local scan.
// ---------------------------------------------------------------------------
__global__ void __launch_bounds__(256) wkv_chunk_kernel(
    const float* __restrict__ r, const float* __restrict__ k,
    const float* __restrict__ v, const float* __restrict__ d,
    const float* __restrict__ u,
    float* __restrict__ ylocal, float* __restrict__ Aout,
    float* __restrict__ Lout, float* __restrict__ Pout)
{
    int wid = threadIdx.x >> 5, lane = threadIdx.x & 31;
    int cid = blockIdx.x * 8 + wid;        // 0..2047
    int bh = cid >> 4, ch = cid & (NCH - 1);
    int b = bh >> 4, h = bh & (HH - 1);
    size_t base = ((size_t)b * TT + (size_t)ch * CHL) * CC + h * HSZ + lane;

    __shared__ float srkd[8][3][32];

    float S[32];
    #pragma unroll
    for (int j = 0; j < 32; ++j) S[j] = 0.f;
    float P = 1.f;
    float ul = u[h * HSZ + lane];

    size_t off = base;
    float rl = r[off], kl = k[off], dl = d[off], vl = v[off];

    for (int t = 0; t < CHL; ++t) {
        int tn = (t + 1 < CHL) ? (t + 1) : t;
        size_t offn = base + (size_t)tn * CC;
        float rn = r[offn], kn = k[offn], dn = d[offn], vn = v[offn];

        Aout[off] = rl * P;
        P *= dl;

        srkd[wid][0][lane] = rl;
        srkd[wid][1][lane] = kl;
        srkd[wid][2][lane] = dl;
        __syncwarp();

        float cp = rl * ul * kl;
        #pragma unroll
        for (int o = 16; o; o >>= 1) cp += __shfl_xor_sync(0xffffffffu, cp, o);

        float y0 = 0.f, y1 = 0.f, y2 = 0.f, y3 = 0.f;
        #pragma unroll
        for (int j4 = 0; j4 < 8; ++j4) {
            float4 r4 = *reinterpret_cast<const float4*>(&srkd[wid][0][j4 * 4]);
            float4 k4 = *reinterpret_cast<const float4*>(&srkd[wid][1][j4 * 4]);
            float4 d4 = *reinterpret_cast<const float4*>(&srkd[wid][2][j4 * 4]);
            y0 = fmaf(r4.x, S[j4*4+0], y0); S[j4*4+0] = fmaf(d4.x, S[j4*4+0], k4.x * vl);
            y1 = fmaf(r4.y, S[j4*4+1], y1); S[j4*4+1] = fmaf(d4.y, S[j4*4+1], k4.y * vl);
            y2 = fmaf(r4.z, S[j4*4+2], y2); S[j4*4+2] = fmaf(d4.z, S[j4*4+2], k4.z * vl);
            y3 = fmaf(r4.w, S[j4*4+3], y3); S[j4*4+3] = fmaf(d4.w, S[j4*4+3], k4.w * vl);
        }
        ylocal[off] = (y0 + y1) + (y2 + y3) + cp * vl;
        __syncwarp();

        rl = rn; kl = kn; dl = dn; vl = vn;
        off += CC;
    }

    #pragma unroll
    for (int j = 0; j < 32; ++j)
        Lout[(size_t)cid * 1024 + j * 32 + lane] = S[j];
    Pout[(size_t)cid * 32 + lane] = P;
}

// ---------------------------------------------------------------------------
// Chunked WKV, kernel 2: scan chunk states across the sequence.
// ---------------------------------------------------------------------------
__global__ void __launch_bounds__(1024) wkv_state_scan_kernel(
    const float* __restrict__ L, const float* __restrict__ P,
    float* __restrict__ S0out)
{
    int bh = blockIdx.x;
    int e = threadIdx.x;         // j*32 + i
    int j = e >> 5;
    float s = 0.f;
    #pragma unroll
    for (int c = 0; c < NCH; ++c) {
        size_t cid = (size_t)bh * NCH + c;
        S0out[cid * 1024 + e] = s;
        s = P[cid * 32 + j] * s + L[cid * 1024 + e];
    }
}

// ---------------------------------------------------------------------------
// Chunked WKV, kernel 3: y += A . S0 (per-chunk correction).
// ---------------------------------------------------------------------------
__global__ void __launch_bounds__(256) wkv_apply_kernel(
    const float* __restrict__ A, const float* __restrict__ S0,
    float* __restrict__ y)
{
    int cid = blockIdx.x;
    int ch = cid & (NCH - 1);
    if (ch == 0) return;
    int bh = cid >> 4;
    int b = bh >> 4, h = bh & (HH - 1);
    int wid = threadIdx.x >> 5, lane = threadIdx.x & 31;

    __shared__ float s0[1024];
    __shared__ float sa[8][32];
    for (int i = threadIdx.x; i < 1024; i += 256)
        s0[i] = S0[(size_t)cid * 1024 + i];
    __syncthreads();

    size_t base = ((size_t)b * TT + (size_t)ch * CHL) * CC + h * HSZ + lane;
    for (int tt = 0; tt < 16; ++tt) {
        int t = wid * 16 + tt;
        size_t off = base + (size_t)t * CC;
        sa[wid][lane] = A[off];
        __syncwarp();
        float acc = 0.f;
        #pragma unroll
        for (int j4 = 0; j4 < 8; ++j4) {
            float4 a4 = *reinterpret_cast<const float4*>(&sa[wid][j4 * 4]);
            acc = fmaf(a4.x, s0[(j4*4+0)*32 + lane], acc);
            acc = fmaf(a4.y, s0[(j4*4+1)*32 + lane], acc);
            acc = fmaf(a4.z, s0[(j4*4+2)*32 + lane], acc);
            acc = fmaf(a4.w, s0[(j4*4+3)*32 + lane], acc);
        }
        y[off] += acc;
        __syncwarp();
    }
}

// ---------------------------------------------------------------------------
// Per-head groupnorm * ln * gate -> bf16 hi/lo split for the Wo GEMM
// ---------------------------------------------------------------------------
__global__ void __launch_bounds__(256) gn_kernel(
    const float* __restrict__ y, const float* __restrict__ gate,
    const float* __restrict__ lnw, const float* __restrict__ lnb,
    __nv_bfloat16* __restrict__ zh, __nv_bfloat16* __restrict__ zl)
{
    int g = blockIdx.x * 8 + (threadIdx.x >> 5);
    int lane = threadIdx.x & 31;
    size_t idx = (size_t)g * 32 + lane;
    float v = y[idx];
    float s = v;
    #pragma unroll
    for (int o = 16; o; o >>= 1) s += __shfl_xor_sync(0xffffffffu, s, o);
    float mu = s * (1.f / 32.f);
    float dv = v - mu;
    float q = dv * dv;
    #pragma unroll
    for (int o = 16; o; o >>= 1) q += __shfl_xor_sync(0xffffffffu, q, o);
    float var = q * (1.f / 32.f);
    float yn = dv * rsqrtf(var + 1e-5f);
    int c = (int)(idx & (CC - 1));
    float z = (yn * lnw[c] + lnb[c]) * gate[idx];
    wsplit(z, zh, zl, idx);
}

// ---------------------------------------------------------------------------
extern "C" void kernel_launch(void* const* d_in, const int* in_sizes, int n_in,
                              void* d_out, int out_size) {
    const float* x      = (const float*)d_in[0];
    const float* tmaa_x = (const float*)d_in[1];
    const float* tmaa_w = (const float*)d_in[2];
    const float* tmaa_k = (const float*)d_in[3];
    const float* tmaa_v = (const float*)d_in[4];
    const float* tmaa_r = (const float*)d_in[5];
    const float* tmaa_g = (const float*)d_in[6];
    const float* w1     = (const float*)d_in[7];   // (C,160)
    const float* w2     = (const float*)d_in[8];   // (5,32,C)
    const float* tdecay = (const float*)d_in[9];   // (C,)
    const float* tdw1   = (const float*)d_in[10];  // (C,64)
    const float* tdw2   = (const float*)d_in[11];  // (64,C)
    const float* faaaa  = (const float*)d_in[12];  // (H,HS)
    const float* Wr     = (const float*)d_in[13];
    const float* Wk     = (const float*)d_in[14];
    const float* Wv     = (const float*)d_in[15];
    const float* Wg     = (const float*)d_in[16];
    const float* Wo     = (const float*)d_in[17];
    const float* lnw    = (const float*)d_in[18];
    const float* lnb    = (const float*)d_in[19];
    float* out = (float*)d_out;

    unsigned char* S;
    cudaGetSymbolAddress((void**)&S, g_scratch);
    float* mixb = (float*)(S + O_MIX);
    float* xw   = (float*)(S + O_XW);
    float* w64  = (float*)(S + O_W64);
    float* db   = (float*)(S + O_DB);
    float* rb   = (float*)(S + O_RB);
    float* kb   = (float*)(S + O_KB);
    float* vb   = (float*)(S + O_VB);
    float* gb   = (float*)(S + O_GB);
    float* yb   = (float*)(S + O_YB);
    float* ab   = (float*)(S + O_AB);
    float* lb   = (float*)(S + O_LB);
    float* pb   = (float*)(S + O_PB);
    float* s0b  = (float*)(S + O_S0);
    __nv_bfloat16* kh = (__nv_bfloat16*)(S + O_KH);
    __nv_bfloat16* kl = (__nv_bfloat16*)(S + O_KL);
    __nv_bfloat16* vh = (__nv_bfloat16*)(S + O_VH);
    __nv_bfloat16* vl = (__nv_bfloat16*)(S + O_VL);
    __nv_bfloat16* rh = (__nv_bfloat16*)(S + O_RH);
    __nv_bfloat16* rl = (__nv_bfloat16*)(S + O_RL);
    __nv_bfloat16* gh = (__nv_bfloat16*)(S + O_GH);
    __nv_bfloat16* gl = (__nv_bfloat16*)(S + O_GL);
    __nv_bfloat16* zh = (__nv_bfloat16*)(S + O_ZH);
    __nv_bfloat16* zl = (__nv_bfloat16*)(S + O_ZL);
    __nv_bfloat16* wrh = (__nv_bfloat16*)(S + O_WRH);
    __nv_bfloat16* wrl = (__nv_bfloat16*)(S + O_WRL);
    __nv_bfloat16* wkh = (__nv_bfloat16*)(S + O_WKH);
    __nv_bfloat16* wkl = (__nv_bfloat16*)(S + O_WKL);
    __nv_bfloat16* wvh = (__nv_bfloat16*)(S + O_WVH);
    __nv_bfloat16* wvl = (__nv_bfloat16*)(S + O_WVL);
    __nv_bfloat16* wgh = (__nv_bfloat16*)(S + O_WGH);
    __nv_bfloat16* wgl = (__nv_bfloat16*)(S + O_WGL);
    __nv_bfloat16* woh = (__nv_bfloat16*)(S + O_WOH);
    __nv_bfloat16* wol = (__nv_bfloat16*)(S + O_WOL);

    cudaFuncSetAttribute(tgemm_kernel<true, 0>, cudaFuncAttributeMaxDynamicSharedMemorySize, TG_SMEM);
    cudaFuncSetAttribute(tgemm_kernel<false, 0>, cudaFuncAttributeMaxDynamicSharedMemorySize, TG_SMEM);

    // 0) weight splits, one launch
    convw_all_kernel<<<dim3(1024, 5), 256>>>(Wr, Wk, Wv, Wg, Wo,
                                             wrh, wrl, wkh, wkl, wvh, wvl,
                                             wgh, wgl, woh, wol);

    // 1) mix = tanh((x + (shift(x)-x)*maa_x) @ w1)   [BT,160], prep fused
    sgemm_kernel<false, 1, true><<<dim3(3, BT / 64), 256>>>(
        x, w1, mixb, nullptr, tmaa_x, BT, 160, CC);

    // 2) 5-way mix back-projection + token mixing (16 bt rows per block)
    mix_combine_kernel<<<BT / 16, 512>>>(x, mixb, w2, tmaa_w, tmaa_k, tmaa_v,
                                         tmaa_r, tmaa_g, xw, kh, kl, vh, vl,
                                         rh, rl, gh, gl);

    // 3) 4 projections in ONE batched tensor-core launch (z==3 (g) = silu)
    {
        TGBatch bt_{};
        bt_.ah[0] = rh; bt_.al[0] = rl; bt_.bh[0] = wrh; bt_.bl[0] = wrl; bt_.c[0] = rb;
        bt_.ah[1] = kh; bt_.al[1] = kl; bt_.bh[1] = wkh; bt_.bl[1] = wkl; bt_.c[1] = kb;
        bt_.ah[2] = vh; bt_.al[2] = vl; bt_.bh[2] = wvh; bt_.bl[2] = wvl; bt_.c[2] = vb;
        bt_.ah[3] = gh; bt_.al[3] = gl; bt_.bh[3] = wgh; bt_.bl[3] = wgl; bt_.c[3] = gb;
        tgemm_kernel<true, 0><<<dim3(4, BT / 128, 4), 256, TG_SMEM>>>(
            bt_, nullptr, nullptr, nullptr, nullptr, nullptr);
    }

    // 4) decay MLP: w64 = tanh(xw @ tdw1); d = exp(-exp(tdecay + w64 @ tdw2))
    sgemm_kernel<false, 1, false><<<dim3(1, BT / 64), 256>>>(
        xw, tdw1, w64, nullptr, nullptr, BT, 64, CC);
    sgemm_kernel<false, 3, false><<<dim3(8, BT / 64), 256>>>(
        w64, tdw2, db, tdecay, nullptr, BT, CC, 64);

    // 5) WKV6 chunked scan: local scans -> state scan -> correction
    wkv_chunk_kernel<<<NCID / 8, 256>>>(rb, kb, vb, db, faaaa, yb, ab, lb, pb);
    wkv_state_scan_kernel<<<BQ * HH, 1024>>>(lb, pb, s0b);
    wkv_apply_kernel<<<NCID, 256>>>(ab, s0b, yb);

    // 6) groupnorm * ln * gate -> z (bf16 split)
    gn_kernel<<<(BT * HH) / 8, 256>>>(yb, gb, lnw, lnb, zh, zl);

    // 7) out = z @ Wo^T (tensor cores)
    {
        TGBatch dummy{};
        tgemm_kernel<false, 0><<<dim3(4, BT / 128), 256, TG_SMEM>>>(
            dummy, zh, zl, woh, wol, out);
    }
}

// round 10
// speedup vs baseline: 2.3454x; 1.0592x over previous
#include <cuda_runtime.h>
#include <cuda_bf16.h>
#include <cstdint>

#define BQ 8
#define TT 2048
#define CC 512
#define HH 16
#define HSZ 32
#define BT (BQ*TT)            // 16384
#define UEL ((size_t)BT*CC)   // 8388608 elements per [B,T,C] buffer
#define NCH 16                // chunks per sequence
#define CHL 128               // chunk length (TT/NCH)
#define NCID (BQ*HH*NCH)      // 2048 total chunks

// ---------------------------------------------------------------------------
// Scratch (bytes). One big device array; no allocations anywhere.
// ---------------------------------------------------------------------------
#define SZ_F32   (UEL*4)
#define SZ_BF16  (UEL*2)
#define SZ_MIX   ((size_t)BT*160*4)
#define SZ_W64B  ((size_t)BT*64*2)
#define SZ_WBF   ((size_t)CC*CC*2)
#define SZ_L     ((size_t)NCID*1024*4)
#define SZ_P     ((size_t)NCID*32*4)

#define O_MIX   ((size_t)0)
#define O_XWH   (O_MIX + SZ_MIX)
#define O_XWL   (O_XWH + SZ_BF16)
#define O_W64H  (O_XWL + SZ_BF16)
#define O_W64L  (O_W64H + SZ_W64B)
#define O_DB    (O_W64L + SZ_W64B)
#define O_RB    (O_DB + SZ_F32)
#define O_KB    (O_RB + SZ_F32)
#define O_VB    (O_KB + SZ_F32)
#define O_GB    (O_VB + SZ_F32)
#define O_YB    (O_GB + SZ_F32)
#define O_AB    (O_YB + SZ_F32)
#define O_LB    (O_AB + SZ_F32)
#define O_PB    (O_LB + SZ_L)
#define O_S0    (O_PB + SZ_P)
#define O_KH    (O_S0 + SZ_L)
#define O_KL    (O_KH + SZ_BF16)
#define O_VH    (O_KL + SZ_BF16)
#define O_VL    (O_VH + SZ_BF16)
#define O_RH    (O_VL + SZ_BF16)
#define O_RL    (O_RH + SZ_BF16)
#define O_GH    (O_RL + SZ_BF16)
#define O_GL    (O_GH + SZ_BF16)
#define O_ZH    (O_GL + SZ_BF16)
#define O_ZL    (O_ZH + SZ_BF16)
#define O_WRH   (O_ZL + SZ_BF16)
#define O_WRL   (O_WRH + SZ_WBF)
#define O_WKH   (O_WRL + SZ_WBF)
#define O_WKL   (O_WKH + SZ_WBF)
#define O_WVH   (O_WKL + SZ_WBF)
#define O_WVL   (O_WVH + SZ_WBF)
#define O_WGH   (O_WVL + SZ_WBF)
#define O_WGL   (O_WGH + SZ_WBF)
#define O_WOH   (O_WGL + SZ_WBF)
#define O_WOL   (O_WOH + SZ_WBF)
#define O_T1H   (O_WOL + SZ_WBF)                 // tdw1^T padded: 128x512 bf16
#define O_T1L   (O_T1H + (size_t)128*512*2)
#define O_T2H   (O_T1L + (size_t)128*512*2)      // tdw2^T: 512x64 bf16
#define O_T2L   (O_T2H + (size_t)512*64*2)
#define SCRATCH_BYTES (O_T2L + (size_t)512*64*2)

__device__ __align__(256) unsigned char g_scratch[SCRATCH_BYTES];

// ---------------------------------------------------------------------------
// mma.sync / cp.async helpers (valid on plain compute_103 / sm_80+)
// ---------------------------------------------------------------------------
__device__ __forceinline__ uint32_t smem_u32(const void* p) {
    uint32_t a;
    asm("{ .reg .u64 t; cvta.to.shared.u64 t, %1; cvt.u32.u64 %0, t; }"
        : "=r"(a) : "l"(p));
    return a;
}

#define LDSM4(r, a) \
    asm volatile("ldmatrix.sync.aligned.m8n8.x4.shared.b16 {%0,%1,%2,%3}, [%4];" \
        : "=r"((r)[0]), "=r"((r)[1]), "=r"((r)[2]), "=r"((r)[3]) : "r"(a))

#define MMA16816(d, a, b0, b1) \
    asm volatile("mma.sync.aligned.m16n8k16.row.col.f32.bf16.bf16.f32 " \
        "{%0,%1,%2,%3}, {%4,%5,%6,%7}, {%8,%9}, {%0,%1,%2,%3};" \
        : "+f"((d)[0]), "+f"((d)[1]), "+f"((d)[2]), "+f"((d)[3]) \
        : "r"((a)[0]), "r"((a)[1]), "r"((a)[2]), "r"((a)[3]), "r"(b0), "r"(b1))

#define CP_ASYNC16(dst, src) \
    asm volatile("cp.async.cg.shared.global [%0], [%1], 16;" :: "r"(dst), "l"(src))
#define CP_COMMIT() asm volatile("cp.async.commit_group;" ::: "memory")
#define CP_WAIT(n)  asm volatile("cp.async.wait_group %0;" :: "n"(n) : "memory")

#define TROWB 80
#define TTILE (128*TROWB)     // 10240
#define TSTAGE (4*TTILE)      // 40960
#define TG_SMEM (2*TSTAGE)    // 81920
#define ROWSKIP (64*1024)     // 64 rows * 512 cols * 2B (K=512 path)
#define DSTSKIP (64*TROWB)

// ---------------------------------------------------------------------------
// split helper
// ---------------------------------------------------------------------------
__device__ __forceinline__ void wsplit(float v, __nv_bfloat16* hi, __nv_bfloat16* lo, size_t i) {
    __nv_bfloat16 h = __float2bfloat16(v);
    hi[i] = h;
    lo[i] = __float2bfloat16(v - __bfloat162float(h));
}

// ---------------------------------------------------------------------------
// Pipelined tensor-core GEMM (hot path, K=512, N=512): unchanged from R9.
// ---------------------------------------------------------------------------
struct TGBatch {
    const __nv_bfloat16 *ah[4], *al[4], *bh[4], *bl[4];
    float* c[4];
};

template<bool BATCH, int EPI>
__global__ void __launch_bounds__(256, 2)
tgemm_kernel(TGBatch bt_,
             const __nv_bfloat16* __restrict__ Ah_, const __nv_bfloat16* __restrict__ Al_,
             const __nv_bfloat16* __restrict__ Bh_, const __nv_bfloat16* __restrict__ Bl_,
             float* __restrict__ C_)
{
    extern __shared__ unsigned char sm[];
    uint32_t smb = smem_u32(sm);
    int tid = threadIdx.x;
    int wid = tid >> 5, lane = tid & 31;
    int bm = blockIdx.y * 128, bn = blockIdx.x * 128;
    int wm = (wid & 3) * 32, wn = (wid >> 2) * 64;

    int z = BATCH ? blockIdx.z : 0;
    const __nv_bfloat16* Ah = BATCH ? bt_.ah[z] : Ah_;
    const __nv_bfloat16* Al = BATCH ? bt_.al[z] : Al_;
    const __nv_bfloat16* Bh = BATCH ? bt_.bh[z] : Bh_;
    const __nv_bfloat16* Bl = BATCH ? bt_.bl[z] : Bl_;
    float* C = BATCH ? bt_.c[z] : C_;
    bool do_silu = BATCH ? (z == 3) : (EPI == 2);

    int rowq = tid >> 2;
    int gcol = (tid & 3) * 8;
    const char* pAh = (const char*)(Ah + (size_t)(bm + rowq) * 512 + gcol);
    const char* pAl = (const char*)(Al + (size_t)(bm + rowq) * 512 + gcol);
    const char* pBh = (const char*)(Bh + (size_t)(bn + rowq) * 512 + gcol);
    const char* pBl = (const char*)(Bl + (size_t)(bn + rowq) * 512 + gcol);
    uint32_t dA = smb + rowq * TROWB + (tid & 3) * 16;
    uint32_t dB = dA + 2 * TTILE;

    float acc[2][8][4];
    #pragma unroll
    for (int i = 0; i < 2; ++i)
        #pragma unroll
        for (int j = 0; j < 8; ++j)
            #pragma unroll
            for (int q = 0; q < 4; ++q) acc[i][j][q] = 0.f;

    int mat = lane >> 3, r8 = lane & 7;
    int lrow = (mat & 1) * 8 + r8;
    int lkb  = (mat >> 1) * 16;
    uint32_t raBase = smb + (wm + lrow) * TROWB + lkb;
    uint32_t rbBase = smb + 2 * TTILE + (wn + lrow) * TROWB + lkb;

    {
        CP_ASYNC16(dA,                    pAh);
        CP_ASYNC16(dA + DSTSKIP,          pAh + ROWSKIP);
        CP_ASYNC16(dA + TTILE,            pAl);
        CP_ASYNC16(dA + TTILE + DSTSKIP,  pAl + ROWSKIP);
        CP_ASYNC16(dB,                    pBh);
        CP_ASYNC16(dB + DSTSKIP,          pBh + ROWSKIP);
        CP_ASYNC16(dB + TTILE,            pBl);
        CP_ASYNC16(dB + TTILE + DSTSKIP,  pBl + ROWSKIP);
        pAh += 64; pAl += 64; pBh += 64; pBl += 64;
        CP_COMMIT();
    }

    for (int ch = 0; ch < 16; ++ch) {
        if (ch + 1 < 16) {
            uint32_t so = ((ch + 1) & 1) * TSTAGE;
            CP_ASYNC16(dA + so,                    pAh);
            CP_ASYNC16(dA + so + DSTSKIP,          pAh + ROWSKIP);
            CP_ASYNC16(dA + so + TTILE,            pAl);
            CP_ASYNC16(dA + so + TTILE + DSTSKIP,  pAl + ROWSKIP);
            CP_ASYNC16(dB + so,                    pBh);
            CP_ASYNC16(dB + so + DSTSKIP,          pBh + ROWSKIP);
            CP_ASYNC16(dB + so + TTILE,            pBl);
            CP_ASYNC16(dB + so + TTILE + DSTSKIP,  pBl + ROWSKIP);
            pAh += 64; pAl += 64; pBh += 64; pBl += 64;
            CP_COMMIT();
            CP_WAIT(1);
        } else {
            CP_WAIT(0);
        }
        __syncthreads();

        uint32_t so = (ch & 1) * TSTAGE;
        uint32_t ra0 = raBase + so;
        uint32_t rb0 = rbBase + so;
        #pragma unroll
        for (int ks = 0; ks < 2; ++ks) {
            uint32_t ah[2][4], al[2][4];
            #pragma unroll
            for (int mt = 0; mt < 2; ++mt) {
                uint32_t ra = ra0 + mt * (16 * TROWB) + ks * 32;
                LDSM4(ah[mt], ra);
                LDSM4(al[mt], ra + TTILE);
            }
            #pragma unroll
            for (int nt = 0; nt < 4; ++nt) {
                uint32_t rb = rb0 + nt * (16 * TROWB) + ks * 32;
                uint32_t bh4[4], bl4[4];
                LDSM4(bh4, rb);
                LDSM4(bl4, rb + TTILE);
                #pragma unroll
                for (int mt = 0; mt < 2; ++mt) {
                    MMA16816(acc[mt][nt*2+0], ah[mt], bh4[0], bh4[2]);
                    MMA16816(acc[mt][nt*2+1], ah[mt], bh4[1], bh4[3]);
                    MMA16816(acc[mt][nt*2+0], ah[mt], bl4[0], bl4[2]);
                    MMA16816(acc[mt][nt*2+1], ah[mt], bl4[1], bl4[3]);
                    MMA16816(acc[mt][nt*2+0], al[mt], bh4[0], bh4[2]);
                    MMA16816(acc[mt][nt*2+1], al[mt], bh4[1], bh4[3]);
                }
            }
        }
        __syncthreads();
    }

    int r0 = lane >> 2, c0 = (lane & 3) * 2;
    #pragma unroll
    for (int mt = 0; mt < 2; ++mt) {
        #pragma unroll
        for (int nt = 0; nt < 4; ++nt) {
            #pragma unroll
            for (int s = 0; s < 2; ++s) {
                float* a4 = acc[mt][nt*2+s];
                int col = bn + wn + nt * 16 + s * 8 + c0;
                int row = bm + wm + mt * 16 + r0;
                float v0 = a4[0], v1 = a4[1], v2 = a4[2], v3 = a4[3];
                if (do_silu) {
                    v0 = v0 / (1.f + __expf(-v0));
                    v1 = v1 / (1.f + __expf(-v1));
                    v2 = v2 / (1.f + __expf(-v2));
                    v3 = v3 / (1.f + __expf(-v3));
                }
                *reinterpret_cast<float2*>(C + (size_t)row * 512 + col)       = make_float2(v0, v1);
                *reinterpret_cast<float2*>(C + (size_t)(row + 8) * 512 + col) = make_float2(v2, v3);
            }
        }
    }
}

// ---------------------------------------------------------------------------
// Parameterized tensor GEMM clone for the decay MLP.
// NK = K/32 chunks. EPI: 1 tanh, 3 exp(-exp(bias+v)). SPLITOUT: bf16 hi/lo out.
// A pitch = K, B pitch = K (B padded to >=128*gridDim.x rows), C pitch = N.
// ---------------------------------------------------------------------------
template<int NK, int EPI, bool SPLITOUT>
__global__ void __launch_bounds__(256, 2)
tgemm2_kernel(const __nv_bfloat16* __restrict__ Ah, const __nv_bfloat16* __restrict__ Al,
              const __nv_bfloat16* __restrict__ Bh, const __nv_bfloat16* __restrict__ Bl,
              float* __restrict__ Cf,
              __nv_bfloat16* __restrict__ Chi, __nv_bfloat16* __restrict__ Clo,
              const float* __restrict__ bias, int N)
{
    constexpr int K = NK * 32;
    constexpr int RSKIP = 64 * K * 2;
    extern __shared__ unsigned char sm[];
    uint32_t smb = smem_u32(sm);
    int tid = threadIdx.x;
    int wid = tid >> 5, lane = tid & 31;
    int bm = blockIdx.y * 128, bn = blockIdx.x * 128;
    int wm = (wid & 3) * 32, wn = (wid >> 2) * 64;

    int rowq = tid >> 2;
    int gcol = (tid & 3) * 8;
    const char* pAh = (const char*)(Ah + (size_t)(bm + rowq) * K + gcol);
    const char* pAl = (const char*)(Al + (size_t)(bm + rowq) * K + gcol);
    const char* pBh = (const char*)(Bh + (size_t)(bn + rowq) * K + gcol);
    const char* pBl = (const char*)(Bl + (size_t)(bn + rowq) * K + gcol);
    uint32_t dA = smb + rowq * TROWB + (tid & 3) * 16;
    uint32_t dB = dA + 2 * TTILE;

    float acc[2][8][4];
    #pragma unroll
    for (int i = 0; i < 2; ++i)
        #pragma unroll
        for (int j = 0; j < 8; ++j)
            #pragma unroll
            for (int q = 0; q < 4; ++q) acc[i][j][q] = 0.f;

    int mat = lane >> 3, r8 = lane & 7;
    int lrow = (mat & 1) * 8 + r8;
    int lkb  = (mat >> 1) * 16;
    uint32_t raBase = smb + (wm + lrow) * TROWB + lkb;
    uint32_t rbBase = smb + 2 * TTILE + (wn + lrow) * TROWB + lkb;

    {
        CP_ASYNC16(dA,                   pAh);
        CP_ASYNC16(dA + DSTSKIP,         pAh + RSKIP);
        CP_ASYNC16(dA + TTILE,           pAl);
        CP_ASYNC16(dA + TTILE + DSTSKIP, pAl + RSKIP);
        CP_ASYNC16(dB,                   pBh);
        CP_ASYNC16(dB + DSTSKIP,         pBh + RSKIP);
        CP_ASYNC16(dB + TTILE,           pBl);
        CP_ASYNC16(dB + TTILE + DSTSKIP, pBl + RSKIP);
        pAh += 64; pAl += 64; pBh += 64; pBl += 64;
        CP_COMMIT();
    }

    for (int ch = 0; ch < NK; ++ch) {
        if (ch + 1 < NK) {
            uint32_t so = ((ch + 1) & 1) * TSTAGE;
            CP_ASYNC16(dA + so,                   pAh);
            CP_ASYNC16(dA + so + DSTSKIP,         pAh + RSKIP);
            CP_ASYNC16(dA + so + TTILE,           pAl);
            CP_ASYNC16(dA + so + TTILE + DSTSKIP, pAl + RSKIP);
            CP_ASYNC16(dB + so,                   pBh);
            CP_ASYNC16(dB + so + DSTSKIP,         pBh + RSKIP);
            CP_ASYNC16(dB + so + TTILE,           pBl);
            CP_ASYNC16(dB + so + TTILE + DSTSKIP, pBl + RSKIP);
            pAh += 64; pAl += 64; pBh += 64; pBl += 64;
            CP_COMMIT();
            CP_WAIT(1);
        } else {
            CP_WAIT(0);
        }
        __syncthreads();

        uint32_t so = (ch & 1) * TSTAGE;
        uint32_t ra0 = raBase + so;
        uint32_t rb0 = rbBase + so;
        #pragma unroll
        for (int ks = 0; ks < 2; ++ks) {
            uint32_t ah[2][4], al[2][4];
            #pragma unroll
            for (int mt = 0; mt < 2; ++mt) {
                uint32_t ra = ra0 + mt * (16 * TROWB) + ks * 32;
                LDSM4(ah[mt], ra);
                LDSM4(al[mt], ra + TTILE);
            }
            #pragma unroll
            for (int nt = 0; nt < 4; ++nt) {
                uint32_t rb = rb0 + nt * (16 * TROWB) + ks * 32;
                uint32_t bh4[4], bl4[4];
                LDSM4(bh4, rb);
                LDSM4(bl4, rb + TTILE);
                #pragma unroll
                for (int mt = 0; mt < 2; ++mt) {
                    MMA16816(acc[mt][nt*2+0], ah[mt], bh4[0], bh4[2]);
                    MMA16816(acc[mt][nt*2+1], ah[mt], bh4[1], bh4[3]);
                    MMA16816(acc[mt][nt*2+0], ah[mt], bl4[0], bl4[2]);
                    MMA16816(acc[mt][nt*2+1], ah[mt], bl4[1], bl4[3]);
                    MMA16816(acc[mt][nt*2+0], al[mt], bh4[0], bh4[2]);
                    MMA16816(acc[mt][nt*2+1], al[mt], bh4[1], bh4[3]);
                }
            }
        }
        __syncthreads();
    }

    int r0 = lane >> 2, c0 = (lane & 3) * 2;
    #pragma unroll
    for (int mt = 0; mt < 2; ++mt) {
        #pragma unroll
        for (int nt = 0; nt < 4; ++nt) {
            #pragma unroll
            for (int s = 0; s < 2; ++s) {
                float* a4 = acc[mt][nt*2+s];
                int col = bn + wn + nt * 16 + s * 8 + c0;
                if (col >= N) continue;
                int row = bm + wm + mt * 16 + r0;
                #pragma unroll
                for (int half = 0; half < 2; ++half) {
                    float v0 = a4[half * 2 + 0], v1 = a4[half * 2 + 1];
                    size_t ro = (size_t)(row + half * 8) * N + col;
                    if (EPI == 1) { v0 = tanhf(v0); v1 = tanhf(v1); }
                    else if (EPI == 3) {
                        v0 = __expf(-__expf(bias[col] + v0));
                        v1 = __expf(-__expf(bias[col + 1] + v1));
                    }
                    if (SPLITOUT) {
                        wsplit(v0, Chi, Clo, ro);
                        wsplit(v1, Chi, Clo, ro + 1);
                    } else {
                        *reinterpret_cast<float2*>(Cf + ro) = make_float2(v0, v1);
                    }
                }
            }
        }
    }
}

// ---------------------------------------------------------------------------
// SIMT SGEMM (mix GEMM only). MIXA fused.
// ---------------------------------------------------------------------------
template<bool BT_MAJOR, int EPI, bool MIXA>
__global__ void __launch_bounds__(256) sgemm_kernel(
    const float* __restrict__ A, const float* __restrict__ Bm,
    float* __restrict__ Cout, const float* __restrict__ bias,
    const float* __restrict__ tmx,
    int M, int N, int K)
{
    __shared__ float As[16][65];
    __shared__ float Bs[16][65];
    int tid = threadIdx.x;
    int bm = blockIdx.y * 64;
    int bn = blockIdx.x * 64;
    int tx = tid & 15, ty = tid >> 4;
    float acc[4][4] = {};
    int arow = tid >> 2, aseg = tid & 3;

    for (int k0 = 0; k0 < K; k0 += 16) {
        int grow = bm + arow;
        const float* ap = A + (size_t)grow * K + k0 + aseg * 4;
        float4 a4 = *reinterpret_cast<const float4*>(ap);
        if (MIXA) {
            float4 xp = make_float4(0.f, 0.f, 0.f, 0.f);
            if (grow & (TT - 1)) xp = *reinterpret_cast<const float4*>(ap - K);
            float4 tm = *reinterpret_cast<const float4*>(tmx + k0 + aseg * 4);
            a4.x += (xp.x - a4.x) * tm.x;
            a4.y += (xp.y - a4.y) * tm.y;
            a4.z += (xp.z - a4.z) * tm.z;
            a4.w += (xp.w - a4.w) * tm.w;
        }
        As[aseg*4+0][arow] = a4.x; As[aseg*4+1][arow] = a4.y;
        As[aseg*4+2][arow] = a4.z; As[aseg*4+3][arow] = a4.w;

        if (BT_MAJOR) {
            int n = tid >> 2, seg = tid & 3;
            float4 b4 = make_float4(0.f, 0.f, 0.f, 0.f);
            if (bn + n < N)
                b4 = *reinterpret_cast<const float4*>(
                    Bm + (size_t)(bn + n) * K + k0 + seg * 4);
            Bs[seg*4+0][n] = b4.x; Bs[seg*4+1][n] = b4.y;
            Bs[seg*4+2][n] = b4.z; Bs[seg*4+3][n] = b4.w;
        } else {
            int kk = tid >> 4, nb = (tid & 15) * 4;
            float4 b4 = make_float4(0.f, 0.f, 0.f, 0.f);
            if (bn + nb < N)
                b4 = *reinterpret_cast<const float4*>(
                    Bm + (size_t)(k0 + kk) * N + bn + nb);
            Bs[kk][nb+0] = b4.x; Bs[kk][nb+1] = b4.y;
            Bs[kk][nb+2] = b4.z; Bs[kk][nb+3] = b4.w;
        }
        __syncthreads();

        #pragma unroll
        for (int kk = 0; kk < 16; ++kk) {
            float ar[4], br[4];
            #pragma unroll
            for (int q = 0; q < 4; ++q) ar[q] = As[kk][ty*4 + q];
            #pragma unroll
            for (int p = 0; p < 4; ++p) br[p] = Bs[kk][tx*4 + p];
            #pragma unroll
            for (int q = 0; q < 4; ++q)
                #pragma unroll
                for (int p = 0; p < 4; ++p)
                    acc[q][p] = fmaf(ar[q], br[p], acc[q][p]);
        }
        __syncthreads();
    }

    #pragma unroll
    for (int q = 0; q < 4; ++q) {
        int row = bm + ty*4 + q;
        #pragma unroll
        for (int p = 0; p < 4; ++p) {
            int col = bn + tx*4 + p;
            if (col < N) {
                float v = acc[q][p];
                if (EPI == 1) v = tanhf(v);
                Cout[(size_t)row * N + col] = v;
            }
        }
    }
}

// ---------------------------------------------------------------------------
// mix back-projection + 5-way token mix. Block = 16 bt rows x 512 c.
// xw now emitted as bf16 hi/lo for the tensorized decay MLP.
// ---------------------------------------------------------------------------
__global__ void __launch_bounds__(512) mix_combine_kernel(
    const float* __restrict__ x, const float* __restrict__ mix,
    const float* __restrict__ W2,
    const float* __restrict__ maaw, const float* __restrict__ maak,
    const float* __restrict__ maav, const float* __restrict__ maar,
    const float* __restrict__ maag,
    __nv_bfloat16* __restrict__ xwh, __nv_bfloat16* __restrict__ xwl,
    __nv_bfloat16* __restrict__ kh, __nv_bfloat16* __restrict__ kl,
    __nv_bfloat16* __restrict__ vh, __nv_bfloat16* __restrict__ vl,
    __nv_bfloat16* __restrict__ rh, __nv_bfloat16* __restrict__ rl,
    __nv_bfloat16* __restrict__ gh, __nv_bfloat16* __restrict__ gl)
{
    __shared__ float s_mix[16][160];
    __shared__ float s_x[16][512];
    __shared__ float s_xp0[512];
    int bt0 = blockIdx.x * 16;
    int c = threadIdx.x;

    for (int i = threadIdx.x; i < 16 * 160; i += 512)
        s_mix[i / 160][i % 160] = mix[(size_t)bt0 * 160 + i];
    #pragma unroll
    for (int row = 0; row < 16; ++row)
        s_x[row][c] = x[(size_t)(bt0 + row) * 512 + c];
    s_xp0[c] = (bt0 & (TT - 1)) ? x[(size_t)(bt0 - 1) * 512 + c] : 0.f;
    __syncthreads();

    float maa[5];
    maa[0] = maaw[c]; maa[1] = maak[c]; maa[2] = maav[c];
    maa[3] = maar[c]; maa[4] = maag[c];

    #pragma unroll
    for (int f = 0; f < 5; ++f) {
        float acc[16];
        #pragma unroll
        for (int row = 0; row < 16; ++row) acc[row] = 0.f;
        #pragma unroll 8
        for (int dd = 0; dd < 32; ++dd) {
            float w = W2[(size_t)(f * 32 + dd) * 512 + c];
            #pragma unroll
            for (int row = 0; row < 16; ++row)
                acc[row] = fmaf(s_mix[row][f * 32 + dd], w, acc[row]);
        }
        #pragma unroll
        for (int row = 0; row < 16; ++row) {
            size_t gi = (size_t)(bt0 + row) * 512 + c;
            float xc = s_x[row][c];
            float xp = (row > 0) ? s_x[row - 1][c] : s_xp0[c];
            float v = fmaf(xp - xc, maa[f] + acc[row], xc);
            if (f == 0)      wsplit(v, xwh, xwl, gi);
            else if (f == 1) wsplit(v, kh, kl, gi);
            else if (f == 2) wsplit(v, vh, vl, gi);
            else if (f == 3) wsplit(v, rh, rl, gi);
            else             wsplit(v, gh, gl, gi);
        }
    }
}

// ---------------------------------------------------------------------------
// All weight fp32 -> bf16 hi/lo splits in one launch (grid.y = which weight)
// ---------------------------------------------------------------------------
__global__ void convw_all_kernel(const float* __restrict__ W0, const float* __restrict__ W1,
                                 const float* __restrict__ W2, const float* __restrict__ W3,
                                 const float* __restrict__ W4,
                                 __nv_bfloat16* __restrict__ H0, __nv_bfloat16* __restrict__ L0,
                                 __nv_bfloat16* __restrict__ H1, __nv_bfloat16* __restrict__ L1,
                                 __nv_bfloat16* __restrict__ H2, __nv_bfloat16* __restrict__ L2,
                                 __nv_bfloat16* __restrict__ H3, __nv_bfloat16* __restrict__ L3,
                                 __nv_bfloat16* __restrict__ H4, __nv_bfloat16* __restrict__ L4)
{
    int w = blockIdx.y;
    const float* W = (w == 0) ? W0 : (w == 1) ? W1 : (w == 2) ? W2 : (w == 3) ? W3 : W4;
    __nv_bfloat16* H = (w == 0) ? H0 : (w == 1) ? H1 : (w == 2) ? H2 : (w == 3) ? H3 : H4;
    __nv_bfloat16* L = (w == 0) ? L0 : (w == 1) ? L1 : (w == 2) ? L2 : (w == 3) ? L3 : L4;
    int i = blockIdx.x * 256 + threadIdx.x;
    float v = W[i];
    __nv_bfloat16 h = __float2bfloat16(v);
    H[i] = h;
    L[i] = __float2bfloat16(v - __bfloat162float(h));
}

// ---------------------------------------------------------------------------
// Decay weight transpose + pad + split.
// y=0: tdw1 (512,64) -> t1 (128,512), rows 64..127 zero.
// y=1: tdw2 (64,512) -> t2 (512,64).
// ---------------------------------------------------------------------------
__global__ void convtd_kernel(const float* __restrict__ tdw1, const float* __restrict__ tdw2,
                              __nv_bfloat16* __restrict__ t1h, __nv_bfloat16* __restrict__ t1l,
                              __nv_bfloat16* __restrict__ t2h, __nv_bfloat16* __restrict__ t2l)
{
    int i = blockIdx.x * 256 + threadIdx.x;
    if (blockIdx.y == 0) {
        if (i < 128 * 512) {
            int n = i >> 9, k = i & 511;
            float v = (n < 64) ? tdw1[(size_t)k * 64 + n] : 0.f;
            wsplit(v, t1h, t1l, i);
        }
    } else {
        if (i < 512 * 64) {
            int n = i >> 6, k = i & 63;
            float v = tdw2[(size_t)k * 512 + n];
            wsplit(v, t2h, t2l, i);
        }
    }
}

// ---------------------------------------------------------------------------
// Chunked WKV, kernel 1: per-chunk local scan. (unchanged from R9)
// ---------------------------------------------------------------------------
__global__ void __launch_bounds__(256) wkv_chunk_kernel(
    const float* __restrict__ r, const float* __restrict__ k,
    const float* __restrict__ v, const float* __restrict__ d,
    const float* __restrict__ u,
    float* __restrict__ ylocal, float* __restrict__ Aout,
    float* __restrict__ Lout, float* __restrict__ Pout)
{
    int wid = threadIdx.x >> 5, lane = threadIdx.x & 31;
    int cid = blockIdx.x * 8 + wid;
    int bh = cid >> 4, ch = cid & (NCH - 1);
    int b = bh >> 4, h = bh & (HH - 1);
    size_t base = ((size_t)b * TT + (size_t)ch * CHL) * CC + h * HSZ + lane;

    __shared__ float srkd[8][3][32];

    float S[32];
    #pragma unroll
    for (int j = 0; j < 32; ++j) S[j] = 0.f;
    float P = 1.f;
    float ul = u[h * HSZ + lane];

    size_t off = base;
    float rl = r[off], kl = k[off], dl = d[off], vl = v[off];

    for (int t = 0; t < CHL; ++t) {
        int tn = (t + 1 < CHL) ? (t + 1) : t;
        size_t offn = base + (size_t)tn * CC;
        float rn = r[offn], kn = k[offn], dn = d[offn], vn = v[offn];

        Aout[off] = rl * P;
        P *= dl;

        srkd[wid][0][lane] = rl;
        srkd[wid][1][lane] = kl;
        srkd[wid][2][lane] = dl;
        __syncwarp();

        float cp = rl * ul * kl;
        #pragma unroll
        for (int o = 16; o; o >>= 1) cp += __shfl_xor_sync(0xffffffffu, cp, o);

        float y0 = 0.f, y1 = 0.f, y2 = 0.f, y3 = 0.f;
        #pragma unroll
        for (int j4 = 0; j4 < 8; ++j4) {
            float4 r4 = *reinterpret_cast<const float4*>(&srkd[wid][0][j4 * 4]);
            float4 k4 = *reinterpret_cast<const float4*>(&srkd[wid][1][j4 * 4]);
            float4 d4 = *reinterpret_cast<const float4*>(&srkd[wid][2][j4 * 4]);
            y0 = fmaf(r4.x, S[j4*4+0], y0); S[j4*4+0] = fmaf(d4.x, S[j4*4+0], k4.x * vl);
            y1 = fmaf(r4.y, S[j4*4+1], y1); S[j4*4+1] = fmaf(d4.y, S[j4*4+1], k4.y * vl);
            y2 = fmaf(r4.z, S[j4*4+2], y2); S[j4*4+2] = fmaf(d4.z, S[j4*4+2], k4.z * vl);
            y3 = fmaf(r4.w, S[j4*4+3], y3); S[j4*4+3] = fmaf(d4.w, S[j4*4+3], k4.w * vl);
        }
        ylocal[off] = (y0 + y1) + (y2 + y3) + cp * vl;
        __syncwarp();

        rl = rn; kl = kn; dl = dn; vl = vn;
        off += CC;
    }

    #pragma unroll
    for (int j = 0; j < 32; ++j)
        Lout[(size_t)cid * 1024 + j * 32 + lane] = S[j];
    Pout[(size_t)cid * 32 + lane] = P;
}

// ---------------------------------------------------------------------------
// Chunked WKV, kernel 2: scan chunk states across the sequence. (unchanged)
// ---------------------------------------------------------------------------
__global__ void __launch_bounds__(1024) wkv_state_scan_kernel(
    const float* __restrict__ L, const float* __restrict__ P,
    float* __restrict__ S0out)
{
    int bh = blockIdx.x;
    int e = threadIdx.x;
    int j = e >> 5;
    float s = 0.f;
    #pragma unroll
    for (int c = 0; c < NCH; ++c) {
        size_t cid = (size_t)bh * NCH + c;
        S0out[cid * 1024 + e] = s;
        s = P[cid * 32 + j] * s + L[cid * 1024 + e];
    }
}

// ---------------------------------------------------------------------------
// Chunked WKV, kernel 3 + fused groupnorm * ln * gate:
// y = ylocal (+ A.S0 for ch>0); per-(t,head) groupnorm over the 32 lanes;
// z = (yn*lnw+lnb)*gate -> bf16 hi/lo. Deletes the separate gn kernel.
// ---------------------------------------------------------------------------
__global__ void __launch_bounds__(256) wkv_apply_gn_kernel(
    const float* __restrict__ ylocal, const float* __restrict__ A,
    const float* __restrict__ S0, const float* __restrict__ gate,
    const float* __restrict__ lnw, const float* __restrict__ lnb,
    __nv_bfloat16* __restrict__ zh, __nv_bfloat16* __restrict__ zl)
{
    int cid = blockIdx.x;
    int ch = cid & (NCH - 1);
    int bh = cid >> 4;
    int b = bh >> 4, h = bh & (HH - 1);
    int wid = threadIdx.x >> 5, lane = threadIdx.x & 31;

    __shared__ float s0[1024];
    __shared__ float sa[8][32];
    if (ch != 0) {
        for (int i = threadIdx.x; i < 1024; i += 256)
            s0[i] = S0[(size_t)cid * 1024 + i];
    }
    __syncthreads();

    float lw = lnw[h * HSZ + lane];
    float lb = lnb[h * HSZ + lane];

    size_t base = ((size_t)b * TT + (size_t)ch * CHL) * CC + h * HSZ + lane;
    for (int tt = 0; tt < 16; ++tt) {
        int t = wid * 16 + tt;
        size_t off = base + (size_t)t * CC;
        float yv = ylocal[off];
        if (ch != 0) {
            sa[wid][lane] = A[off];
            __syncwarp();
            float acc = 0.f;
            #pragma unroll
            for (int j4 = 0; j4 < 8; ++j4) {
                float4 a4 = *reinterpret_cast<const float4*>(&sa[wid][j4 * 4]);
                acc = fmaf(a4.x, s0[(j4*4+0)*32 + lane], acc);
                acc = fmaf(a4.y, s0[(j4*4+1)*32 + lane], acc);
                acc = fmaf(a4.z, s0[(j4*4+2)*32 + lane], acc);
                acc = fmaf(a4.w, s0[(j4*4+3)*32 + lane], acc);
            }
            yv += acc;
            __syncwarp();
        }
        // groupnorm over the 32 head channels (lanes)
        float s = yv;
        #pragma unroll
        for (int o = 16; o; o >>= 1) s += __shfl_xor_sync(0xffffffffu, s, o);
        float mu = s * (1.f / 32.f);
        float dv = yv - mu;
        float q = dv * dv;
        #pragma unroll
        for (int o = 16; o; o >>= 1) q += __shfl_xor_sync(0xffffffffu, q, o);
        float yn = dv * rsqrtf(q * (1.f / 32.f) + 1e-5f);
        float z = (yn * lw + lb) * gate[off];
        wsplit(z, zh, zl, off);
    }
}

// ---------------------------------------------------------------------------
extern "C" void kernel_launch(void* const* d_in, const int* in_sizes, int n_in,
                              void* d_out, int out_size) {
    const float* x      = (const float*)d_in[0];
    const float* tmaa_x = (const float*)d_in[1];
    const float* tmaa_w = (const float*)d_in[2];
    const float* tmaa_k = (const float*)d_in[3];
    const float* tmaa_v = (const float*)d_in[4];
    const float* tmaa_r = (const float*)d_in[5];
    const float* tmaa_g = (const float*)d_in[6];
    const float* w1     = (const float*)d_in[7];   // (C,160)
    const float* w2     = (const float*)d_in[8];   // (5,32,C)
    const float* tdecay = (const float*)d_in[9];   // (C,)
    const float* tdw1   = (const float*)d_in[10];  // (C,64)
    const float* tdw2   = (const float*)d_in[11];  // (64,C)
    const float* faaaa  = (const float*)d_in[12];  // (H,HS)
    const float* Wr     = (const float*)d_in[13];
    const float* Wk     = (const float*)d_in[14];
    const float* Wv     = (const float*)d_in[15];
    const float* Wg     = (const float*)d_in[16];
    const float* Wo     = (const float*)d_in[17];
    const float* lnw    = (const float*)d_in[18];
    const float* lnb    = (const float*)d_in[19];
    float* out = (float*)d_out;

    unsigned char* S;
    cudaGetSymbolAddress((void**)&S, g_scratch);
    float* mixb = (float*)(S + O_MIX);
    float* db   = (float*)(S + O_DB);
    float* rb   = (float*)(S + O_RB);
    float* kb   = (float*)(S + O_KB);
    float* vb   = (float*)(S + O_VB);
    float* gb   = (float*)(S + O_GB);
    float* yb   = (float*)(S + O_YB);
    float* ab   = (float*)(S + O_AB);
    float* lb   = (float*)(S + O_LB);
    float* pb   = (float*)(S + O_PB);
    float* s0b  = (float*)(S + O_S0);
    __nv_bfloat16* xwh = (__nv_bfloat16*)(S + O_XWH);
    __nv_bfloat16* xwl = (__nv_bfloat16*)(S + O_XWL);
    __nv_bfloat16* w64h = (__nv_bfloat16*)(S + O_W64H);
    __nv_bfloat16* w64l = (__nv_bfloat16*)(S + O_W64L);
    __nv_bfloat16* kh = (__nv_bfloat16*)(S + O_KH);
    __nv_bfloat16* kl = (__nv_bfloat16*)(S + O_KL);
    __nv_bfloat16* vh = (__nv_bfloat16*)(S + O_VH);
    __nv_bfloat16* vl = (__nv_bfloat16*)(S + O_VL);
    __nv_bfloat16* rh = (__nv_bfloat16*)(S + O_RH);
    __nv_bfloat16* rl = (__nv_bfloat16*)(S + O_RL);
    __nv_bfloat16* gh = (__nv_bfloat16*)(S + O_GH);
    __nv_bfloat16* gl = (__nv_bfloat16*)(S + O_GL);
    __nv_bfloat16* zh = (__nv_bfloat16*)(S + O_ZH);
    __nv_bfloat16* zl = (__nv_bfloat16*)(S + O_ZL);
    __nv_bfloat16* wrh = (__nv_bfloat16*)(S + O_WRH);
    __nv_bfloat16* wrl = (__nv_bfloat16*)(S + O_WRL);
    __nv_bfloat16* wkh = (__nv_bfloat16*)(S + O_WKH);
    __nv_bfloat16* wkl = (__nv_bfloat16*)(S + O_WKL);
    __nv_bfloat16* wvh = (__nv_bfloat16*)(S + O_WVH);
    __nv_bfloat16* wvl = (__nv_bfloat16*)(S + O_WVL);
    __nv_bfloat16* wgh = (__nv_bfloat16*)(S + O_WGH);
    __nv_bfloat16* wgl = (__nv_bfloat16*)(S + O_WGL);
    __nv_bfloat16* woh = (__nv_bfloat16*)(S + O_WOH);
    __nv_bfloat16* wol = (__nv_bfloat16*)(S + O_WOL);
    __nv_bfloat16* t1h = (__nv_bfloat16*)(S + O_T1H);
    __nv_bfloat16* t1l = (__nv_bfloat16*)(S + O_T1L);
    __nv_bfloat16* t2h = (__nv_bfloat16*)(S + O_T2H);
    __nv_bfloat16* t2l = (__nv_bfloat16*)(S + O_T2L);

    cudaFuncSetAttribute(tgemm_kernel<true, 0>, cudaFuncAttributeMaxDynamicSharedMemorySize, TG_SMEM);
    cudaFuncSetAttribute(tgemm_kernel<false, 0>, cudaFuncAttributeMaxDynamicSharedMemorySize, TG_SMEM);
    cudaFuncSetAttribute(tgemm2_kernel<16, 1, true>, cudaFuncAttributeMaxDynamicSharedMemorySize, TG_SMEM);
    cudaFuncSetAttribute(tgemm2_kernel<2, 3, false>, cudaFuncAttributeMaxDynamicSharedMemorySize, TG_SMEM);

    // 0) weight splits
    convw_all_kernel<<<dim3(1024, 5), 256>>>(Wr, Wk, Wv, Wg, Wo,
                                             wrh, wrl, wkh, wkl, wvh, wvl,
                                             wgh, wgl, woh, wol);
    convtd_kernel<<<dim3(256, 2), 256>>>(tdw1, tdw2, t1h, t1l, t2h, t2l);

    // 1) mix = tanh((x + (shift(x)-x)*maa_x) @ w1)   [BT,160], prep fused
    sgemm_kernel<false, 1, true><<<dim3(3, BT / 64), 256>>>(
        x, w1, mixb, nullptr, tmaa_x, BT, 160, CC);

    // 2) 5-way mix back-projection + token mixing
    mix_combine_kernel<<<BT / 16, 512>>>(x, mixb, w2, tmaa_w, tmaa_k, tmaa_v,
                                         tmaa_r, tmaa_g, xwh, xwl, kh, kl,
                                         vh, vl, rh, rl, gh, gl);

    // 3) 4 projections in ONE batched tensor-core launch (z==3 (g) = silu)
    {
        TGBatch bt_{};
        bt_.ah[0] = rh; bt_.al[0] = rl; bt_.bh[0] = wrh; bt_.bl[0] = wrl; bt_.c[0] = rb;
        bt_.ah[1] = kh; bt_.al[1] = kl; bt_.bh[1] = wkh; bt_.bl[1] = wkl; bt_.c[1] = kb;
        bt_.ah[2] = vh; bt_.al[2] = vl; bt_.bh[2] = wvh; bt_.bl[2] = wvl; bt_.c[2] = vb;
        bt_.ah[3] = gh; bt_.al[3] = gl; bt_.bh[3] = wgh; bt_.bl[3] = wgl; bt_.c[3] = gb;
        tgemm_kernel<true, 0><<<dim3(4, BT / 128, 4), 256, TG_SMEM>>>(
            bt_, nullptr, nullptr, nullptr, nullptr, nullptr);
    }

    // 4) decay MLP on tensor cores:
    //    w64 = tanh(xw @ tdw1)  [N=64, K=512], split-out bf16
    tgemm2_kernel<16, 1, true><<<dim3(1, BT / 128), 256, TG_SMEM>>>(
        xwh, xwl, t1h, t1l, nullptr, w64h, w64l, nullptr, 64);
    //    d = exp(-exp(tdecay + w64 @ tdw2))  [N=512, K=64]
    tgemm2_kernel<2, 3, false><<<dim3(4, BT / 128), 256, TG_SMEM>>>(
        w64h, w64l, t2h, t2l, db, nullptr, nullptr, tdecay, 512);

    // 5) WKV6 chunked scan: local scans -> state scan -> correction + gn fused
    wkv_chunk_kernel<<<NCID / 8, 256>>>(rb, kb, vb, db, faaaa, yb, ab, lb, pb);
    wkv_state_scan_kernel<<<BQ * HH, 1024>>>(lb, pb, s0b);
    wkv_apply_gn_kernel<<<NCID, 256>>>(yb, ab, s0b, gb, lnw, lnb, zh, zl);

    // 6) out = z @ Wo^T (tensor cores)
    {
        TGBatch dummy{};
        tgemm_kernel<false, 0><<<dim3(4, BT / 128), 256, TG_SMEM>>>(
            dummy, zh, zl, woh, wol, out);
    }
}

// round 11
// speedup vs baseline: 2.5314x; 1.0793x over previous
#include <cuda_runtime.h>
#include <cuda_bf16.h>
#include <cstdint>

#define BQ 8
#define TT 2048
#define CC 512
#define HH 16
#define HSZ 32
#define BT (BQ*TT)            // 16384
#define UEL ((size_t)BT*CC)   // 8388608 elements per [B,T,C] buffer
#define NCH 16                // chunks per sequence
#define CHL 128               // chunk length (TT/NCH)
#define NCID (BQ*HH*NCH)      // 2048 total chunks

// ---------------------------------------------------------------------------
// Scratch (bytes). One big device array; no allocations anywhere.
// ---------------------------------------------------------------------------
#define SZ_F32   (UEL*4)
#define SZ_BF16  (UEL*2)
#define SZ_MIX   ((size_t)BT*160*4)
#define SZ_W64B  ((size_t)BT*64*2)
#define SZ_WBF   ((size_t)CC*CC*2)
#define SZ_L     ((size_t)NCID*1024*4)
#define SZ_P     ((size_t)NCID*32*4)

#define O_MIX   ((size_t)0)
#define O_XWH   (O_MIX + SZ_MIX)
#define O_XWL   (O_XWH + SZ_BF16)
#define O_W64H  (O_XWL + SZ_BF16)
#define O_W64L  (O_W64H + SZ_W64B)
#define O_DB    (O_W64L + SZ_W64B)
#define O_RB    (O_DB + SZ_F32)
#define O_KB    (O_RB + SZ_F32)
#define O_VB    (O_KB + SZ_F32)
#define O_GB    (O_VB + SZ_F32)
#define O_YB    (O_GB + SZ_F32)
#define O_AB    (O_YB + SZ_F32)
#define O_LB    (O_AB + SZ_F32)
#define O_PB    (O_LB + SZ_L)
#define O_S0    (O_PB + SZ_P)
#define O_KH    (O_S0 + SZ_L)
#define O_KL    (O_KH + SZ_BF16)
#define O_VH    (O_KL + SZ_BF16)
#define O_VL    (O_VH + SZ_BF16)
#define O_RH    (O_VL + SZ_BF16)
#define O_RL    (O_RH + SZ_BF16)
#define O_GH    (O_RL + SZ_BF16)
#define O_GL    (O_GH + SZ_BF16)
#define O_ZH    (O_GL + SZ_BF16)
#define O_ZL    (O_ZH + SZ_BF16)
#define O_XXH   (O_ZL + SZ_BF16)
#define O_XXL   (O_XXH + SZ_BF16)
#define O_WRH   (O_XXL + SZ_BF16)
#define O_WRL   (O_WRH + SZ_WBF)
#define O_WKH   (O_WRL + SZ_WBF)
#define O_WKL   (O_WKH + SZ_WBF)
#define O_WVH   (O_WKL + SZ_WBF)
#define O_WVL   (O_WVH + SZ_WBF)
#define O_WGH   (O_WVL + SZ_WBF)
#define O_WGL   (O_WGH + SZ_WBF)
#define O_WOH   (O_WGL + SZ_WBF)
#define O_WOL   (O_WOH + SZ_WBF)
#define O_T1H   (O_WOL + SZ_WBF)                 // tdw1^T padded: 128x512 bf16
#define O_T1L   (O_T1H + (size_t)128*512*2)
#define O_T2H   (O_T1L + (size_t)128*512*2)      // tdw2^T: 512x64 bf16
#define O_T2L   (O_T2H + (size_t)512*64*2)
#define O_M1H   (O_T2L + (size_t)512*64*2)       // w1^T padded: 256x512 bf16
#define O_M1L   (O_M1H + (size_t)256*512*2)
#define SCRATCH_BYTES (O_M1L + (size_t)256*512*2)

__device__ __align__(256) unsigned char g_scratch[SCRATCH_BYTES];

// ---------------------------------------------------------------------------
// mma.sync / cp.async helpers (valid on plain compute_103 / sm_80+)
// ---------------------------------------------------------------------------
__device__ __forceinline__ uint32_t smem_u32(const void* p) {
    uint32_t a;
    asm("{ .reg .u64 t; cvta.to.shared.u64 t, %1; cvt.u32.u64 %0, t; }"
        : "=r"(a) : "l"(p));
    return a;
}

#define LDSM4(r, a) \
    asm volatile("ldmatrix.sync.aligned.m8n8.x4.shared.b16 {%0,%1,%2,%3}, [%4];" \
        : "=r"((r)[0]), "=r"((r)[1]), "=r"((r)[2]), "=r"((r)[3]) : "r"(a))

#define MMA16816(d, a, b0, b1) \
    asm volatile("mma.sync.aligned.m16n8k16.row.col.f32.bf16.bf16.f32 " \
        "{%0,%1,%2,%3}, {%4,%5,%6,%7}, {%8,%9}, {%0,%1,%2,%3};" \
        : "+f"((d)[0]), "+f"((d)[1]), "+f"((d)[2]), "+f"((d)[3]) \
        : "r"((a)[0]), "r"((a)[1]), "r"((a)[2]), "r"((a)[3]), "r"(b0), "r"(b1))

#define CP_ASYNC16(dst, src) \
    asm volatile("cp.async.cg.shared.global [%0], [%1], 16;" :: "r"(dst), "l"(src))
#define CP_COMMIT() asm volatile("cp.async.commit_group;" ::: "memory")
#define CP_WAIT(n)  asm volatile("cp.async.wait_group %0;" :: "n"(n) : "memory")

#define TROWB 80
#define TTILE (128*TROWB)     // 10240
#define TSTAGE (4*TTILE)      // 40960
#define TG_SMEM (2*TSTAGE)    // 81920
#define ROWSKIP (64*1024)     // 64 rows * 512 cols * 2B (K=512 path)
#define DSTSKIP (64*TROWB)

// ---------------------------------------------------------------------------
// split helper
// ---------------------------------------------------------------------------
__device__ __forceinline__ void wsplit(float v, __nv_bfloat16* hi, __nv_bfloat16* lo, size_t i) {
    __nv_bfloat16 h = __float2bfloat16(v);
    hi[i] = h;
    lo[i] = __float2bfloat16(v - __bfloat162float(h));
}

// ---------------------------------------------------------------------------
// Pipelined tensor-core GEMM (hot path, K=512, N=512): unchanged.
// ---------------------------------------------------------------------------
struct TGBatch {
    const __nv_bfloat16 *ah[4], *al[4], *bh[4], *bl[4];
    float* c[4];
};

template<bool BATCH, int EPI>
__global__ void __launch_bounds__(256, 2)
tgemm_kernel(TGBatch bt_,
             const __nv_bfloat16* __restrict__ Ah_, const __nv_bfloat16* __restrict__ Al_,
             const __nv_bfloat16* __restrict__ Bh_, const __nv_bfloat16* __restrict__ Bl_,
             float* __restrict__ C_)
{
    extern __shared__ unsigned char sm[];
    uint32_t smb = smem_u32(sm);
    int tid = threadIdx.x;
    int wid = tid >> 5, lane = tid & 31;
    int bm = blockIdx.y * 128, bn = blockIdx.x * 128;
    int wm = (wid & 3) * 32, wn = (wid >> 2) * 64;

    int z = BATCH ? blockIdx.z : 0;
    const __nv_bfloat16* Ah = BATCH ? bt_.ah[z] : Ah_;
    const __nv_bfloat16* Al = BATCH ? bt_.al[z] : Al_;
    const __nv_bfloat16* Bh = BATCH ? bt_.bh[z] : Bh_;
    const __nv_bfloat16* Bl = BATCH ? bt_.bl[z] : Bl_;
    float* C = BATCH ? bt_.c[z] : C_;
    bool do_silu = BATCH ? (z == 3) : (EPI == 2);

    int rowq = tid >> 2;
    int gcol = (tid & 3) * 8;
    const char* pAh = (const char*)(Ah + (size_t)(bm + rowq) * 512 + gcol);
    const char* pAl = (const char*)(Al + (size_t)(bm + rowq) * 512 + gcol);
    const char* pBh = (const char*)(Bh + (size_t)(bn + rowq) * 512 + gcol);
    const char* pBl = (const char*)(Bl + (size_t)(bn + rowq) * 512 + gcol);
    uint32_t dA = smb + rowq * TROWB + (tid & 3) * 16;
    uint32_t dB = dA + 2 * TTILE;

    float acc[2][8][4];
    #pragma unroll
    for (int i = 0; i < 2; ++i)
        #pragma unroll
        for (int j = 0; j < 8; ++j)
            #pragma unroll
            for (int q = 0; q < 4; ++q) acc[i][j][q] = 0.f;

    int mat = lane >> 3, r8 = lane & 7;
    int lrow = (mat & 1) * 8 + r8;
    int lkb  = (mat >> 1) * 16;
    uint32_t raBase = smb + (wm + lrow) * TROWB + lkb;
    uint32_t rbBase = smb + 2 * TTILE + (wn + lrow) * TROWB + lkb;

    {
        CP_ASYNC16(dA,                    pAh);
        CP_ASYNC16(dA + DSTSKIP,          pAh + ROWSKIP);
        CP_ASYNC16(dA + TTILE,            pAl);
        CP_ASYNC16(dA + TTILE + DSTSKIP,  pAl + ROWSKIP);
        CP_ASYNC16(dB,                    pBh);
        CP_ASYNC16(dB + DSTSKIP,          pBh + ROWSKIP);
        CP_ASYNC16(dB + TTILE,            pBl);
        CP_ASYNC16(dB + TTILE + DSTSKIP,  pBl + ROWSKIP);
        pAh += 64; pAl += 64; pBh += 64; pBl += 64;
        CP_COMMIT();
    }

    for (int ch = 0; ch < 16; ++ch) {
        if (ch + 1 < 16) {
            uint32_t so = ((ch + 1) & 1) * TSTAGE;
            CP_ASYNC16(dA + so,                    pAh);
            CP_ASYNC16(dA + so + DSTSKIP,          pAh + ROWSKIP);
            CP_ASYNC16(dA + so + TTILE,            pAl);
            CP_ASYNC16(dA + so + TTILE + DSTSKIP,  pAl + ROWSKIP);
            CP_ASYNC16(dB + so,                    pBh);
            CP_ASYNC16(dB + so + DSTSKIP,          pBh + ROWSKIP);
            CP_ASYNC16(dB + so + TTILE,            pBl);
            CP_ASYNC16(dB + so + TTILE + DSTSKIP,  pBl + ROWSKIP);
            pAh += 64; pAl += 64; pBh += 64; pBl += 64;
            CP_COMMIT();
            CP_WAIT(1);
        } else {
            CP_WAIT(0);
        }
        __syncthreads();

        uint32_t so = (ch & 1) * TSTAGE;
        uint32_t ra0 = raBase + so;
        uint32_t rb0 = rbBase + so;
        #pragma unroll
        for (int ks = 0; ks < 2; ++ks) {
            uint32_t ah[2][4], al[2][4];
            #pragma unroll
            for (int mt = 0; mt < 2; ++mt) {
                uint32_t ra = ra0 + mt * (16 * TROWB) + ks * 32;
                LDSM4(ah[mt], ra);
                LDSM4(al[mt], ra + TTILE);
            }
            #pragma unroll
            for (int nt = 0; nt < 4; ++nt) {
                uint32_t rb = rb0 + nt * (16 * TROWB) + ks * 32;
                uint32_t bh4[4], bl4[4];
                LDSM4(bh4, rb);
                LDSM4(bl4, rb + TTILE);
                #pragma unroll
                for (int mt = 0; mt < 2; ++mt) {
                    MMA16816(acc[mt][nt*2+0], ah[mt], bh4[0], bh4[2]);
                    MMA16816(acc[mt][nt*2+1], ah[mt], bh4[1], bh4[3]);
                    MMA16816(acc[mt][nt*2+0], ah[mt], bl4[0], bl4[2]);
                    MMA16816(acc[mt][nt*2+1], ah[mt], bl4[1], bl4[3]);
                    MMA16816(acc[mt][nt*2+0], al[mt], bh4[0], bh4[2]);
                    MMA16816(acc[mt][nt*2+1], al[mt], bh4[1], bh4[3]);
                }
            }
        }
        __syncthreads();
    }

    int r0 = lane >> 2, c0 = (lane & 3) * 2;
    #pragma unroll
    for (int mt = 0; mt < 2; ++mt) {
        #pragma unroll
        for (int nt = 0; nt < 4; ++nt) {
            #pragma unroll
            for (int s = 0; s < 2; ++s) {
                float* a4 = acc[mt][nt*2+s];
                int col = bn + wn + nt * 16 + s * 8 + c0;
                int row = bm + wm + mt * 16 + r0;
                float v0 = a4[0], v1 = a4[1], v2 = a4[2], v3 = a4[3];
                if (do_silu) {
                    v0 = v0 / (1.f + __expf(-v0));
                    v1 = v1 / (1.f + __expf(-v1));
                    v2 = v2 / (1.f + __expf(-v2));
                    v3 = v3 / (1.f + __expf(-v3));
                }
                *reinterpret_cast<float2*>(C + (size_t)row * 512 + col)       = make_float2(v0, v1);
                *reinterpret_cast<float2*>(C + (size_t)(row + 8) * 512 + col) = make_float2(v2, v3);
            }
        }
    }
}

// ---------------------------------------------------------------------------
// Parameterized tensor GEMM (decay MLP + mix GEMM).
// NK = K/32 chunks. EPI: 1 tanh, 3 exp(-exp(bias+v)). SPLITOUT: bf16 hi/lo out.
// A pitch = K, B pitch = K (B padded to >=128*gridDim.x rows), C pitch = N.
// ---------------------------------------------------------------------------
template<int NK, int EPI, bool SPLITOUT>
__global__ void __launch_bounds__(256, 2)
tgemm2_kernel(const __nv_bfloat16* __restrict__ Ah, const __nv_bfloat16* __restrict__ Al,
              const __nv_bfloat16* __restrict__ Bh, const __nv_bfloat16* __restrict__ Bl,
              float* __restrict__ Cf,
              __nv_bfloat16* __restrict__ Chi, __nv_bfloat16* __restrict__ Clo,
              const float* __restrict__ bias, int N)
{
    constexpr int K = NK * 32;
    constexpr int RSKIP = 64 * K * 2;
    extern __shared__ unsigned char sm[];
    uint32_t smb = smem_u32(sm);
    int tid = threadIdx.x;
    int wid = tid >> 5, lane = tid & 31;
    int bm = blockIdx.y * 128, bn = blockIdx.x * 128;
    int wm = (wid & 3) * 32, wn = (wid >> 2) * 64;

    int rowq = tid >> 2;
    int gcol = (tid & 3) * 8;
    const char* pAh = (const char*)(Ah + (size_t)(bm + rowq) * K + gcol);
    const char* pAl = (const char*)(Al + (size_t)(bm + rowq) * K + gcol);
    const char* pBh = (const char*)(Bh + (size_t)(bn + rowq) * K + gcol);
    const char* pBl = (const char*)(Bl + (size_t)(bn + rowq) * K + gcol);
    uint32_t dA = smb + rowq * TROWB + (tid & 3) * 16;
    uint32_t dB = dA + 2 * TTILE;

    float acc[2][8][4];
    #pragma unroll
    for (int i = 0; i < 2; ++i)
        #pragma unroll
        for (int j = 0; j < 8; ++j)
            #pragma unroll
            for (int q = 0; q < 4; ++q) acc[i][j][q] = 0.f;

    int mat = lane >> 3, r8 = lane & 7;
    int lrow = (mat & 1) * 8 + r8;
    int lkb  = (mat >> 1) * 16;
    uint32_t raBase = smb + (wm + lrow) * TROWB + lkb;
    uint32_t rbBase = smb + 2 * TTILE + (wn + lrow) * TROWB + lkb;

    {
        CP_ASYNC16(dA,                   pAh);
        CP_ASYNC16(dA + DSTSKIP,         pAh + RSKIP);
        CP_ASYNC16(dA + TTILE,           pAl);
        CP_ASYNC16(dA + TTILE + DSTSKIP, pAl + RSKIP);
        CP_ASYNC16(dB,                   pBh);
        CP_ASYNC16(dB + DSTSKIP,         pBh + RSKIP);
        CP_ASYNC16(dB + TTILE,           pBl);
        CP_ASYNC16(dB + TTILE + DSTSKIP, pBl + RSKIP);
        pAh += 64; pAl += 64; pBh += 64; pBl += 64;
        CP_COMMIT();
    }

    for (int ch = 0; ch < NK; ++ch) {
        if (ch + 1 < NK) {
            uint32_t so = ((ch + 1) & 1) * TSTAGE;
            CP_ASYNC16(dA + so,                   pAh);
            CP_ASYNC16(dA + so + DSTSKIP,         pAh + RSKIP);
            CP_ASYNC16(dA + so + TTILE,           pAl);
            CP_ASYNC16(dA + so + TTILE + DSTSKIP, pAl + RSKIP);
            CP_ASYNC16(dB + so,                   pBh);
            CP_ASYNC16(dB + so + DSTSKIP,         pBh + RSKIP);
            CP_ASYNC16(dB + so + TTILE,           pBl);
            CP_ASYNC16(dB + so + TTILE + DSTSKIP, pBl + RSKIP);
            pAh += 64; pAl += 64; pBh += 64; pBl += 64;
            CP_COMMIT();
            CP_WAIT(1);
        } else {
            CP_WAIT(0);
        }
        __syncthreads();

        uint32_t so = (ch & 1) * TSTAGE;
        uint32_t ra0 = raBase + so;
        uint32_t rb0 = rbBase + so;
        #pragma unroll
        for (int ks = 0; ks < 2; ++ks) {
            uint32_t ah[2][4], al[2][4];
            #pragma unroll
            for (int mt = 0; mt < 2; ++mt) {
                uint32_t ra = ra0 + mt * (16 * TROWB) + ks * 32;
                LDSM4(ah[mt], ra);
                LDSM4(al[mt], ra + TTILE);
            }
            #pragma unroll
            for (int nt = 0; nt < 4; ++nt) {
                uint32_t rb = rb0 + nt * (16 * TROWB) + ks * 32;
                uint32_t bh4[4], bl4[4];
                LDSM4(bh4, rb);
                LDSM4(bl4, rb + TTILE);
                #pragma unroll
                for (int mt = 0; mt < 2; ++mt) {
                    MMA16816(acc[mt][nt*2+0], ah[mt], bh4[0], bh4[2]);
                    MMA16816(acc[mt][nt*2+1], ah[mt], bh4[1], bh4[3]);
                    MMA16816(acc[mt][nt*2+0], ah[mt], bl4[0], bl4[2]);
                    MMA16816(acc[mt][nt*2+1], ah[mt], bl4[1], bl4[3]);
                    MMA16816(acc[mt][nt*2+0], al[mt], bh4[0], bh4[2]);
                    MMA16816(acc[mt][nt*2+1], al[mt], bh4[1], bh4[3]);
                }
            }
        }
        __syncthreads();
    }

    int r0 = lane >> 2, c0 = (lane & 3) * 2;
    #pragma unroll
    for (int mt = 0; mt < 2; ++mt) {
        #pragma unroll
        for (int nt = 0; nt < 4; ++nt) {
            #pragma unroll
            for (int s = 0; s < 2; ++s) {
                float* a4 = acc[mt][nt*2+s];
                int col = bn + wn + nt * 16 + s * 8 + c0;
                if (col >= N) continue;
                int row = bm + wm + mt * 16 + r0;
                #pragma unroll
                for (int half = 0; half < 2; ++half) {
                    float v0 = a4[half * 2 + 0], v1 = a4[half * 2 + 1];
                    size_t ro = (size_t)(row + half * 8) * N + col;
                    if (EPI == 1) { v0 = tanhf(v0); v1 = tanhf(v1); }
                    else if (EPI == 3) {
                        v0 = __expf(-__expf(bias[col] + v0));
                        v1 = __expf(-__expf(bias[col + 1] + v1));
                    }
                    if (SPLITOUT) {
                        wsplit(v0, Chi, Clo, ro);
                        wsplit(v1, Chi, Clo, ro + 1);
                    } else {
                        *reinterpret_cast<float2*>(Cf + ro) = make_float2(v0, v1);
                    }
                }
            }
        }
    }
}

// ---------------------------------------------------------------------------
// prep: xxx = x + (xshift - x) * maa_x  -> bf16 hi/lo
// ---------------------------------------------------------------------------
__global__ void __launch_bounds__(256) prep_split_kernel(
    const float* __restrict__ x, const float* __restrict__ tmx,
    __nv_bfloat16* __restrict__ xxh, __nv_bfloat16* __restrict__ xxl)
{
    size_t i = (size_t)blockIdx.x * 256 + threadIdx.x;
    int c = (int)(i & (CC - 1));
    int t = (int)((i >> 9) & (TT - 1));
    float xv = x[i];
    float xp = (t > 0) ? x[i - CC] : 0.f;
    wsplit(fmaf(xp - xv, tmx[c], xv), xxh, xxl, i);
}

// ---------------------------------------------------------------------------
// mix back-projection + 5-way token mix. Block = 16 bt rows x 512 c.
// ---------------------------------------------------------------------------
__global__ void __launch_bounds__(512) mix_combine_kernel(
    const float* __restrict__ x, const float* __restrict__ mix,
    const float* __restrict__ W2,
    const float* __restrict__ maaw, const float* __restrict__ maak,
    const float* __restrict__ maav, const float* __restrict__ maar,
    const float* __restrict__ maag,
    __nv_bfloat16* __restrict__ xwh, __nv_bfloat16* __restrict__ xwl,
    __nv_bfloat16* __restrict__ kh, __nv_bfloat16* __restrict__ kl,
    __nv_bfloat16* __restrict__ vh, __nv_bfloat16* __restrict__ vl,
    __nv_bfloat16* __restrict__ rh, __nv_bfloat16* __restrict__ rl,
    __nv_bfloat16* __restrict__ gh, __nv_bfloat16* __restrict__ gl)
{
    __shared__ float s_mix[16][160];
    __shared__ float s_x[16][512];
    __shared__ float s_xp0[512];
    int bt0 = blockIdx.x * 16;
    int c = threadIdx.x;

    for (int i = threadIdx.x; i < 16 * 160; i += 512)
        s_mix[i / 160][i % 160] = mix[(size_t)bt0 * 160 + i];
    #pragma unroll
    for (int row = 0; row < 16; ++row)
        s_x[row][c] = x[(size_t)(bt0 + row) * 512 + c];
    s_xp0[c] = (bt0 & (TT - 1)) ? x[(size_t)(bt0 - 1) * 512 + c] : 0.f;
    __syncthreads();

    float maa[5];
    maa[0] = maaw[c]; maa[1] = maak[c]; maa[2] = maav[c];
    maa[3] = maar[c]; maa[4] = maag[c];

    #pragma unroll
    for (int f = 0; f < 5; ++f) {
        float acc[16];
        #pragma unroll
        for (int row = 0; row < 16; ++row) acc[row] = 0.f;
        #pragma unroll 8
        for (int dd = 0; dd < 32; ++dd) {
            float w = W2[(size_t)(f * 32 + dd) * 512 + c];
            #pragma unroll
            for (int row = 0; row < 16; ++row)
                acc[row] = fmaf(s_mix[row][f * 32 + dd], w, acc[row]);
        }
        #pragma unroll
        for (int row = 0; row < 16; ++row) {
            size_t gi = (size_t)(bt0 + row) * 512 + c;
            float xc = s_x[row][c];
            float xp = (row > 0) ? s_x[row - 1][c] : s_xp0[c];
            float v = fmaf(xp - xc, maa[f] + acc[row], xc);
            if (f == 0)      wsplit(v, xwh, xwl, gi);
            else if (f == 1) wsplit(v, kh, kl, gi);
            else if (f == 2) wsplit(v, vh, vl, gi);
            else if (f == 3) wsplit(v, rh, rl, gi);
            else             wsplit(v, gh, gl, gi);
        }
    }
}

// ---------------------------------------------------------------------------
// All weight fp32 -> bf16 hi/lo splits in one launch (grid.y = which weight)
// ---------------------------------------------------------------------------
__global__ void convw_all_kernel(const float* __restrict__ W0, const float* __restrict__ W1,
                                 const float* __restrict__ W2, const float* __restrict__ W3,
                                 const float* __restrict__ W4,
                                 __nv_bfloat16* __restrict__ H0, __nv_bfloat16* __restrict__ L0,
                                 __nv_bfloat16* __restrict__ H1, __nv_bfloat16* __restrict__ L1,
                                 __nv_bfloat16* __restrict__ H2, __nv_bfloat16* __restrict__ L2,
                                 __nv_bfloat16* __restrict__ H3, __nv_bfloat16* __restrict__ L3,
                                 __nv_bfloat16* __restrict__ H4, __nv_bfloat16* __restrict__ L4)
{
    int w = blockIdx.y;
    const float* W = (w == 0) ? W0 : (w == 1) ? W1 : (w == 2) ? W2 : (w == 3) ? W3 : W4;
    __nv_bfloat16* H = (w == 0) ? H0 : (w == 1) ? H1 : (w == 2) ? H2 : (w == 3) ? H3 : H4;
    __nv_bfloat16* L = (w == 0) ? L0 : (w == 1) ? L1 : (w == 2) ? L2 : (w == 3) ? L3 : L4;
    int i = blockIdx.x * 256 + threadIdx.x;
    float v = W[i];
    __nv_bfloat16 h = __float2bfloat16(v);
    H[i] = h;
    L[i] = __float2bfloat16(v - __bfloat162float(h));
}

// ---------------------------------------------------------------------------
// Small-weight transpose + pad + split (decay MLP weights and mix w1).
// y=0: tdw1 (512,64) -> t1 (128,512), rows 64..127 zero.
// y=1: tdw2 (64,512) -> t2 (512,64).
// y=2..3: w1 (512,160) -> m1 (256,512), rows 160..255 zero.
// ---------------------------------------------------------------------------
__global__ void convtd_kernel(const float* __restrict__ tdw1, const float* __restrict__ tdw2,
                              const float* __restrict__ w1,
                              __nv_bfloat16* __restrict__ t1h, __nv_bfloat16* __restrict__ t1l,
                              __nv_bfloat16* __restrict__ t2h, __nv_bfloat16* __restrict__ t2l,
                              __nv_bfloat16* __restrict__ m1h, __nv_bfloat16* __restrict__ m1l)
{
    int i = blockIdx.x * 256 + threadIdx.x;
    if (blockIdx.y == 0) {
        if (i < 128 * 512) {
            int n = i >> 9, k = i & 511;
            float v = (n < 64) ? tdw1[(size_t)k * 64 + n] : 0.f;
            wsplit(v, t1h, t1l, i);
        }
    } else if (blockIdx.y == 1) {
        if (i < 512 * 64) {
            int n = i >> 6, k = i & 63;
            float v = tdw2[(size_t)k * 512 + n];
            wsplit(v, t2h, t2l, i);
        }
    } else {
        int j = (blockIdx.y - 2) * 65536 + i;
        if (j < 256 * 512) {
            int n = j >> 9, k = j & 511;
            float v = (n < 160) ? w1[(size_t)k * 160 + n] : 0.f;
            wsplit(v, m1h, m1l, j);
        }
    }
}

// ---------------------------------------------------------------------------
// Chunked WKV, kernel 1: per-chunk local scan.
// ---------------------------------------------------------------------------
__global__ void __launch_bounds__(256) wkv_chunk_kernel(
    const float* __restrict__ r, const float* __restrict__ k,
    const float* __restrict__ v, const float* __restrict__ d,
    const float* __restrict__ u,
    float* __restrict__ ylocal, float* __restrict__ Aout,
    float* __restrict__ Lout, float* __restrict__ Pout)
{
    int wid = threadIdx.x >> 5, lane = threadIdx.x & 31;
    int cid = blockIdx.x * 8 + wid;
    int bh = cid >> 4, ch = cid & (NCH - 1);
    int b = bh >> 4, h = bh & (HH - 1);
    size_t base = ((size_t)b * TT + (size_t)ch * CHL) * CC + h * HSZ + lane;

    __shared__ float srkd[8][3][32];

    float S[32];
    #pragma unroll
    for (int j = 0; j < 32; ++j) S[j] = 0.f;
    float P = 1.f;
    float ul = u[h * HSZ + lane];

    size_t off = base;
    float rl = r[off], kl = k[off], dl = d[off], vl = v[off];

    for (int t = 0; t < CHL; ++t) {
        int tn = (t + 1 < CHL) ? (t + 1) : t;
        size_t offn = base + (size_t)tn * CC;
        float rn = r[offn], kn = k[offn], dn = d[offn], vn = v[offn];

        Aout[off] = rl * P;
        P *= dl;

        srkd[wid][0][lane] = rl;
        srkd[wid][1][lane] = kl;
        srkd[wid][2][lane] = dl;
        __syncwarp();

        float cp = rl * ul * kl;
        #pragma unroll
        for (int o = 16; o; o >>= 1) cp += __shfl_xor_sync(0xffffffffu, cp, o);

        float y0 = 0.f, y1 = 0.f, y2 = 0.f, y3 = 0.f;
        #pragma unroll
        for (int j4 = 0; j4 < 8; ++j4) {
            float4 r4 = *reinterpret_cast<const float4*>(&srkd[wid][0][j4 * 4]);
            float4 k4 = *reinterpret_cast<const float4*>(&srkd[wid][1][j4 * 4]);
            float4 d4 = *reinterpret_cast<const float4*>(&srkd[wid][2][j4 * 4]);
            y0 = fmaf(r4.x, S[j4*4+0], y0); S[j4*4+0] = fmaf(d4.x, S[j4*4+0], k4.x * vl);
            y1 = fmaf(r4.y, S[j4*4+1], y1); S[j4*4+1] = fmaf(d4.y, S[j4*4+1], k4.y * vl);
            y2 = fmaf(r4.z, S[j4*4+2], y2); S[j4*4+2] = fmaf(d4.z, S[j4*4+2], k4.z * vl);
            y3 = fmaf(r4.w, S[j4*4+3], y3); S[j4*4+3] = fmaf(d4.w, S[j4*4+3], k4.w * vl);
        }
        ylocal[off] = (y0 + y1) + (y2 + y3) + cp * vl;
        __syncwarp();

        rl = rn; kl = kn; dl = dn; vl = vn;
        off += CC;
    }

    #pragma unroll
    for (int j = 0; j < 32; ++j)
        Lout[(size_t)cid * 1024 + j * 32 + lane] = S[j];
    Pout[(size_t)cid * 32 + lane] = P;
}

// ---------------------------------------------------------------------------
// Chunked WKV, kernel 2: scan chunk states across the sequence.
// ---------------------------------------------------------------------------
__global__ void __launch_bounds__(1024) wkv_state_scan_kernel(
    const float* __restrict__ L, const float* __restrict__ P,
    float* __restrict__ S0out)
{
    int bh = blockIdx.x;
    int e = threadIdx.x;
    int j = e >> 5;
    float s = 0.f;
    #pragma unroll
    for (int c = 0; c < NCH; ++c) {
        size_t cid = (size_t)bh * NCH + c;
        S0out[cid * 1024 + e] = s;
        s = P[cid * 32 + j] * s + L[cid * 1024 + e];
    }
}

// ---------------------------------------------------------------------------
// Chunked WKV, kernel 3 + fused groupnorm * ln * gate -> bf16 hi/lo.
// ---------------------------------------------------------------------------
__global__ void __launch_bounds__(256) wkv_apply_gn_kernel(
    const float* __restrict__ ylocal, const float* __restrict__ A,
    const float* __restrict__ S0, const float* __restrict__ gate,
    const float* __restrict__ lnw, const float* __restrict__ lnb,
    __nv_bfloat16* __restrict__ zh, __nv_bfloat16* __restrict__ zl)
{
    int cid = blockIdx.x;
    int ch = cid & (NCH - 1);
    int bh = cid >> 4;
    int b = bh >> 4, h = bh & (HH - 1);
    int wid = threadIdx.x >> 5, lane = threadIdx.x & 31;

    __shared__ float s0[1024];
    __shared__ float sa[8][32];
    if (ch != 0) {
        for (int i = threadIdx.x; i < 1024; i += 256)
            s0[i] = S0[(size_t)cid * 1024 + i];
    }
    __syncthreads();

    float lw = lnw[h * HSZ + lane];
    float lb = lnb[h * HSZ + lane];

    size_t base = ((size_t)b * TT + (size_t)ch * CHL) * CC + h * HSZ + lane;
    for (int tt = 0; tt < 16; ++tt) {
        int t = wid * 16 + tt;
        size_t off = base + (size_t)t * CC;
        float yv = ylocal[off];
        if (ch != 0) {
            sa[wid][lane] = A[off];
            __syncwarp();
            float acc = 0.f;
            #pragma unroll
            for (int j4 = 0; j4 < 8; ++j4) {
                float4 a4 = *reinterpret_cast<const float4*>(&sa[wid][j4 * 4]);
                acc = fmaf(a4.x, s0[(j4*4+0)*32 + lane], acc);
                acc = fmaf(a4.y, s0[(j4*4+1)*32 + lane], acc);
                acc = fmaf(a4.z, s0[(j4*4+2)*32 + lane], acc);
                acc = fmaf(a4.w, s0[(j4*4+3)*32 + lane], acc);
            }
            yv += acc;
            __syncwarp();
        }
        float s = yv;
        #pragma unroll
        for (int o = 16; o; o >>= 1) s += __shfl_xor_sync(0xffffffffu, s, o);
        float mu = s * (1.f / 32.f);
        float dv = yv - mu;
        float q = dv * dv;
        #pragma unroll
        for (int o = 16; o; o >>= 1) q += __shfl_xor_sync(0xffffffffu, q, o);
        float yn = dv * rsqrtf(q * (1.f / 32.f) + 1e-5f);
        float z = (yn * lw + lb) * gate[off];
        wsplit(z, zh, zl, off);
    }
}

// ---------------------------------------------------------------------------
extern "C" void kernel_launch(void* const* d_in, const int* in_sizes, int n_in,
                              void* d_out, int out_size) {
    const float* x      = (const float*)d_in[0];
    const float* tmaa_x = (const float*)d_in[1];
    const float* tmaa_w = (const float*)d_in[2];
    const float* tmaa_k = (const float*)d_in[3];
    const float* tmaa_v = (const float*)d_in[4];
    const float* tmaa_r = (const float*)d_in[5];
    const float* tmaa_g = (const float*)d_in[6];
    const float* w1     = (const float*)d_in[7];   // (C,160)
    const float* w2     = (const float*)d_in[8];   // (5,32,C)
    const float* tdecay = (const float*)d_in[9];   // (C,)
    const float* tdw1   = (const float*)d_in[10];  // (C,64)
    const float* tdw2   = (const float*)d_in[11];  // (64,C)
    const float* faaaa  = (const float*)d_in[12];  // (H,HS)
    const float* Wr     = (const float*)d_in[13];
    const float* Wk     = (const float*)d_in[14];
    const float* Wv     = (const float*)d_in[15];
    const float* Wg     = (const float*)d_in[16];
    const float* Wo     = (const float*)d_in[17];
    const float* lnw    = (const float*)d_in[18];
    const float* lnb    = (const float*)d_in[19];
    float* out = (float*)d_out;

    unsigned char* S;
    cudaGetSymbolAddress((void**)&S, g_scratch);
    float* mixb = (float*)(S + O_MIX);
    float* db   = (float*)(S + O_DB);
    float* rb   = (float*)(S + O_RB);
    float* kb   = (float*)(S + O_KB);
    float* vb   = (float*)(S + O_VB);
    float* gb   = (float*)(S + O_GB);
    float* yb   = (float*)(S + O_YB);
    float* ab   = (float*)(S + O_AB);
    float* lb   = (float*)(S + O_LB);
    float* pb   = (float*)(S + O_PB);
    float* s0b  = (float*)(S + O_S0);
    __nv_bfloat16* xwh = (__nv_bfloat16*)(S + O_XWH);
    __nv_bfloat16* xwl = (__nv_bfloat16*)(S + O_XWL);
    __nv_bfloat16* w64h = (__nv_bfloat16*)(S + O_W64H);
    __nv_bfloat16* w64l = (__nv_bfloat16*)(S + O_W64L);
    __nv_bfloat16* kh = (__nv_bfloat16*)(S + O_KH);
    __nv_bfloat16* kl = (__nv_bfloat16*)(S + O_KL);
    __nv_bfloat16* vh = (__nv_bfloat16*)(S + O_VH);
    __nv_bfloat16* vl = (__nv_bfloat16*)(S + O_VL);
    __nv_bfloat16* rh = (__nv_bfloat16*)(S + O_RH);
    __nv_bfloat16* rl = (__nv_bfloat16*)(S + O_RL);
    __nv_bfloat16* gh = (__nv_bfloat16*)(S + O_GH);
    __nv_bfloat16* gl = (__nv_bfloat16*)(S + O_GL);
    __nv_bfloat16* zh = (__nv_bfloat16*)(S + O_ZH);
    __nv_bfloat16* zl = (__nv_bfloat16*)(S + O_ZL);
    __nv_bfloat16* xxh = (__nv_bfloat16*)(S + O_XXH);
    __nv_bfloat16* xxl = (__nv_bfloat16*)(S + O_XXL);
    __nv_bfloat16* wrh = (__nv_bfloat16*)(S + O_WRH);
    __nv_bfloat16* wrl = (__nv_bfloat16*)(S + O_WRL);
    __nv_bfloat16* wkh = (__nv_bfloat16*)(S + O_WKH);
    __nv_bfloat16* wkl = (__nv_bfloat16*)(S + O_WKL);
    __nv_bfloat16* wvh = (__nv_bfloat16*)(S + O_WVH);
    __nv_bfloat16* wvl = (__nv_bfloat16*)(S + O_WVL);
    __nv_bfloat16* wgh = (__nv_bfloat16*)(S + O_WGH);
    __nv_bfloat16* wgl = (__nv_bfloat16*)(S + O_WGL);
    __nv_bfloat16* woh = (__nv_bfloat16*)(S + O_WOH);
    __nv_bfloat16* wol = (__nv_bfloat16*)(S + O_WOL);
    __nv_bfloat16* t1h = (__nv_bfloat16*)(S + O_T1H);
    __nv_bfloat16* t1l = (__nv_bfloat16*)(S + O_T1L);
    __nv_bfloat16* t2h = (__nv_bfloat16*)(S + O_T2H);
    __nv_bfloat16* t2l = (__nv_bfloat16*)(S + O_T2L);
    __nv_bfloat16* m1h = (__nv_bfloat16*)(S + O_M1H);
    __nv_bfloat16* m1l = (__nv_bfloat16*)(S + O_M1L);

    cudaFuncSetAttribute(tgemm_kernel<true, 0>, cudaFuncAttributeMaxDynamicSharedMemorySize, TG_SMEM);
    cudaFuncSetAttribute(tgemm_kernel<false, 0>, cudaFuncAttributeMaxDynamicSharedMemorySize, TG_SMEM);
    cudaFuncSetAttribute(tgemm2_kernel<16, 1, true>, cudaFuncAttributeMaxDynamicSharedMemorySize, TG_SMEM);
    cudaFuncSetAttribute(tgemm2_kernel<2, 3, false>, cudaFuncAttributeMaxDynamicSharedMemorySize, TG_SMEM);
    cudaFuncSetAttribute(tgemm2_kernel<16, 1, false>, cudaFuncAttributeMaxDynamicSharedMemorySize, TG_SMEM);

    // 0) weight splits
    convw_all_kernel<<<dim3(1024, 5), 256>>>(Wr, Wk, Wv, Wg, Wo,
                                             wrh, wrl, wkh, wkl, wvh, wvl,
                                             wgh, wgl, woh, wol);
    convtd_kernel<<<dim3(256, 4), 256>>>(tdw1, tdw2, w1, t1h, t1l, t2h, t2l, m1h, m1l);

    // 1) xxx = x + (shift(x)-x)*maa_x -> bf16 split
    prep_split_kernel<<<(int)(UEL / 256), 256>>>(x, tmaa_x, xxh, xxl);

    // 2) mix = tanh(xxx @ w1)  [BT,160] on tensor cores (N=160, K=512)
    tgemm2_kernel<16, 1, false><<<dim3(2, BT / 128), 256, TG_SMEM>>>(
        xxh, xxl, m1h, m1l, mixb, nullptr, nullptr, nullptr, 160);

    // 3) 5-way mix back-projection + token mixing
    mix_combine_kernel<<<BT / 16, 512>>>(x, mixb, w2, tmaa_w, tmaa_k, tmaa_v,
                                         tmaa_r, tmaa_g, xwh, xwl, kh, kl,
                                         vh, vl, rh, rl, gh, gl);

    // 4) 4 projections in ONE batched tensor-core launch (z==3 (g) = silu)
    {
        TGBatch bt_{};
        bt_.ah[0] = rh; bt_.al[0] = rl; bt_.bh[0] = wrh; bt_.bl[0] = wrl; bt_.c[0] = rb;
        bt_.ah[1] = kh; bt_.al[1] = kl; bt_.bh[1] = wkh; bt_.bl[1] = wkl; bt_.c[1] = kb;
        bt_.ah[2] = vh; bt_.al[2] = vl; bt_.bh[2] = wvh; bt_.bl[2] = wvl; bt_.c[2] = vb;
        bt_.ah[3] = gh; bt_.al[3] = gl; bt_.bh[3] = wgh; bt_.bl[3] = wgl; bt_.c[3] = gb;
        tgemm_kernel<true, 0><<<dim3(4, BT / 128, 4), 256, TG_SMEM>>>(
            bt_, nullptr, nullptr, nullptr, nullptr, nullptr);
    }

    // 5) decay MLP on tensor cores
    tgemm2_kernel<16, 1, true><<<dim3(1, BT / 128), 256, TG_SMEM>>>(
        xwh, xwl, t1h, t1l, nullptr, w64h, w64l, nullptr, 64);
    tgemm2_kernel<2, 3, false><<<dim3(4, BT / 128), 256, TG_SMEM>>>(
        w64h, w64l, t2h, t2l, db, nullptr, nullptr, tdecay, 512);

    // 6) WKV6 chunked scan: local scans -> state scan -> correction + gn fused
    wkv_chunk_kernel<<<NCID / 8, 256>>>(rb, kb, vb, db, faaaa, yb, ab, lb, pb);
    wkv_state_scan_kernel<<<BQ * HH, 1024>>>(lb, pb, s0b);
    wkv_apply_gn_kernel<<<NCID, 256>>>(yb, ab, s0b, gb, lnw, lnb, zh, zl);

    // 7) out = z @ Wo^T (tensor cores)
    {
        TGBatch dummy{};
        tgemm_kernel<false, 0><<<dim3(4, BT / 128), 256, TG_SMEM>>>(
            dummy, zh, zl, woh, wol, out);
    }
}

// round 12
// speedup vs baseline: 2.7147x; 1.0724x over previous
#include <cuda_runtime.h>
#include <cuda_bf16.h>
#include <cstdint>

#define BQ 8
#define TT 2048
#define CC 512
#define HH 16
#define HSZ 32
#define BT (BQ*TT)            // 16384
#define UEL ((size_t)BT*CC)   // 8388608 elements per [B,T,C] buffer
#define NCH 16                // chunks per sequence
#define CHL 128               // chunk length (TT/NCH)
#define NCID (BQ*HH*NCH)      // 2048 total chunks

// ---------------------------------------------------------------------------
// Scratch (bytes). One big device array; no allocations anywhere.
// ---------------------------------------------------------------------------
#define SZ_F32   (UEL*4)
#define SZ_BF16  (UEL*2)
#define SZ_MIX   ((size_t)BT*160*4)
#define SZ_W64B  ((size_t)BT*64*2)
#define SZ_WBF   ((size_t)CC*CC*2)
#define SZ_L     ((size_t)NCID*1024*4)
#define SZ_P     ((size_t)NCID*32*4)

#define O_MIX   ((size_t)0)
#define O_XWH   (O_MIX + SZ_MIX)
#define O_XWL   (O_XWH + SZ_BF16)
#define O_W64H  (O_XWL + SZ_BF16)
#define O_W64L  (O_W64H + SZ_W64B)
#define O_DB    (O_W64L + SZ_W64B)
#define O_RB    (O_DB + SZ_F32)
#define O_KB    (O_RB + SZ_F32)
#define O_VB    (O_KB + SZ_F32)
#define O_GB    (O_VB + SZ_F32)
#define O_YB    (O_GB + SZ_F32)
#define O_AB    (O_YB + SZ_F32)
#define O_LB    (O_AB + SZ_F32)
#define O_PB    (O_LB + SZ_L)
#define O_S0    (O_PB + SZ_P)
#define O_KH    (O_S0 + SZ_L)
#define O_KL    (O_KH + SZ_BF16)
#define O_VH    (O_KL + SZ_BF16)
#define O_VL    (O_VH + SZ_BF16)
#define O_RH    (O_VL + SZ_BF16)
#define O_RL    (O_RH + SZ_BF16)
#define O_GH    (O_RL + SZ_BF16)
#define O_GL    (O_GH + SZ_BF16)
#define O_ZH    (O_GL + SZ_BF16)
#define O_ZL    (O_ZH + SZ_BF16)
#define O_XXH   (O_ZL + SZ_BF16)
#define O_XXL   (O_XXH + SZ_BF16)
#define O_WRH   (O_XXL + SZ_BF16)
#define O_WRL   (O_WRH + SZ_WBF)
#define O_WKH   (O_WRL + SZ_WBF)
#define O_WKL   (O_WKH + SZ_WBF)
#define O_WVH   (O_WKL + SZ_WBF)
#define O_WVL   (O_WVH + SZ_WBF)
#define O_WGH   (O_WVL + SZ_WBF)
#define O_WGL   (O_WGH + SZ_WBF)
#define O_WOH   (O_WGL + SZ_WBF)
#define O_WOL   (O_WOH + SZ_WBF)
#define O_T1H   (O_WOL + SZ_WBF)                 // tdw1^T padded: 128x512 bf16
#define O_T1L   (O_T1H + (size_t)128*512*2)
#define O_T2H   (O_T1L + (size_t)128*512*2)      // tdw2^T: 512x64 bf16
#define O_T2L   (O_T2H + (size_t)512*64*2)
#define O_M1H   (O_T2L + (size_t)512*64*2)       // w1^T padded: 256x512 bf16
#define O_M1L   (O_M1H + (size_t)256*512*2)
#define O_MIXP  (O_M1L + (size_t)256*512*2)      // 5 planes of (BT,512) bf16
#define O_W2T   (O_MIXP + (size_t)5*UEL*2)       // W2^T: 5 x 512 x 32 bf16
#define SCRATCH_BYTES (O_W2T + (size_t)5*512*32*2)

__device__ __align__(256) unsigned char g_scratch[SCRATCH_BYTES];

// ---------------------------------------------------------------------------
// mma.sync / cp.async helpers (valid on plain compute_103 / sm_80+)
// ---------------------------------------------------------------------------
__device__ __forceinline__ uint32_t smem_u32(const void* p) {
    uint32_t a;
    asm("{ .reg .u64 t; cvta.to.shared.u64 t, %1; cvt.u32.u64 %0, t; }"
        : "=r"(a) : "l"(p));
    return a;
}

#define LDSM4(r, a) \
    asm volatile("ldmatrix.sync.aligned.m8n8.x4.shared.b16 {%0,%1,%2,%3}, [%4];" \
        : "=r"((r)[0]), "=r"((r)[1]), "=r"((r)[2]), "=r"((r)[3]) : "r"(a))

#define MMA16816(d, a, b0, b1) \
    asm volatile("mma.sync.aligned.m16n8k16.row.col.f32.bf16.bf16.f32 " \
        "{%0,%1,%2,%3}, {%4,%5,%6,%7}, {%8,%9}, {%0,%1,%2,%3};" \
        : "+f"((d)[0]), "+f"((d)[1]), "+f"((d)[2]), "+f"((d)[3]) \
        : "r"((a)[0]), "r"((a)[1]), "r"((a)[2]), "r"((a)[3]), "r"(b0), "r"(b1))

#define CP_ASYNC16(dst, src) \
    asm volatile("cp.async.cg.shared.global [%0], [%1], 16;" :: "r"(dst), "l"(src))
#define CP_COMMIT() asm volatile("cp.async.commit_group;" ::: "memory")
#define CP_WAIT(n)  asm volatile("cp.async.wait_group %0;" :: "n"(n) : "memory")

#define TROWB 80
#define TTILE (128*TROWB)     // 10240
#define TSTAGE (4*TTILE)      // 40960
#define TG_SMEM (2*TSTAGE)    // 81920
#define ROWSKIP (64*1024)     // 64 rows * 512 cols * 2B (K=512 path)
#define DSTSKIP (64*TROWB)

// ---------------------------------------------------------------------------
// split / pack helpers
// ---------------------------------------------------------------------------
__device__ __forceinline__ void wsplit(float v, __nv_bfloat16* hi, __nv_bfloat16* lo, size_t i) {
    __nv_bfloat16 h = __float2bfloat16(v);
    hi[i] = h;
    lo[i] = __float2bfloat16(v - __bfloat162float(h));
}
__device__ __forceinline__ uint32_t pack_bf2(float a, float b) {
    __nv_bfloat162 p;
    p.x = __float2bfloat16(a);
    p.y = __float2bfloat16(b);
    return *reinterpret_cast<uint32_t*>(&p);
}

// ---------------------------------------------------------------------------
// Pipelined tensor-core GEMM (hot path, K=512, N=512): unchanged.
// ---------------------------------------------------------------------------
struct TGBatch {
    const __nv_bfloat16 *ah[4], *al[4], *bh[4], *bl[4];
    float* c[4];
};

template<bool BATCH, int EPI>
__global__ void __launch_bounds__(256, 2)
tgemm_kernel(TGBatch bt_,
             const __nv_bfloat16* __restrict__ Ah_, const __nv_bfloat16* __restrict__ Al_,
             const __nv_bfloat16* __restrict__ Bh_, const __nv_bfloat16* __restrict__ Bl_,
             float* __restrict__ C_)
{
    extern __shared__ unsigned char sm[];
    uint32_t smb = smem_u32(sm);
    int tid = threadIdx.x;
    int wid = tid >> 5, lane = tid & 31;
    int bm = blockIdx.y * 128, bn = blockIdx.x * 128;
    int wm = (wid & 3) * 32, wn = (wid >> 2) * 64;

    int z = BATCH ? blockIdx.z : 0;
    const __nv_bfloat16* Ah = BATCH ? bt_.ah[z] : Ah_;
    const __nv_bfloat16* Al = BATCH ? bt_.al[z] : Al_;
    const __nv_bfloat16* Bh = BATCH ? bt_.bh[z] : Bh_;
    const __nv_bfloat16* Bl = BATCH ? bt_.bl[z] : Bl_;
    float* C = BATCH ? bt_.c[z] : C_;
    bool do_silu = BATCH ? (z == 3) : (EPI == 2);

    int rowq = tid >> 2;
    int gcol = (tid & 3) * 8;
    const char* pAh = (const char*)(Ah + (size_t)(bm + rowq) * 512 + gcol);
    const char* pAl = (const char*)(Al + (size_t)(bm + rowq) * 512 + gcol);
    const char* pBh = (const char*)(Bh + (size_t)(bn + rowq) * 512 + gcol);
    const char* pBl = (const char*)(Bl + (size_t)(bn + rowq) * 512 + gcol);
    uint32_t dA = smb + rowq * TROWB + (tid & 3) * 16;
    uint32_t dB = dA + 2 * TTILE;

    float acc[2][8][4];
    #pragma unroll
    for (int i = 0; i < 2; ++i)
        #pragma unroll
        for (int j = 0; j < 8; ++j)
            #pragma unroll
            for (int q = 0; q < 4; ++q) acc[i][j][q] = 0.f;

    int mat = lane >> 3, r8 = lane & 7;
    int lrow = (mat & 1) * 8 + r8;
    int lkb  = (mat >> 1) * 16;
    uint32_t raBase = smb + (wm + lrow) * TROWB + lkb;
    uint32_t rbBase = smb + 2 * TTILE + (wn + lrow) * TROWB + lkb;

    {
        CP_ASYNC16(dA,                    pAh);
        CP_ASYNC16(dA + DSTSKIP,          pAh + ROWSKIP);
        CP_ASYNC16(dA + TTILE,            pAl);
        CP_ASYNC16(dA + TTILE + DSTSKIP,  pAl + ROWSKIP);
        CP_ASYNC16(dB,                    pBh);
        CP_ASYNC16(dB + DSTSKIP,          pBh + ROWSKIP);
        CP_ASYNC16(dB + TTILE,            pBl);
        CP_ASYNC16(dB + TTILE + DSTSKIP,  pBl + ROWSKIP);
        pAh += 64; pAl += 64; pBh += 64; pBl += 64;
        CP_COMMIT();
    }

    for (int ch = 0; ch < 16; ++ch) {
        if (ch + 1 < 16) {
            uint32_t so = ((ch + 1) & 1) * TSTAGE;
            CP_ASYNC16(dA + so,                    pAh);
            CP_ASYNC16(dA + so + DSTSKIP,          pAh + ROWSKIP);
            CP_ASYNC16(dA + so + TTILE,            pAl);
            CP_ASYNC16(dA + so + TTILE + DSTSKIP,  pAl + ROWSKIP);
            CP_ASYNC16(dB + so,                    pBh);
            CP_ASYNC16(dB + so + DSTSKIP,          pBh + ROWSKIP);
            CP_ASYNC16(dB + so + TTILE,            pBl);
            CP_ASYNC16(dB + so + TTILE + DSTSKIP,  pBl + ROWSKIP);
            pAh += 64; pAl += 64; pBh += 64; pBl += 64;
            CP_COMMIT();
            CP_WAIT(1);
        } else {
            CP_WAIT(0);
        }
        __syncthreads();

        uint32_t so = (ch & 1) * TSTAGE;
        uint32_t ra0 = raBase + so;
        uint32_t rb0 = rbBase + so;
        #pragma unroll
        for (int ks = 0; ks < 2; ++ks) {
            uint32_t ah[2][4], al[2][4];
            #pragma unroll
            for (int mt = 0; mt < 2; ++mt) {
                uint32_t ra = ra0 + mt * (16 * TROWB) + ks * 32;
                LDSM4(ah[mt], ra);
                LDSM4(al[mt], ra + TTILE);
            }
            #pragma unroll
            for (int nt = 0; nt < 4; ++nt) {
                uint32_t rb = rb0 + nt * (16 * TROWB) + ks * 32;
                uint32_t bh4[4], bl4[4];
                LDSM4(bh4, rb);
                LDSM4(bl4, rb + TTILE);
                #pragma unroll
                for (int mt = 0; mt < 2; ++mt) {
                    MMA16816(acc[mt][nt*2+0], ah[mt], bh4[0], bh4[2]);
                    MMA16816(acc[mt][nt*2+1], ah[mt], bh4[1], bh4[3]);
                    MMA16816(acc[mt][nt*2+0], ah[mt], bl4[0], bl4[2]);
                    MMA16816(acc[mt][nt*2+1], ah[mt], bl4[1], bl4[3]);
                    MMA16816(acc[mt][nt*2+0], al[mt], bh4[0], bh4[2]);
                    MMA16816(acc[mt][nt*2+1], al[mt], bh4[1], bh4[3]);
                }
            }
        }
        __syncthreads();
    }

    int r0 = lane >> 2, c0 = (lane & 3) * 2;
    #pragma unroll
    for (int mt = 0; mt < 2; ++mt) {
        #pragma unroll
        for (int nt = 0; nt < 4; ++nt) {
            #pragma unroll
            for (int s = 0; s < 2; ++s) {
                float* a4 = acc[mt][nt*2+s];
                int col = bn + wn + nt * 16 + s * 8 + c0;
                int row = bm + wm + mt * 16 + r0;
                float v0 = a4[0], v1 = a4[1], v2 = a4[2], v3 = a4[3];
                if (do_silu) {
                    v0 = v0 / (1.f + __expf(-v0));
                    v1 = v1 / (1.f + __expf(-v1));
                    v2 = v2 / (1.f + __expf(-v2));
                    v3 = v3 / (1.f + __expf(-v3));
                }
                *reinterpret_cast<float2*>(C + (size_t)row * 512 + col)       = make_float2(v0, v1);
                *reinterpret_cast<float2*>(C + (size_t)(row + 8) * 512 + col) = make_float2(v2, v3);
            }
        }
    }
}

// ---------------------------------------------------------------------------
// Parameterized tensor GEMM (decay MLP + mix GEMM).
// NK = K/32 chunks. EPI: 1 tanh, 3 exp(-exp(bias+v)).
// OM: 0 fp32 out, 1 split bf16 hi/lo out, 2 single bf16 out.
// ---------------------------------------------------------------------------
template<int NK, int EPI, int OM>
__global__ void __launch_bounds__(256, 2)
tgemm2_kernel(const __nv_bfloat16* __restrict__ Ah, const __nv_bfloat16* __restrict__ Al,
              const __nv_bfloat16* __restrict__ Bh, const __nv_bfloat16* __restrict__ Bl,
              float* __restrict__ Cf,
              __nv_bfloat16* __restrict__ Chi, __nv_bfloat16* __restrict__ Clo,
              const float* __restrict__ bias, int N)
{
    constexpr int K = NK * 32;
    constexpr int RSKIP = 64 * K * 2;
    extern __shared__ unsigned char sm[];
    uint32_t smb = smem_u32(sm);
    int tid = threadIdx.x;
    int wid = tid >> 5, lane = tid & 31;
    int bm = blockIdx.y * 128, bn = blockIdx.x * 128;
    int wm = (wid & 3) * 32, wn = (wid >> 2) * 64;

    int rowq = tid >> 2;
    int gcol = (tid & 3) * 8;
    const char* pAh = (const char*)(Ah + (size_t)(bm + rowq) * K + gcol);
    const char* pAl = (const char*)(Al + (size_t)(bm + rowq) * K + gcol);
    const char* pBh = (const char*)(Bh + (size_t)(bn + rowq) * K + gcol);
    const char* pBl = (const char*)(Bl + (size_t)(bn + rowq) * K + gcol);
    uint32_t dA = smb + rowq * TROWB + (tid & 3) * 16;
    uint32_t dB = dA + 2 * TTILE;

    float acc[2][8][4];
    #pragma unroll
    for (int i = 0; i < 2; ++i)
        #pragma unroll
        for (int j = 0; j < 8; ++j)
            #pragma unroll
            for (int q = 0; q < 4; ++q) acc[i][j][q] = 0.f;

    int mat = lane >> 3, r8 = lane & 7;
    int lrow = (mat & 1) * 8 + r8;
    int lkb  = (mat >> 1) * 16;
    uint32_t raBase = smb + (wm + lrow) * TROWB + lkb;
    uint32_t rbBase = smb + 2 * TTILE + (wn + lrow) * TROWB + lkb;

    {
        CP_ASYNC16(dA,                   pAh);
        CP_ASYNC16(dA + DSTSKIP,         pAh + RSKIP);
        CP_ASYNC16(dA + TTILE,           pAl);
        CP_ASYNC16(dA + TTILE + DSTSKIP, pAl + RSKIP);
        CP_ASYNC16(dB,                   pBh);
        CP_ASYNC16(dB + DSTSKIP,         pBh + RSKIP);
        CP_ASYNC16(dB + TTILE,           pBl);
        CP_ASYNC16(dB + TTILE + DSTSKIP, pBl + RSKIP);
        pAh += 64; pAl += 64; pBh += 64; pBl += 64;
        CP_COMMIT();
    }

    for (int ch = 0; ch < NK; ++ch) {
        if (ch + 1 < NK) {
            uint32_t so = ((ch + 1) & 1) * TSTAGE;
            CP_ASYNC16(dA + so,                   pAh);
            CP_ASYNC16(dA + so + DSTSKIP,         pAh + RSKIP);
            CP_ASYNC16(dA + so + TTILE,           pAl);
            CP_ASYNC16(dA + so + TTILE + DSTSKIP, pAl + RSKIP);
            CP_ASYNC16(dB + so,                   pBh);
            CP_ASYNC16(dB + so + DSTSKIP,         pBh + RSKIP);
            CP_ASYNC16(dB + so + TTILE,           pBl);
            CP_ASYNC16(dB + so + TTILE + DSTSKIP, pBl + RSKIP);
            pAh += 64; pAl += 64; pBh += 64; pBl += 64;
            CP_COMMIT();
            CP_WAIT(1);
        } else {
            CP_WAIT(0);
        }
        __syncthreads();

        uint32_t so = (ch & 1) * TSTAGE;
        uint32_t ra0 = raBase + so;
        uint32_t rb0 = rbBase + so;
        #pragma unroll
        for (int ks = 0; ks < 2; ++ks) {
            uint32_t ah[2][4], al[2][4];
            #pragma unroll
            for (int mt = 0; mt < 2; ++mt) {
                uint32_t ra = ra0 + mt * (16 * TROWB) + ks * 32;
                LDSM4(ah[mt], ra);
                LDSM4(al[mt], ra + TTILE);
            }
            #pragma unroll
            for (int nt = 0; nt < 4; ++nt) {
                uint32_t rb = rb0 + nt * (16 * TROWB) + ks * 32;
                uint32_t bh4[4], bl4[4];
                LDSM4(bh4, rb);
                LDSM4(bl4, rb + TTILE);
                #pragma unroll
                for (int mt = 0; mt < 2; ++mt) {
                    MMA16816(acc[mt][nt*2+0], ah[mt], bh4[0], bh4[2]);
                    MMA16816(acc[mt][nt*2+1], ah[mt], bh4[1], bh4[3]);
                    MMA16816(acc[mt][nt*2+0], ah[mt], bl4[0], bl4[2]);
                    MMA16816(acc[mt][nt*2+1], ah[mt], bl4[1], bl4[3]);
                    MMA16816(acc[mt][nt*2+0], al[mt], bh4[0], bh4[2]);
                    MMA16816(acc[mt][nt*2+1], al[mt], bh4[1], bh4[3]);
                }
            }
        }
        __syncthreads();
    }

    int r0 = lane >> 2, c0 = (lane & 3) * 2;
    #pragma unroll
    for (int mt = 0; mt < 2; ++mt) {
        #pragma unroll
        for (int nt = 0; nt < 4; ++nt) {
            #pragma unroll
            for (int s = 0; s < 2; ++s) {
                float* a4 = acc[mt][nt*2+s];
                int col = bn + wn + nt * 16 + s * 8 + c0;
                if (col >= N) continue;
                int row = bm + wm + mt * 16 + r0;
                #pragma unroll
                for (int half = 0; half < 2; ++half) {
                    float v0 = a4[half * 2 + 0], v1 = a4[half * 2 + 1];
                    size_t ro = (size_t)(row + half * 8) * N + col;
                    if (EPI == 1) { v0 = tanhf(v0); v1 = tanhf(v1); }
                    else if (EPI == 3) {
                        v0 = __expf(-__expf(bias[col] + v0));
                        v1 = __expf(-__expf(bias[col + 1] + v1));
                    }
                    if (OM == 1) {
                        wsplit(v0, Chi, Clo, ro);
                        wsplit(v1, Chi, Clo, ro + 1);
                    } else if (OM == 2) {
                        *reinterpret_cast<uint32_t*>(Chi + ro) = pack_bf2(v0, v1);
                    } else {
                        *reinterpret_cast<float2*>(Cf + ro) = make_float2(v0, v1);
                    }
                }
            }
        }
    }
}

// ---------------------------------------------------------------------------
// Mix back-projection GEMM: mixproj_f = mix[:, f*32:(f+1)*32] @ W2T[f]
// A: bf16 (BT,160) pitched; B: w2t (5,512,32) bf16; C: mixp plane bf16 (BT,512).
// Single bf16 term (back-projection output ~1e-6 vs maa ~1: bf16 is ample).
// K=32 (one stage), grid (4, BT/128, 5).
// ---------------------------------------------------------------------------
__global__ void __launch_bounds__(256)
tgemm3_kernel(const __nv_bfloat16* __restrict__ mixbh,
              const __nv_bfloat16* __restrict__ w2t,
              __nv_bfloat16* __restrict__ mixp)
{
    __shared__ unsigned char sm3[2 * TTILE];
    uint32_t smb = smem_u32(sm3);
    int tid = threadIdx.x;
    int wid = tid >> 5, lane = tid & 31;
    int bn = blockIdx.x * 128, bm = blockIdx.y * 128, f = blockIdx.z;
    int wm = (wid & 3) * 32, wn = (wid >> 2) * 64;

    // A and B tiles: 128 rows x 32 bf16 (64B data per row, TROWB stride)
    #pragma unroll
    for (int q = 0; q < 2; ++q) {
        int e = tid * 2 + q;           // 0..511
        int row = e >> 2, g = e & 3;
        CP_ASYNC16(smb + row * TROWB + g * 16,
                   mixbh + (size_t)(bm + row) * 160 + f * 32 + g * 8);
        CP_ASYNC16(smb + TTILE + row * TROWB + g * 16,
                   w2t + (size_t)f * 512 * 32 + (size_t)(bn + row) * 32 + g * 8);
    }
    CP_COMMIT();
    CP_WAIT(0);
    __syncthreads();

    float acc[2][8][4];
    #pragma unroll
    for (int i = 0; i < 2; ++i)
        #pragma unroll
        for (int j = 0; j < 8; ++j)
            #pragma unroll
            for (int q = 0; q < 4; ++q) acc[i][j][q] = 0.f;

    int mat = lane >> 3, r8 = lane & 7;
    int lrow = (mat & 1) * 8 + r8;
    int lkb  = (mat >> 1) * 16;
    uint32_t ra0 = smb + (wm + lrow) * TROWB + lkb;
    uint32_t rb0 = smb + TTILE + (wn + lrow) * TROWB + lkb;

    #pragma unroll
    for (int ks = 0; ks < 2; ++ks) {
        uint32_t ah[2][4];
        #pragma unroll
        for (int mt = 0; mt < 2; ++mt)
            LDSM4(ah[mt], ra0 + mt * (16 * TROWB) + ks * 32);
        #pragma unroll
        for (int nt = 0; nt < 4; ++nt) {
            uint32_t bh4[4];
            LDSM4(bh4, rb0 + nt * (16 * TROWB) + ks * 32);
            #pragma unroll
            for (int mt = 0; mt < 2; ++mt) {
                MMA16816(acc[mt][nt*2+0], ah[mt], bh4[0], bh4[2]);
                MMA16816(acc[mt][nt*2+1], ah[mt], bh4[1], bh4[3]);
            }
        }
    }

    __nv_bfloat16* Cb = mixp + (size_t)f * UEL;
    int r0 = lane >> 2, c0 = (lane & 3) * 2;
    #pragma unroll
    for (int mt = 0; mt < 2; ++mt) {
        #pragma unroll
        for (int nt = 0; nt < 4; ++nt) {
            #pragma unroll
            for (int s = 0; s < 2; ++s) {
                float* a4 = acc[mt][nt*2+s];
                int col = bn + wn + nt * 16 + s * 8 + c0;
                int row = bm + wm + mt * 16 + r0;
                *reinterpret_cast<uint32_t*>(Cb + (size_t)row * 512 + col)       = pack_bf2(a4[0], a4[1]);
                *reinterpret_cast<uint32_t*>(Cb + (size_t)(row + 8) * 512 + col) = pack_bf2(a4[2], a4[3]);
            }
        }
    }
}

// ---------------------------------------------------------------------------
// Elementwise 5-way token mix apply: x_f = x + (xshift-x)*(maa_f + mixproj_f)
// 4 elements/thread, vectorized loads + packed bf16 stores.
// ---------------------------------------------------------------------------
__global__ void __launch_bounds__(256) mixapply_kernel(
    const float* __restrict__ x, const __nv_bfloat16* __restrict__ mixp,
    const float* __restrict__ maaw, const float* __restrict__ maak,
    const float* __restrict__ maav, const float* __restrict__ maar,
    const float* __restrict__ maag,
    __nv_bfloat16* __restrict__ xwh, __nv_bfloat16* __restrict__ xwl,
    __nv_bfloat16* __restrict__ kh, __nv_bfloat16* __restrict__ kl,
    __nv_bfloat16* __restrict__ vh, __nv_bfloat16* __restrict__ vl,
    __nv_bfloat16* __restrict__ rh, __nv_bfloat16* __restrict__ rl,
    __nv_bfloat16* __restrict__ gh, __nv_bfloat16* __restrict__ gl)
{
    size_t i = ((size_t)blockIdx.x * 256 + threadIdx.x) * 4;
    int c = (int)(i & 511);
    int t = (int)((i >> 9) & (TT - 1));
    float4 xv = *reinterpret_cast<const float4*>(x + i);
    float4 xp = make_float4(0.f, 0.f, 0.f, 0.f);
    if (t) xp = *reinterpret_cast<const float4*>(x + i - 512);
    float xc[4] = {xv.x, xv.y, xv.z, xv.w};
    float xx[4] = {xp.x - xv.x, xp.y - xv.y, xp.z - xv.z, xp.w - xv.w};

    #pragma unroll
    for (int f = 0; f < 5; ++f) {
        const float* maa = (f == 0) ? maaw : (f == 1) ? maak : (f == 2) ? maav
                         : (f == 3) ? maar : maag;
        float4 m4 = *reinterpret_cast<const float4*>(maa + c);
        uint2 mp = *reinterpret_cast<const uint2*>(mixp + (size_t)f * UEL + i);
        __nv_bfloat162 m01 = *reinterpret_cast<__nv_bfloat162*>(&mp.x);
        __nv_bfloat162 m23 = *reinterpret_cast<__nv_bfloat162*>(&mp.y);
        float mv[4] = {__bfloat162float(m01.x), __bfloat162float(m01.y),
                       __bfloat162float(m23.x), __bfloat162float(m23.y)};
        float ma[4] = {m4.x, m4.y, m4.z, m4.w};
        float v[4], h[4];
        #pragma unroll
        for (int e = 0; e < 4; ++e) {
            v[e] = fmaf(xx[e], ma[e] + mv[e], xc[e]);
            h[e] = __bfloat162float(__float2bfloat16(v[e]));
        }
        uint2 hi2, lo2;
        hi2.x = pack_bf2(v[0], v[1]);
        hi2.y = pack_bf2(v[2], v[3]);
        lo2.x = pack_bf2(v[0] - h[0], v[1] - h[1]);
        lo2.y = pack_bf2(v[2] - h[2], v[3] - h[3]);
        __nv_bfloat16* dh = (f == 0) ? xwh : (f == 1) ? kh : (f == 2) ? vh
                          : (f == 3) ? rh : gh;
        __nv_bfloat16* dl = (f == 0) ? xwl : (f == 1) ? kl : (f == 2) ? vl
                          : (f == 3) ? rl : gl;
        *reinterpret_cast<uint2*>(dh + i) = hi2;
        *reinterpret_cast<uint2*>(dl + i) = lo2;
    }
}

// ---------------------------------------------------------------------------
// prep: xxx = x + (xshift - x) * maa_x  -> bf16 hi/lo
// ---------------------------------------------------------------------------
__global__ void __launch_bounds__(256) prep_split_kernel(
    const float* __restrict__ x, const float* __restrict__ tmx,
    __nv_bfloat16* __restrict__ xxh, __nv_bfloat16* __restrict__ xxl)
{
    size_t i = (size_t)blockIdx.x * 256 + threadIdx.x;
    int c = (int)(i & (CC - 1));
    int t = (int)((i >> 9) & (TT - 1));
    float xv = x[i];
    float xp = (t > 0) ? x[i - CC] : 0.f;
    wsplit(fmaf(xp - xv, tmx[c], xv), xxh, xxl, i);
}

// ---------------------------------------------------------------------------
// All weight fp32 -> bf16 hi/lo splits in one launch (grid.y = which weight)
// ---------------------------------------------------------------------------
__global__ void convw_all_kernel(const float* __restrict__ W0, const float* __restrict__ W1,
                                 const float* __restrict__ W2, const float* __restrict__ W3,
                                 const float* __restrict__ W4,
                                 __nv_bfloat16* __restrict__ H0, __nv_bfloat16* __restrict__ L0,
                                 __nv_bfloat16* __restrict__ H1, __nv_bfloat16* __restrict__ L1,
                                 __nv_bfloat16* __restrict__ H2, __nv_bfloat16* __restrict__ L2,
                                 __nv_bfloat16* __restrict__ H3, __nv_bfloat16* __restrict__ L3,
                                 __nv_bfloat16* __restrict__ H4, __nv_bfloat16* __restrict__ L4)
{
    int w = blockIdx.y;
    const float* W = (w == 0) ? W0 : (w == 1) ? W1 : (w == 2) ? W2 : (w == 3) ? W3 : W4;
    __nv_bfloat16* H = (w == 0) ? H0 : (w == 1) ? H1 : (w == 2) ? H2 : (w == 3) ? H3 : H4;
    __nv_bfloat16* L = (w == 0) ? L0 : (w == 1) ? L1 : (w == 2) ? L2 : (w == 3) ? L3 : L4;
    int i = blockIdx.x * 256 + threadIdx.x;
    float v = W[i];
    __nv_bfloat16 h = __float2bfloat16(v);
    H[i] = h;
    L[i] = __float2bfloat16(v - __bfloat162float(h));
}

// ---------------------------------------------------------------------------
// Small-weight transpose + pad + split.
// y=0: tdw1 (512,64) -> t1 (128,512), rows 64..127 zero.
// y=1: tdw2 (64,512) -> t2 (512,64).
// y=2..3: w1 (512,160) -> m1 (256,512), rows 160..255 zero.
// y=4: W2 (5,32,512) -> w2t (5,512,32) bf16 single.
// ---------------------------------------------------------------------------
__global__ void convtd_kernel(const float* __restrict__ tdw1, const float* __restrict__ tdw2,
                              const float* __restrict__ w1, const float* __restrict__ W2,
                              __nv_bfloat16* __restrict__ t1h, __nv_bfloat16* __restrict__ t1l,
                              __nv_bfloat16* __restrict__ t2h, __nv_bfloat16* __restrict__ t2l,
                              __nv_bfloat16* __restrict__ m1h, __nv_bfloat16* __restrict__ m1l,
                              __nv_bfloat16* __restrict__ w2t)
{
    int i = blockIdx.x * 256 + threadIdx.x;
    if (blockIdx.y == 0) {
        if (i < 128 * 512) {
            int n = i >> 9, k = i & 511;
            float v = (n < 64) ? tdw1[(size_t)k * 64 + n] : 0.f;
            wsplit(v, t1h, t1l, i);
        }
    } else if (blockIdx.y == 1) {
        if (i < 512 * 64) {
            int n = i >> 6, k = i & 63;
            float v = tdw2[(size_t)k * 512 + n];
            wsplit(v, t2h, t2l, i);
        }
    } else if (blockIdx.y <= 3) {
        int j = (int)(blockIdx.y - 2) * 81920 + i;
        if (j < 256 * 512) {
            int n = j >> 9, k = j & 511;
            float v = (n < 160) ? w1[(size_t)k * 160 + n] : 0.f;
            wsplit(v, m1h, m1l, j);
        }
    } else {
        if (i < 5 * 512 * 32) {
            int f = i >> 14, rem = i & 16383;
            int c = rem >> 5, dd = rem & 31;
            w2t[i] = __float2bfloat16(W2[(size_t)(f * 32 + dd) * 512 + c]);
        }
    }
}

// ---------------------------------------------------------------------------
// Chunked WKV, kernel 1: per-chunk local scan.
// ---------------------------------------------------------------------------
__global__ void __launch_bounds__(256) wkv_chunk_kernel(
    const float* __restrict__ r, const float* __restrict__ k,
    const float* __restrict__ v, const float* __restrict__ d,
    const float* __restrict__ u,
    float* __restrict__ ylocal, float* __restrict__ Aout,
    float* __restrict__ Lout, float* __restrict__ Pout)
{
    int wid = threadIdx.x >> 5, lane = threadIdx.x & 31;
    int cid = blockIdx.x * 8 + wid;
    int bh = cid >> 4, ch = cid & (NCH - 1);
    int b = bh >> 4, h = bh & (HH - 1);
    size_t base = ((size_t)b * TT + (size_t)ch * CHL) * CC + h * HSZ + lane;

    __shared__ float srkd[8][3][32];

    float S[32];
    #pragma unroll
    for (int j = 0; j < 32; ++j) S[j] = 0.f;
    float P = 1.f;
    float ul = u[h * HSZ + lane];

    size_t off = base;
    float rl = r[off], kl = k[off], dl = d[off], vl = v[off];

    for (int t = 0; t < CHL; ++t) {
        int tn = (t + 1 < CHL) ? (t + 1) : t;
        size_t offn = base + (size_t)tn * CC;
        float rn = r[offn], kn = k[offn], dn = d[offn], vn = v[offn];

        Aout[off] = rl * P;
        P *= dl;

        srkd[wid][0][lane] = rl;
        srkd[wid][1][lane] = kl;
        srkd[wid][2][lane] = dl;
        __syncwarp();

        float cp = rl * ul * kl;
        #pragma unroll
        for (int o = 16; o; o >>= 1) cp += __shfl_xor_sync(0xffffffffu, cp, o);

        float y0 = 0.f, y1 = 0.f, y2 = 0.f, y3 = 0.f;
        #pragma unroll
        for (int j4 = 0; j4 < 8; ++j4) {
            float4 r4 = *reinterpret_cast<const float4*>(&srkd[wid][0][j4 * 4]);
            float4 k4 = *reinterpret_cast<const float4*>(&srkd[wid][1][j4 * 4]);
            float4 d4 = *reinterpret_cast<const float4*>(&srkd[wid][2][j4 * 4]);
            y0 = fmaf(r4.x, S[j4*4+0], y0); S[j4*4+0] = fmaf(d4.x, S[j4*4+0], k4.x * vl);
            y1 = fmaf(r4.y, S[j4*4+1], y1); S[j4*4+1] = fmaf(d4.y, S[j4*4+1], k4.y * vl);
            y2 = fmaf(r4.z, S[j4*4+2], y2); S[j4*4+2] = fmaf(d4.z, S[j4*4+2], k4.z * vl);
            y3 = fmaf(r4.w, S[j4*4+3], y3); S[j4*4+3] = fmaf(d4.w, S[j4*4+3], k4.w * vl);
        }
        ylocal[off] = (y0 + y1) + (y2 + y3) + cp * vl;
        __syncwarp();

        rl = rn; kl = kn; dl = dn; vl = vn;
        off += CC;
    }

    #pragma unroll
    for (int j = 0; j < 32; ++j)
        Lout[(size_t)cid * 1024 + j * 32 + lane] = S[j];
    Pout[(size_t)cid * 32 + lane] = P;
}

// ---------------------------------------------------------------------------
// Chunked WKV, kernel 2: scan chunk states across the sequence.
// ---------------------------------------------------------------------------
__global__ void __launch_bounds__(1024) wkv_state_scan_kernel(
    const float* __restrict__ L, const float* __restrict__ P,
    float* __restrict__ S0out)
{
    int bh = blockIdx.x;
    int e = threadIdx.x;
    int j = e >> 5;
    float s = 0.f;
    #pragma unroll
    for (int c = 0; c < NCH; ++c) {
        size_t cid = (size_t)bh * NCH + c;
        S0out[cid * 1024 + e] = s;
        s = P[cid * 32 + j] * s + L[cid * 1024 + e];
    }
}

// ---------------------------------------------------------------------------
// Chunked WKV, kernel 3 + fused groupnorm * ln * gate -> bf16 hi/lo.
// ---------------------------------------------------------------------------
__global__ void __launch_bounds__(256) wkv_apply_gn_kernel(
    const float* __restrict__ ylocal, const float* __restrict__ A,
    const float* __restrict__ S0, const float* __restrict__ gate,
    const float* __restrict__ lnw, const float* __restrict__ lnb,
    __nv_bfloat16* __restrict__ zh, __nv_bfloat16* __restrict__ zl)
{
    int cid = blockIdx.x;
    int ch = cid & (NCH - 1);
    int bh = cid >> 4;
    int b = bh >> 4, h = bh & (HH - 1);
    int wid = threadIdx.x >> 5, lane = threadIdx.x & 31;

    __shared__ float s0[1024];
    __shared__ float sa[8][32];
    if (ch != 0) {
        for (int i = threadIdx.x; i < 1024; i += 256)
            s0[i] = S0[(size_t)cid * 1024 + i];
    }
    __syncthreads();

    float lw = lnw[h * HSZ + lane];
    float lb = lnb[h * HSZ + lane];

    size_t base = ((size_t)b * TT + (size_t)ch * CHL) * CC + h * HSZ + lane;
    for (int tt = 0; tt < 16; ++tt) {
        int t = wid * 16 + tt;
        size_t off = base + (size_t)t * CC;
        float yv = ylocal[off];
        if (ch != 0) {
            sa[wid][lane] = A[off];
            __syncwarp();
            float acc = 0.f;
            #pragma unroll
            for (int j4 = 0; j4 < 8; ++j4) {
                float4 a4 = *reinterpret_cast<const float4*>(&sa[wid][j4 * 4]);
                acc = fmaf(a4.x, s0[(j4*4+0)*32 + lane], acc);
                acc = fmaf(a4.y, s0[(j4*4+1)*32 + lane], acc);
                acc = fmaf(a4.z, s0[(j4*4+2)*32 + lane], acc);
                acc = fmaf(a4.w, s0[(j4*4+3)*32 + lane], acc);
            }
            yv += acc;
            __syncwarp();
        }
        float s = yv;
        #pragma unroll
        for (int o = 16; o; o >>= 1) s += __shfl_xor_sync(0xffffffffu, s, o);
        float mu = s * (1.f / 32.f);
        float dv = yv - mu;
        float q = dv * dv;
        #pragma unroll
        for (int o = 16; o; o >>= 1) q += __shfl_xor_sync(0xffffffffu, q, o);
        float yn = dv * rsqrtf(q * (1.f / 32.f) + 1e-5f);
        float z = (yn * lw + lb) * gate[off];
        wsplit(z, zh, zl, off);
    }
}

// ---------------------------------------------------------------------------
extern "C" void kernel_launch(void* const* d_in, const int* in_sizes, int n_in,
                              void* d_out, int out_size) {
    const float* x      = (const float*)d_in[0];
    const float* tmaa_x = (const float*)d_in[1];
    const float* tmaa_w = (const float*)d_in[2];
    const float* tmaa_k = (const float*)d_in[3];
    const float* tmaa_v = (const float*)d_in[4];
    const float* tmaa_r = (const float*)d_in[5];
    const float* tmaa_g = (const float*)d_in[6];
    const float* w1     = (const float*)d_in[7];   // (C,160)
    const float* w2     = (const float*)d_in[8];   // (5,32,C)
    const float* tdecay = (const float*)d_in[9];   // (C,)
    const float* tdw1   = (const float*)d_in[10];  // (C,64)
    const float* tdw2   = (const float*)d_in[11];  // (64,C)
    const float* faaaa  = (const float*)d_in[12];  // (H,HS)
    const float* Wr     = (const float*)d_in[13];
    const float* Wk     = (const float*)d_in[14];
    const float* Wv     = (const float*)d_in[15];
    const float* Wg     = (const float*)d_in[16];
    const float* Wo     = (const float*)d_in[17];
    const float* lnw    = (const float*)d_in[18];
    const float* lnb    = (const float*)d_in[19];
    float* out = (float*)d_out;

    unsigned char* S;
    cudaGetSymbolAddress((void**)&S, g_scratch);
    __nv_bfloat16* mixbh = (__nv_bfloat16*)(S + O_MIX);   // bf16 (BT,160)
    float* db   = (float*)(S + O_DB);
    float* rb   = (float*)(S + O_RB);
    float* kb   = (float*)(S + O_KB);
    float* vb   = (float*)(S + O_VB);
    float* gb   = (float*)(S + O_GB);
    float* yb   = (float*)(S + O_YB);
    float* ab   = (float*)(S + O_AB);
    float* lb   = (float*)(S + O_LB);
    float* pb   = (float*)(S + O_PB);
    float* s0b  = (float*)(S + O_S0);
    __nv_bfloat16* xwh = (__nv_bfloat16*)(S + O_XWH);
    __nv_bfloat16* xwl = (__nv_bfloat16*)(S + O_XWL);
    __nv_bfloat16* w64h = (__nv_bfloat16*)(S + O_W64H);
    __nv_bfloat16* w64l = (__nv_bfloat16*)(S + O_W64L);
    __nv_bfloat16* kh = (__nv_bfloat16*)(S + O_KH);
    __nv_bfloat16* kl = (__nv_bfloat16*)(S + O_KL);
    __nv_bfloat16* vh = (__nv_bfloat16*)(S + O_VH);
    __nv_bfloat16* vl = (__nv_bfloat16*)(S + O_VL);
    __nv_bfloat16* rh = (__nv_bfloat16*)(S + O_RH);
    __nv_bfloat16* rl = (__nv_bfloat16*)(S + O_RL);
    __nv_bfloat16* gh = (__nv_bfloat16*)(S + O_GH);
    __nv_bfloat16* gl = (__nv_bfloat16*)(S + O_GL);
    __nv_bfloat16* zh = (__nv_bfloat16*)(S + O_ZH);
    __nv_bfloat16* zl = (__nv_bfloat16*)(S + O_ZL);
    __nv_bfloat16* xxh = (__nv_bfloat16*)(S + O_XXH);
    __nv_bfloat16* xxl = (__nv_bfloat16*)(S + O_XXL);
    __nv_bfloat16* wrh = (__nv_bfloat16*)(S + O_WRH);
    __nv_bfloat16* wrl = (__nv_bfloat16*)(S + O_WRL);
    __nv_bfloat16* wkh = (__nv_bfloat16*)(S + O_WKH);
    __nv_bfloat16* wkl = (__nv_bfloat16*)(S + O_WKL);
    __nv_bfloat16* wvh = (__nv_bfloat16*)(S + O_WVH);
    __nv_bfloat16* wvl = (__nv_bfloat16*)(S + O_WVL);
    __nv_bfloat16* wgh = (__nv_bfloat16*)(S + O_WGH);
    __nv_bfloat16* wgl = (__nv_bfloat16*)(S + O_WGL);
    __nv_bfloat16* woh = (__nv_bfloat16*)(S + O_WOH);
    __nv_bfloat16* wol = (__nv_bfloat16*)(S + O_WOL);
    __nv_bfloat16* t1h = (__nv_bfloat16*)(S + O_T1H);
    __nv_bfloat16* t1l = (__nv_bfloat16*)(S + O_T1L);
    __nv_bfloat16* t2h = (__nv_bfloat16*)(S + O_T2H);
    __nv_bfloat16* t2l = (__nv_bfloat16*)(S + O_T2L);
    __nv_bfloat16* m1h = (__nv_bfloat16*)(S + O_M1H);
    __nv_bfloat16* m1l = (__nv_bfloat16*)(S + O_M1L);
    __nv_bfloat16* mixp = (__nv_bfloat16*)(S + O_MIXP);
    __nv_bfloat16* w2t  = (__nv_bfloat16*)(S + O_W2T);

    cudaFuncSetAttribute(tgemm_kernel<true, 0>, cudaFuncAttributeMaxDynamicSharedMemorySize, TG_SMEM);
    cudaFuncSetAttribute(tgemm_kernel<false, 0>, cudaFuncAttributeMaxDynamicSharedMemorySize, TG_SMEM);
    cudaFuncSetAttribute(tgemm2_kernel<16, 1, 1>, cudaFuncAttributeMaxDynamicSharedMemorySize, TG_SMEM);
    cudaFuncSetAttribute(tgemm2_kernel<2, 3, 0>, cudaFuncAttributeMaxDynamicSharedMemorySize, TG_SMEM);
    cudaFuncSetAttribute(tgemm2_kernel<16, 1, 2>, cudaFuncAttributeMaxDynamicSharedMemorySize, TG_SMEM);

    // 0) weight splits
    convw_all_kernel<<<dim3(1024, 5), 256>>>(Wr, Wk, Wv, Wg, Wo,
                                             wrh, wrl, wkh, wkl, wvh, wvl,
                                             wgh, wgl, woh, wol);
    convtd_kernel<<<dim3(320, 5), 256>>>(tdw1, tdw2, w1, w2,
                                         t1h, t1l, t2h, t2l, m1h, m1l, w2t);

    // 1) xxx = x + (shift(x)-x)*maa_x -> bf16 split
    prep_split_kernel<<<(int)(UEL / 256), 256>>>(x, tmaa_x, xxh, xxl);

    // 2) mix = tanh(xxx @ w1)  [BT,160] on tensor cores, bf16 out
    tgemm2_kernel<16, 1, 2><<<dim3(2, BT / 128), 256, TG_SMEM>>>(
        xxh, xxl, m1h, m1l, nullptr, mixbh, nullptr, nullptr, 160);

    // 3a) back-projection GEMMs: mixproj_f = mix_f @ W2T[f]  (batched over f)
    tgemm3_kernel<<<dim3(4, BT / 128, 5), 256>>>(mixbh, w2t, mixp);

    // 3b) elementwise 5-way token mixing -> bf16 hi/lo operands
    mixapply_kernel<<<(int)(UEL / 1024), 256>>>(x, mixp, tmaa_w, tmaa_k, tmaa_v,
                                                tmaa_r, tmaa_g, xwh, xwl, kh, kl,
                                                vh, vl, rh, rl, gh, gl);

    // 4) 4 projections in ONE batched tensor-core launch (z==3 (g) = silu)
    {
        TGBatch bt_{};
        bt_.ah[0] = rh; bt_.al[0] = rl; bt_.bh[0] = wrh; bt_.bl[0] = wrl; bt_.c[0] = rb;
        bt_.ah[1] = kh; bt_.al[1] = kl; bt_.bh[1] = wkh; bt_.bl[1] = wkl; bt_.c[1] = kb;
        bt_.ah[2] = vh; bt_.al[2] = vl; bt_.bh[2] = wvh; bt_.bl[2] = wvl; bt_.c[2] = vb;
        bt_.ah[3] = gh; bt_.al[3] = gl; bt_.bh[3] = wgh; bt_.bl[3] = wgl; bt_.c[3] = gb;
        tgemm_kernel<true, 0><<<dim3(4, BT / 128, 4), 256, TG_SMEM>>>(
            bt_, nullptr, nullptr, nullptr, nullptr, nullptr);
    }

    // 5) decay MLP on tensor cores
    tgemm2_kernel<16, 1, 1><<<dim3(1, BT / 128), 256, TG_SMEM>>>(
        xwh, xwl, t1h, t1l, nullptr, w64h, w64l, nullptr, 64);
    tgemm2_kernel<2, 3, 0><<<dim3(4, BT / 128), 256, TG_SMEM>>>(
        w64h, w64l, t2h, t2l, db, nullptr, nullptr, tdecay, 512);

    // 6) WKV6 chunked scan: local scans -> state scan -> correction + gn fused
    wkv_chunk_kernel<<<NCID / 8, 256>>>(rb, kb, vb, db, faaaa, yb, ab, lb, pb);
    wkv_state_scan_kernel<<<BQ * HH, 1024>>>(lb, pb, s0b);
    wkv_apply_gn_kernel<<<NCID, 256>>>(yb, ab, s0b, gb, lnw, lnb, zh, zl);

    // 7) out = z @ Wo^T (tensor cores)
    {
        TGBatch dummy{};
        tgemm_kernel<false, 0><<<dim3(4, BT / 128), 256, TG_SMEM>>>(
            dummy, zh, zl, woh, wol, out);
    }
}